// round 1
// baseline (speedup 1.0000x reference)
#include <cuda_runtime.h>
#include <math.h>

#define S_LEN   2048
#define D_MOD   2048
#define NHEAD   16
#define HD      128
#define BATCH   2
#define M_TOT   (BATCH * S_LEN)   // 4096

// Scratch (device globals: allocation-free rule)
__device__ float g_q [BATCH * S_LEN * D_MOD];
__device__ float g_k [BATCH * S_LEN * D_MOD];
__device__ float g_v [BATCH * S_LEN * D_MOD];
__device__ float g_ao[BATCH * S_LEN * D_MOD];

// ---------------------------------------------------------------------------
// SGEMM NT: C[M,N] = X[M,K] * W[N,K]^T   (both operands K-contiguous)
// BM=BN=128, BK=16, 256 threads, 8x8 per thread (two 4-wide fragments each dim)
// ---------------------------------------------------------------------------
__global__ __launch_bounds__(256) void sgemm_nt(
    const float* __restrict__ X, const float* __restrict__ W,
    float* __restrict__ C, int M, int N, int K)
{
    __shared__ float As[16][128];
    __shared__ float Bs[16][128];

    const int tid = threadIdx.x;
    const int tx = tid & 15;
    const int ty = tid >> 4;
    const int bm = blockIdx.y * 128;
    const int bn = blockIdx.x * 128;

    const float* Xp = X + (size_t)bm * K;
    const float* Wp = W + (size_t)bn * K;

    float acc[8][8];
#pragma unroll
    for (int i = 0; i < 8; i++)
#pragma unroll
        for (int j = 0; j < 8; j++) acc[i][j] = 0.f;

    for (int k0 = 0; k0 < K; k0 += 16) {
#pragma unroll
        for (int it = 0; it < 2; it++) {
            int idx = tid + it * 256;           // 0..511
            int r  = idx >> 2;                  // 0..127
            int c  = (idx & 3) << 2;            // 0,4,8,12
            float4 va = *reinterpret_cast<const float4*>(Xp + (size_t)r * K + k0 + c);
            As[c + 0][r] = va.x; As[c + 1][r] = va.y;
            As[c + 2][r] = va.z; As[c + 3][r] = va.w;
            float4 vb = *reinterpret_cast<const float4*>(Wp + (size_t)r * K + k0 + c);
            Bs[c + 0][r] = vb.x; Bs[c + 1][r] = vb.y;
            Bs[c + 2][r] = vb.z; Bs[c + 3][r] = vb.w;
        }
        __syncthreads();

#pragma unroll
        for (int k = 0; k < 16; k++) {
            float4 a0 = *reinterpret_cast<const float4*>(&As[k][ty * 4]);
            float4 a1 = *reinterpret_cast<const float4*>(&As[k][64 + ty * 4]);
            float4 b0 = *reinterpret_cast<const float4*>(&Bs[k][tx * 4]);
            float4 b1 = *reinterpret_cast<const float4*>(&Bs[k][64 + tx * 4]);
            float a[8] = {a0.x, a0.y, a0.z, a0.w, a1.x, a1.y, a1.z, a1.w};
            float b[8] = {b0.x, b0.y, b0.z, b0.w, b1.x, b1.y, b1.z, b1.w};
#pragma unroll
            for (int i = 0; i < 8; i++)
#pragma unroll
                for (int j = 0; j < 8; j++)
                    acc[i][j] += a[i] * b[j];
        }
        __syncthreads();
    }

#pragma unroll
    for (int i = 0; i < 8; i++) {
        int r = bm + (i < 4 ? ty * 4 + i : 64 + ty * 4 + (i - 4));
        float4 o0 = make_float4(acc[i][0], acc[i][1], acc[i][2], acc[i][3]);
        float4 o1 = make_float4(acc[i][4], acc[i][5], acc[i][6], acc[i][7]);
        *reinterpret_cast<float4*>(&C[(size_t)r * N + bn + tx * 4])      = o0;
        *reinterpret_cast<float4*>(&C[(size_t)r * N + bn + 64 + tx * 4]) = o1;
    }
}

// ---------------------------------------------------------------------------
// RoPE: in-place on q and k laid out [B, S, H, HD]
// one thread per (b,s,h,d<64) pair
// ---------------------------------------------------------------------------
__global__ __launch_bounds__(256) void rope_kernel(
    float* __restrict__ q, float* __restrict__ k,
    const float* __restrict__ cosb, const float* __restrict__ sinb)
{
    int idx = blockIdx.x * blockDim.x + threadIdx.x;   // B*S*H*64 = 2^22
    int d = idx & 63;
    int h = (idx >> 6) & 15;
    int s = (idx >> 10) & 2047;
    int b = idx >> 21;

    size_t base = ((size_t)(b * S_LEN + s)) * D_MOD + h * HD;
    float c1 = cosb[s * HD + d];
    float s1 = sinb[s * HD + d];
    float c2 = cosb[s * HD + 64 + d];
    float s2 = sinb[s * HD + 64 + d];

    float q1 = q[base + d], q2 = q[base + 64 + d];
    q[base + d]      = q1 * c1 - q2 * s1;
    q[base + 64 + d] = q2 * c2 + q1 * s2;

    float k1 = k[base + d], k2 = k[base + 64 + d];
    k[base + d]      = k1 * c1 - k2 * s1;
    k[base + 64 + d] = k2 * c2 + k1 * s2;
}

// ---------------------------------------------------------------------------
// Flash attention (causal), fp32.
// Br = 128 q-rows per CTA, Bc = 64 k-rows per iteration, hd = 128.
// 256 threads (16x16). Per-thread: 8 q-rows x (4 S-cols / 8 O-cols).
// q,k,v,out are in [B, S, H, HD] layout (i.e. [M, D] with head offset).
// ---------------------------------------------------------------------------
#define LDQ 132
#define LDK 132
#define LDV 132
#define LDP 68

__global__ __launch_bounds__(256, 1) void attn_kernel(
    const float* __restrict__ Qg, const float* __restrict__ Kg,
    const float* __restrict__ Vg, float* __restrict__ Og)
{
    extern __shared__ float sm[];
    float* Qs = sm;                       // [128][132]
    float* Ks = Qs + 128 * LDQ;           // [64][132]
    float* Vs = Ks + 64 * LDK;            // [64][132]
    float* Ps = Vs + 64 * LDV;            // [128][68]

    const int tid = threadIdx.x;
    const int tx = tid & 15;
    const int ty = tid >> 4;
    const int bid = blockIdx.x;
    const int qb = 15 - (bid >> 5);       // longest jobs scheduled first
    const int bh = bid & 31;
    const int b  = bh >> 4;
    const int h  = bh & 15;

    const size_t row0 = (size_t)b * S_LEN;
    const int    hoff = h * HD;
    const int    q0   = qb * 128;

    // load Q tile
#pragma unroll
    for (int it = 0; it < 16; it++) {
        int idx = tid + it * 256;
        int r = idx >> 5;
        int c = (idx & 31) << 2;
        float4 v = *reinterpret_cast<const float4*>(
            &Qg[(row0 + q0 + r) * D_MOD + hoff + c]);
        *reinterpret_cast<float4*>(&Qs[r * LDQ + c]) = v;
    }

    int rrow[8];
#pragma unroll
    for (int i = 0; i < 8; i++)
        rrow[i] = (i < 4) ? (ty * 4 + i) : (64 + ty * 4 + (i - 4));

    float m[8], l[8], o[8][8];
#pragma unroll
    for (int i = 0; i < 8; i++) {
        m[i] = -1e30f; l[i] = 0.f;
#pragma unroll
        for (int j = 0; j < 8; j++) o[i][j] = 0.f;
    }

    const float scale = 0.08838834764831845f;   // 1/sqrt(128)
    const int kb_max = qb * 2 + 1;

    for (int kb = 0; kb <= kb_max; kb++) {
        __syncthreads();   // smem reuse barrier (also covers initial Q load)
        // load K,V tiles (64 x 128 each)
#pragma unroll
        for (int it = 0; it < 8; it++) {
            int idx = tid + it * 256;
            int r = idx >> 5;
            int c = (idx & 31) << 2;
            size_t g = (row0 + kb * 64 + r) * D_MOD + hoff + c;
            *reinterpret_cast<float4*>(&Ks[r * LDK + c]) =
                *reinterpret_cast<const float4*>(&Kg[g]);
            *reinterpret_cast<float4*>(&Vs[r * LDV + c]) =
                *reinterpret_cast<const float4*>(&Vg[g]);
        }
        __syncthreads();

        // S = Q * K^T (128 x 64 tile; this thread: 8 rows x 4 cols)
        float sacc[8][4];
#pragma unroll
        for (int i = 0; i < 8; i++)
#pragma unroll
            for (int j = 0; j < 4; j++) sacc[i][j] = 0.f;

#pragma unroll 2
        for (int kk = 0; kk < 128; kk += 4) {
            float4 bf[4];
#pragma unroll
            for (int j = 0; j < 4; j++)
                bf[j] = *reinterpret_cast<const float4*>(&Ks[(tx + 16 * j) * LDK + kk]);
#pragma unroll
            for (int i = 0; i < 8; i++) {
                float4 af = *reinterpret_cast<const float4*>(&Qs[rrow[i] * LDQ + kk]);
#pragma unroll
                for (int j = 0; j < 4; j++) {
                    sacc[i][j] += af.x * bf[j].x;
                    sacc[i][j] += af.y * bf[j].y;
                    sacc[i][j] += af.z * bf[j].z;
                    sacc[i][j] += af.w * bf[j].w;
                }
            }
        }

        // online softmax update; write P tile to smem
#pragma unroll
        for (int i = 0; i < 8; i++) {
            int grow = q0 + rrow[i];
            float mx = m[i];
            float sv[4];
#pragma unroll
            for (int j = 0; j < 4; j++) {
                float v = sacc[i][j] * scale;
                int col = kb * 64 + tx + 16 * j;
                if (col > grow) v = -1e30f;
                sv[j] = v;
                mx = fmaxf(mx, v);
            }
#pragma unroll
            for (int off = 8; off >= 1; off >>= 1)
                mx = fmaxf(mx, __shfl_xor_sync(0xffffffffu, mx, off));

            float corr = __expf(m[i] - mx);
            m[i] = mx;
            float psum = 0.f;
#pragma unroll
            for (int j = 0; j < 4; j++) {
                float p = __expf(sv[j] - mx);
                psum += p;
                Ps[rrow[i] * LDP + tx + 16 * j] = p;
            }
            l[i] = l[i] * corr + psum;
#pragma unroll
            for (int j = 0; j < 8; j++) o[i][j] *= corr;
        }
        __syncthreads();

        // O += P * V  (128x64 @ 64x128; this thread: 8 rows x 8 cols)
#pragma unroll 4
        for (int jj = 0; jj < 64; jj += 4) {
            float v0[4][4], v1[4][4];
#pragma unroll
            for (int t = 0; t < 4; t++) {
                float4 a = *reinterpret_cast<const float4*>(&Vs[(jj + t) * LDV + tx * 4]);
                float4 c = *reinterpret_cast<const float4*>(&Vs[(jj + t) * LDV + 64 + tx * 4]);
                v0[t][0] = a.x; v0[t][1] = a.y; v0[t][2] = a.z; v0[t][3] = a.w;
                v1[t][0] = c.x; v1[t][1] = c.y; v1[t][2] = c.z; v1[t][3] = c.w;
            }
#pragma unroll
            for (int i = 0; i < 8; i++) {
                float4 pf = *reinterpret_cast<const float4*>(&Ps[rrow[i] * LDP + jj]);
                float pv[4] = {pf.x, pf.y, pf.z, pf.w};
#pragma unroll
                for (int t = 0; t < 4; t++) {
#pragma unroll
                    for (int c = 0; c < 4; c++) {
                        o[i][c]     += pv[t] * v0[t][c];
                        o[i][4 + c] += pv[t] * v1[t][c];
                    }
                }
            }
        }
    }

    // epilogue: normalize and write out
#pragma unroll
    for (int i = 0; i < 8; i++) {
        float lt = l[i];
#pragma unroll
        for (int off = 8; off >= 1; off >>= 1)
            lt += __shfl_xor_sync(0xffffffffu, lt, off);
        float inv = 1.f / lt;
        size_t obase = (row0 + q0 + rrow[i]) * D_MOD + hoff;
        float4 o0 = make_float4(o[i][0] * inv, o[i][1] * inv, o[i][2] * inv, o[i][3] * inv);
        float4 o1 = make_float4(o[i][4] * inv, o[i][5] * inv, o[i][6] * inv, o[i][7] * inv);
        *reinterpret_cast<float4*>(&Og[obase + tx * 4])      = o0;
        *reinterpret_cast<float4*>(&Og[obase + 64 + tx * 4]) = o1;
    }
}

// ---------------------------------------------------------------------------
extern "C" void kernel_launch(void* const* d_in, const int* in_sizes, int n_in,
                              void* d_out, int out_size)
{
    const float* x    = (const float*)d_in[0];
    const float* cosb = (const float*)d_in[1];
    const float* sinb = (const float*)d_in[2];
    const float* Wq   = (const float*)d_in[3];
    const float* Wk   = (const float*)d_in[4];
    const float* Wv   = (const float*)d_in[5];
    const float* Wo   = (const float*)d_in[6];
    float* out = (float*)d_out;

    float *q, *k, *v, *ao;
    cudaGetSymbolAddress((void**)&q,  g_q);
    cudaGetSymbolAddress((void**)&k,  g_k);
    cudaGetSymbolAddress((void**)&v,  g_v);
    cudaGetSymbolAddress((void**)&ao, g_ao);

    const int attn_smem = (128 * LDQ + 64 * LDK + 64 * LDV + 128 * LDP) * 4;
    cudaFuncSetAttribute(attn_kernel,
                         cudaFuncAttributeMaxDynamicSharedMemorySize, attn_smem);

    dim3 ggrid(D_MOD / 128, M_TOT / 128);   // (16, 32)
    sgemm_nt<<<ggrid, 256>>>(x, Wq, q, M_TOT, D_MOD, D_MOD);
    sgemm_nt<<<ggrid, 256>>>(x, Wk, k, M_TOT, D_MOD, D_MOD);
    sgemm_nt<<<ggrid, 256>>>(x, Wv, v, M_TOT, D_MOD, D_MOD);

    rope_kernel<<<(BATCH * S_LEN * NHEAD * 64) / 256, 256>>>(q, k, cosb, sinb);

    attn_kernel<<<BATCH * NHEAD * (S_LEN / 128), 256, attn_smem>>>(q, k, v, ao);

    sgemm_nt<<<ggrid, 256>>>(ao, Wo, out, M_TOT, D_MOD, D_MOD);
}

// round 2
// speedup vs baseline: 1.0003x; 1.0003x over previous
#include <cuda_runtime.h>
#include <math.h>

#define S_LEN   2048
#define D_MOD   2048
#define NHEAD   16
#define HD      128
#define BATCH   2
#define M_TOT   (BATCH * S_LEN)   // 4096

typedef unsigned long long u64;

__device__ __forceinline__ u64 pack2(float lo, float hi) {
    u64 r;
    asm("mov.b64 %0, {%1, %2};" : "=l"(r) : "f"(lo), "f"(hi));
    return r;
}
__device__ __forceinline__ float2 unpack2(u64 v) {
    float2 r;
    asm("mov.b64 {%0, %1}, %2;" : "=f"(r.x), "=f"(r.y) : "l"(v));
    return r;
}
// d = a * b + d   (packed 2x fp32)
__device__ __forceinline__ void ffma2(u64& d, u64 a, u64 b) {
    asm("fma.rn.f32x2 %0, %1, %2, %0;" : "+l"(d) : "l"(a), "l"(b));
}
// d = d * c       (packed 2x fp32)
__device__ __forceinline__ void fmul2(u64& d, u64 c) {
    asm("mul.rn.f32x2 %0, %0, %1;" : "+l"(d) : "l"(c));
}

// Scratch (device globals: allocation-free rule)
__device__ float g_q [BATCH * S_LEN * D_MOD];
__device__ float g_k [BATCH * S_LEN * D_MOD];
__device__ float g_v [BATCH * S_LEN * D_MOD];
__device__ float g_ao[BATCH * S_LEN * D_MOD];

// ---------------------------------------------------------------------------
// SGEMM NT: C[M,N] = X[M,K] * W[N,K]^T   (both operands K-contiguous)
// BM=BN=128, BK=16, 256 threads, 8x8 per thread, FFMA2 (fma.rn.f32x2) mainloop
// ---------------------------------------------------------------------------
__global__ __launch_bounds__(256) void sgemm_nt(
    const float* __restrict__ X, const float* __restrict__ W,
    float* __restrict__ C, int M, int N, int K)
{
    __shared__ float As[16][128];
    __shared__ float Bs[16][128];

    const int tid = threadIdx.x;
    const int tx = tid & 15;
    const int ty = tid >> 4;
    const int bm = blockIdx.y * 128;
    const int bn = blockIdx.x * 128;

    const float* Xp = X + (size_t)bm * K;
    const float* Wp = W + (size_t)bn * K;

    // acc2[i][j] packs output cols (2j, 2j+1) for row i of the 8x8 microtile
    u64 acc2[8][4];
#pragma unroll
    for (int i = 0; i < 8; i++)
#pragma unroll
        for (int j = 0; j < 4; j++) acc2[i][j] = 0ull;

    for (int k0 = 0; k0 < K; k0 += 16) {
#pragma unroll
        for (int it = 0; it < 2; it++) {
            int idx = tid + it * 256;           // 0..511
            int r  = idx >> 2;                  // 0..127
            int c  = (idx & 3) << 2;            // 0,4,8,12
            float4 va = *reinterpret_cast<const float4*>(Xp + (size_t)r * K + k0 + c);
            As[c + 0][r] = va.x; As[c + 1][r] = va.y;
            As[c + 2][r] = va.z; As[c + 3][r] = va.w;
            float4 vb = *reinterpret_cast<const float4*>(Wp + (size_t)r * K + k0 + c);
            Bs[c + 0][r] = vb.x; Bs[c + 1][r] = vb.y;
            Bs[c + 2][r] = vb.z; Bs[c + 3][r] = vb.w;
        }
        __syncthreads();

#pragma unroll
        for (int k = 0; k < 16; k++) {
            float4 a0 = *reinterpret_cast<const float4*>(&As[k][ty * 4]);
            float4 a1 = *reinterpret_cast<const float4*>(&As[k][64 + ty * 4]);
            float4 b0 = *reinterpret_cast<const float4*>(&Bs[k][tx * 4]);
            float4 b1 = *reinterpret_cast<const float4*>(&Bs[k][64 + tx * 4]);
            u64 bp[4];
            bp[0] = pack2(b0.x, b0.y); bp[1] = pack2(b0.z, b0.w);
            bp[2] = pack2(b1.x, b1.y); bp[3] = pack2(b1.z, b1.w);
            float a[8] = {a0.x, a0.y, a0.z, a0.w, a1.x, a1.y, a1.z, a1.w};
#pragma unroll
            for (int i = 0; i < 8; i++) {
                u64 ap = pack2(a[i], a[i]);
#pragma unroll
                for (int j = 0; j < 4; j++)
                    ffma2(acc2[i][j], ap, bp[j]);
            }
        }
        __syncthreads();
    }

#pragma unroll
    for (int i = 0; i < 8; i++) {
        int r = bm + (i < 4 ? ty * 4 + i : 64 + ty * 4 + (i - 4));
        float2 c0 = unpack2(acc2[i][0]);
        float2 c1 = unpack2(acc2[i][1]);
        float2 c2 = unpack2(acc2[i][2]);
        float2 c3 = unpack2(acc2[i][3]);
        float4 o0 = make_float4(c0.x, c0.y, c1.x, c1.y);
        float4 o1 = make_float4(c2.x, c2.y, c3.x, c3.y);
        *reinterpret_cast<float4*>(&C[(size_t)r * N + bn + tx * 4])      = o0;
        *reinterpret_cast<float4*>(&C[(size_t)r * N + bn + 64 + tx * 4]) = o1;
    }
}

// ---------------------------------------------------------------------------
// RoPE: in-place on q and k laid out [B, S, H, HD]
// ---------------------------------------------------------------------------
__global__ __launch_bounds__(256) void rope_kernel(
    float* __restrict__ q, float* __restrict__ k,
    const float* __restrict__ cosb, const float* __restrict__ sinb)
{
    int idx = blockIdx.x * blockDim.x + threadIdx.x;   // B*S*H*64 = 2^22
    int d = idx & 63;
    int h = (idx >> 6) & 15;
    int s = (idx >> 10) & 2047;
    int b = idx >> 21;

    size_t base = ((size_t)(b * S_LEN + s)) * D_MOD + h * HD;
    float c1 = cosb[s * HD + d];
    float s1 = sinb[s * HD + d];
    float c2 = cosb[s * HD + 64 + d];
    float s2 = sinb[s * HD + 64 + d];

    float q1 = q[base + d], q2 = q[base + 64 + d];
    q[base + d]      = q1 * c1 - q2 * s1;
    q[base + 64 + d] = q2 * c2 + q1 * s2;

    float k1 = k[base + d], k2 = k[base + 64 + d];
    k[base + d]      = k1 * c1 - k2 * s1;
    k[base + 64 + d] = k2 * c2 + k1 * s2;
}

// ---------------------------------------------------------------------------
// Flash attention (causal), fp32 with FFMA2 mainloops.
// Br = 128, Bc = 64, hd = 128. 256 threads (16x16).
// ---------------------------------------------------------------------------
#define LDQ 132
#define LDK 132
#define LDV 132
#define LDP 68

__global__ __launch_bounds__(256, 1) void attn_kernel(
    const float* __restrict__ Qg, const float* __restrict__ Kg,
    const float* __restrict__ Vg, float* __restrict__ Og)
{
    extern __shared__ float sm[];
    float* Qs = sm;                       // [128][132]
    float* Ks = Qs + 128 * LDQ;           // [64][132]
    float* Vs = Ks + 64 * LDK;            // [64][132]
    float* Ps = Vs + 64 * LDV;            // [128][68]

    const int tid = threadIdx.x;
    const int tx = tid & 15;
    const int ty = tid >> 4;
    const int bid = blockIdx.x;
    const int qb = 15 - (bid >> 5);       // longest jobs scheduled first
    const int bh = bid & 31;
    const int b  = bh >> 4;
    const int h  = bh & 15;

    const size_t row0 = (size_t)b * S_LEN;
    const int    hoff = h * HD;
    const int    q0   = qb * 128;

    // load Q tile
#pragma unroll
    for (int it = 0; it < 16; it++) {
        int idx = tid + it * 256;
        int r = idx >> 5;
        int c = (idx & 31) << 2;
        float4 v = *reinterpret_cast<const float4*>(
            &Qg[(row0 + q0 + r) * D_MOD + hoff + c]);
        *reinterpret_cast<float4*>(&Qs[r * LDQ + c]) = v;
    }

    int rrow[8];
#pragma unroll
    for (int i = 0; i < 8; i++)
        rrow[i] = (i < 4) ? (ty * 4 + i) : (64 + ty * 4 + (i - 4));

    float m[8], l[8];
    u64 o2[8][4];                         // packed output cols (2j,2j+1)
#pragma unroll
    for (int i = 0; i < 8; i++) {
        m[i] = -1e30f; l[i] = 0.f;
#pragma unroll
        for (int j = 0; j < 4; j++) o2[i][j] = 0ull;
    }

    const float scale = 0.08838834764831845f;   // 1/sqrt(128)
    const int kb_max = qb * 2 + 1;

    for (int kb = 0; kb <= kb_max; kb++) {
        __syncthreads();   // smem reuse barrier (also covers initial Q load)
        // load K,V tiles (64 x 128 each)
#pragma unroll
        for (int it = 0; it < 8; it++) {
            int idx = tid + it * 256;
            int r = idx >> 5;
            int c = (idx & 31) << 2;
            size_t g = (row0 + kb * 64 + r) * D_MOD + hoff + c;
            *reinterpret_cast<float4*>(&Ks[r * LDK + c]) =
                *reinterpret_cast<const float4*>(&Kg[g]);
            *reinterpret_cast<float4*>(&Vs[r * LDV + c]) =
                *reinterpret_cast<const float4*>(&Vg[g]);
        }
        __syncthreads();

        // S = Q * K^T (128 x 64 tile; this thread: 8 rows x 4 cols)
        // packed across row pairs: sacc2[ip][j].lo = row 2ip, .hi = row 2ip+1
        u64 sacc2[4][4];
#pragma unroll
        for (int ip = 0; ip < 4; ip++)
#pragma unroll
            for (int j = 0; j < 4; j++) sacc2[ip][j] = 0ull;

#pragma unroll 2
        for (int kk = 0; kk < 128; kk += 4) {
            float4 bf[4];
#pragma unroll
            for (int j = 0; j < 4; j++)
                bf[j] = *reinterpret_cast<const float4*>(&Ks[(tx + 16 * j) * LDK + kk]);
            u64 bb[4][4];  // [elem][j] broadcast packs
#pragma unroll
            for (int j = 0; j < 4; j++) {
                bb[0][j] = pack2(bf[j].x, bf[j].x);
                bb[1][j] = pack2(bf[j].y, bf[j].y);
                bb[2][j] = pack2(bf[j].z, bf[j].z);
                bb[3][j] = pack2(bf[j].w, bf[j].w);
            }
#pragma unroll
            for (int ip = 0; ip < 4; ip++) {
                float4 af0 = *reinterpret_cast<const float4*>(&Qs[rrow[2 * ip]     * LDQ + kk]);
                float4 af1 = *reinterpret_cast<const float4*>(&Qs[rrow[2 * ip + 1] * LDQ + kk]);
                u64 aa[4];
                aa[0] = pack2(af0.x, af1.x);
                aa[1] = pack2(af0.y, af1.y);
                aa[2] = pack2(af0.z, af1.z);
                aa[3] = pack2(af0.w, af1.w);
#pragma unroll
                for (int j = 0; j < 4; j++) {
                    ffma2(sacc2[ip][j], aa[0], bb[0][j]);
                    ffma2(sacc2[ip][j], aa[1], bb[1][j]);
                    ffma2(sacc2[ip][j], aa[2], bb[2][j]);
                    ffma2(sacc2[ip][j], aa[3], bb[3][j]);
                }
            }
        }

        // unpack scores
        float sacc[8][4];
#pragma unroll
        for (int ip = 0; ip < 4; ip++)
#pragma unroll
            for (int j = 0; j < 4; j++) {
                float2 s2v = unpack2(sacc2[ip][j]);
                sacc[2 * ip][j]     = s2v.x;
                sacc[2 * ip + 1][j] = s2v.y;
            }

        // online softmax update; write P tile to smem
#pragma unroll
        for (int i = 0; i < 8; i++) {
            int grow = q0 + rrow[i];
            float mx = m[i];
            float sv[4];
#pragma unroll
            for (int j = 0; j < 4; j++) {
                float v = sacc[i][j] * scale;
                int col = kb * 64 + tx + 16 * j;
                if (col > grow) v = -1e30f;
                sv[j] = v;
                mx = fmaxf(mx, v);
            }
#pragma unroll
            for (int off = 8; off >= 1; off >>= 1)
                mx = fmaxf(mx, __shfl_xor_sync(0xffffffffu, mx, off));

            float corr = __expf(m[i] - mx);
            m[i] = mx;
            float psum = 0.f;
#pragma unroll
            for (int j = 0; j < 4; j++) {
                float p = __expf(sv[j] - mx);
                psum += p;
                Ps[rrow[i] * LDP + tx + 16 * j] = p;
            }
            l[i] = l[i] * corr + psum;
            u64 cp = pack2(corr, corr);
#pragma unroll
            for (int j = 0; j < 4; j++) fmul2(o2[i][j], cp);
        }
        __syncthreads();

        // O += P * V  (128x64 @ 64x128; this thread: 8 rows x 8 cols, packed)
#pragma unroll 2
        for (int jj = 0; jj < 64; jj += 4) {
            u64 vv[4][4];  // [t][col-pair]
#pragma unroll
            for (int t = 0; t < 4; t++) {
                float4 a = *reinterpret_cast<const float4*>(&Vs[(jj + t) * LDV + tx * 4]);
                float4 c = *reinterpret_cast<const float4*>(&Vs[(jj + t) * LDV + 64 + tx * 4]);
                vv[t][0] = pack2(a.x, a.y); vv[t][1] = pack2(a.z, a.w);
                vv[t][2] = pack2(c.x, c.y); vv[t][3] = pack2(c.z, c.w);
            }
#pragma unroll
            for (int i = 0; i < 8; i++) {
                float4 pf = *reinterpret_cast<const float4*>(&Ps[rrow[i] * LDP + jj]);
                u64 pp[4];
                pp[0] = pack2(pf.x, pf.x); pp[1] = pack2(pf.y, pf.y);
                pp[2] = pack2(pf.z, pf.z); pp[3] = pack2(pf.w, pf.w);
#pragma unroll
                for (int t = 0; t < 4; t++) {
#pragma unroll
                    for (int jp = 0; jp < 4; jp++)
                        ffma2(o2[i][jp], pp[t], vv[t][jp]);
                }
            }
        }
    }

    // epilogue: normalize and write out
#pragma unroll
    for (int i = 0; i < 8; i++) {
        float lt = l[i];
#pragma unroll
        for (int off = 8; off >= 1; off >>= 1)
            lt += __shfl_xor_sync(0xffffffffu, lt, off);
        float inv = 1.f / lt;
        size_t obase = (row0 + q0 + rrow[i]) * D_MOD + hoff;
        float2 c0 = unpack2(o2[i][0]);
        float2 c1 = unpack2(o2[i][1]);
        float2 c2 = unpack2(o2[i][2]);
        float2 c3 = unpack2(o2[i][3]);
        float4 oa = make_float4(c0.x * inv, c0.y * inv, c1.x * inv, c1.y * inv);
        float4 ob = make_float4(c2.x * inv, c2.y * inv, c3.x * inv, c3.y * inv);
        *reinterpret_cast<float4*>(&Og[obase + tx * 4])      = oa;
        *reinterpret_cast<float4*>(&Og[obase + 64 + tx * 4]) = ob;
    }
}

// ---------------------------------------------------------------------------
extern "C" void kernel_launch(void* const* d_in, const int* in_sizes, int n_in,
                              void* d_out, int out_size)
{
    const float* x    = (const float*)d_in[0];
    const float* cosb = (const float*)d_in[1];
    const float* sinb = (const float*)d_in[2];
    const float* Wq   = (const float*)d_in[3];
    const float* Wk   = (const float*)d_in[4];
    const float* Wv   = (const float*)d_in[5];
    const float* Wo   = (const float*)d_in[6];
    float* out = (float*)d_out;

    float *q, *k, *v, *ao;
    cudaGetSymbolAddress((void**)&q,  g_q);
    cudaGetSymbolAddress((void**)&k,  g_k);
    cudaGetSymbolAddress((void**)&v,  g_v);
    cudaGetSymbolAddress((void**)&ao, g_ao);

    const int attn_smem = (128 * LDQ + 64 * LDK + 64 * LDV + 128 * LDP) * 4;
    cudaFuncSetAttribute(attn_kernel,
                         cudaFuncAttributeMaxDynamicSharedMemorySize, attn_smem);

    dim3 ggrid(D_MOD / 128, M_TOT / 128);   // (16, 32)
    sgemm_nt<<<ggrid, 256>>>(x, Wq, q, M_TOT, D_MOD, D_MOD);
    sgemm_nt<<<ggrid, 256>>>(x, Wk, k, M_TOT, D_MOD, D_MOD);
    sgemm_nt<<<ggrid, 256>>>(x, Wv, v, M_TOT, D_MOD, D_MOD);

    rope_kernel<<<(BATCH * S_LEN * NHEAD * 64) / 256, 256>>>(q, k, cosb, sinb);

    attn_kernel<<<BATCH * NHEAD * (S_LEN / 128), 256, attn_smem>>>(q, k, v, ao);

    sgemm_nt<<<ggrid, 256>>>(ao, Wo, out, M_TOT, D_MOD, D_MOD);
}

// round 4
// speedup vs baseline: 1.7001x; 1.6996x over previous
#include <cuda_runtime.h>
#include <cuda_bf16.h>
#include <math.h>
#include <cstdint>

#define S_LEN   2048
#define D_MOD   2048
#define NHEAD   16
#define HD      128
#define BATCH   2
#define M_TOT   (BATCH * S_LEN)   // 4096

typedef unsigned long long u64;

// ---------------------------------------------------------------------------
// helpers
// ---------------------------------------------------------------------------
__device__ __forceinline__ uint32_t smem_u32(const void* p) {
    uint32_t a;
    asm("{ .reg .u64 t; cvta.to.shared.u64 t, %1; cvt.u32.u64 %0, t; }"
        : "=r"(a) : "l"(p));
    return a;
}
__device__ __forceinline__ u64 pack2(float lo, float hi) {
    u64 r; asm("mov.b64 %0, {%1, %2};" : "=l"(r) : "f"(lo), "f"(hi)); return r;
}
__device__ __forceinline__ float2 unpack2(u64 v) {
    float2 r; asm("mov.b64 {%0, %1}, %2;" : "=f"(r.x), "=f"(r.y) : "l"(v)); return r;
}
__device__ __forceinline__ void ffma2(u64& d, u64 a, u64 b) {
    asm("fma.rn.f32x2 %0, %1, %2, %0;" : "+l"(d) : "l"(a), "l"(b));
}
__device__ __forceinline__ void fmul2(u64& d, u64 c) {
    asm("mul.rn.f32x2 %0, %0, %1;" : "+l"(d) : "l"(c));
}

#define CP_ASYNC16(dst, src) \
    asm volatile("cp.async.cg.shared.global [%0], [%1], 16;" \
                 :: "r"(dst), "l"(src) : "memory")
#define CP_COMMIT() asm volatile("cp.async.commit_group;" ::: "memory")
#define CP_WAIT1()  asm volatile("cp.async.wait_group 1;" ::: "memory")
#define CP_WAIT0()  asm volatile("cp.async.wait_group 0;" ::: "memory")

__device__ __forceinline__ void ldm_x4(uint32_t addr, uint32_t& r0, uint32_t& r1,
                                       uint32_t& r2, uint32_t& r3) {
    asm volatile("ldmatrix.sync.aligned.m8n8.x4.shared.b16 {%0,%1,%2,%3}, [%4];"
                 : "=r"(r0), "=r"(r1), "=r"(r2), "=r"(r3) : "r"(addr));
}
__device__ __forceinline__ void mma_bf16(float* d, const uint32_t* a, const uint32_t* b) {
    asm volatile(
        "mma.sync.aligned.m16n8k16.row.col.f32.bf16.bf16.f32 "
        "{%0,%1,%2,%3}, {%4,%5,%6,%7}, {%8,%9}, {%0,%1,%2,%3};"
        : "+f"(d[0]), "+f"(d[1]), "+f"(d[2]), "+f"(d[3])
        : "r"(a[0]), "r"(a[1]), "r"(a[2]), "r"(a[3]), "r"(b[0]), "r"(b[1]));
}

// ---------------------------------------------------------------------------
// Scratch (device globals: allocation-free rule)
// ---------------------------------------------------------------------------
__device__ float g_q [M_TOT * D_MOD];
__device__ float g_k [M_TOT * D_MOD];
__device__ float g_v [M_TOT * D_MOD];
__device__ float g_ao[M_TOT * D_MOD];

__device__ __nv_bfloat16 g_xhi [M_TOT * D_MOD];
__device__ __nv_bfloat16 g_xlo [M_TOT * D_MOD];
__device__ __nv_bfloat16 g_whi [4][D_MOD * D_MOD];
__device__ __nv_bfloat16 g_wlo [4][D_MOD * D_MOD];
__device__ __nv_bfloat16 g_aohi[M_TOT * D_MOD];
__device__ __nv_bfloat16 g_aolo[M_TOT * D_MOD];

// ---------------------------------------------------------------------------
// Split fp32 -> (hi, lo) bf16 pair.   lo = bf16(x - float(hi))
// ---------------------------------------------------------------------------
__global__ __launch_bounds__(256) void split_bf16_kernel(
    const float4* __restrict__ src, uint2* __restrict__ hi, uint2* __restrict__ lo, int n4)
{
    int i = blockIdx.x * blockDim.x + threadIdx.x;
    if (i >= n4) return;
    float4 x = src[i];
    __nv_bfloat16 h0 = __float2bfloat16(x.x);
    __nv_bfloat16 h1 = __float2bfloat16(x.y);
    __nv_bfloat16 h2 = __float2bfloat16(x.z);
    __nv_bfloat16 h3 = __float2bfloat16(x.w);
    __nv_bfloat16 l0 = __float2bfloat16(x.x - __bfloat162float(h0));
    __nv_bfloat16 l1 = __float2bfloat16(x.y - __bfloat162float(h1));
    __nv_bfloat16 l2 = __float2bfloat16(x.z - __bfloat162float(h2));
    __nv_bfloat16 l3 = __float2bfloat16(x.w - __bfloat162float(h3));
    __nv_bfloat162 ha; ha.x = h0; ha.y = h1;
    __nv_bfloat162 hb; hb.x = h2; hb.y = h3;
    __nv_bfloat162 la; la.x = l0; la.y = l1;
    __nv_bfloat162 lb; lb.x = l2; lb.y = l3;
    uint2 hv, lv;
    hv.x = *reinterpret_cast<uint32_t*>(&ha); hv.y = *reinterpret_cast<uint32_t*>(&hb);
    lv.x = *reinterpret_cast<uint32_t*>(&la); lv.y = *reinterpret_cast<uint32_t*>(&lb);
    hi[i] = hv; lo[i] = lv;
}

// ---------------------------------------------------------------------------
// HMMA bf16-split GEMM NT: C[M,N] = A[M,K] * B[N,K]^T  (fp32 via 3 products)
// CTA 128x128, BK=32, 256 threads (8 warps, warp tile 64x32), cp.async pipe.
// SMEM per stage: 4 tiles of 128 x 32 bf16 (row pitch 40 halves = 80 B).
// ---------------------------------------------------------------------------
#define TPITCH   80                     // bytes per smem row (40 halves)
#define TSZ      (128 * TPITCH)         // 10240 bytes per tile
#define STAGE_SZ (4 * TSZ)              // Ah, Al, Bh, Bl = 40960
#define GEMM_SMEM (2 * STAGE_SZ)        // 81920

__device__ __forceinline__ void g2s_stage(
    uint32_t sbase, const __nv_bfloat16* s0, const __nv_bfloat16* s1,
    const __nv_bfloat16* s2, const __nv_bfloat16* s3, int kc, int tid)
{
#pragma unroll
    for (int t = 0; t < 2; t++) {
        int idx = tid + t * 256;          // 0..511
        int row = idx >> 2;               // 0..127
        int c16 = idx & 3;                // 16-byte chunk within 64B row
        uint32_t d = sbase + row * TPITCH + c16 * 16;
        size_t g = (size_t)row * D_MOD + kc + c16 * 8;
        CP_ASYNC16(d + 0 * TSZ, s0 + g);
        CP_ASYNC16(d + 1 * TSZ, s1 + g);
        CP_ASYNC16(d + 2 * TSZ, s2 + g);
        CP_ASYNC16(d + 3 * TSZ, s3 + g);
    }
}

__global__ __launch_bounds__(256, 1) void gemm_hmma(
    const __nv_bfloat16* __restrict__ Ahi, const __nv_bfloat16* __restrict__ Alo,
    const __nv_bfloat16* __restrict__ Bhi, const __nv_bfloat16* __restrict__ Blo,
    float* __restrict__ C)
{
    extern __shared__ char smem[];
    uint32_t sb = smem_u32(smem);
    const int tid  = threadIdx.x;
    const int wid  = tid >> 5;
    const int lane = tid & 31;
    const int wm   = wid & 1;          // 0..1  (64-row slab)
    const int wn   = wid >> 1;         // 0..3  (32-col slab)
    const int bm = blockIdx.y * 128;
    const int bn = blockIdx.x * 128;

    const __nv_bfloat16* pAh = Ahi + (size_t)bm * D_MOD;
    const __nv_bfloat16* pAl = Alo + (size_t)bm * D_MOD;
    const __nv_bfloat16* pBh = Bhi + (size_t)bn * D_MOD;
    const __nv_bfloat16* pBl = Blo + (size_t)bn * D_MOD;

    float acc[4][4][4];
#pragma unroll
    for (int i = 0; i < 4; i++)
#pragma unroll
        for (int j = 0; j < 4; j++)
#pragma unroll
            for (int e = 0; e < 4; e++) acc[i][j][e] = 0.f;

    // ldmatrix lane addresses (byte offsets within a tile)
    // A x4: lanes 0-15 rows (lane&15) @k0 ; lanes 16-31 same rows @k0+8
    const uint32_t a_off = (uint32_t)((lane & 15) * TPITCH + (lane >> 4) * 16);
    // B x4 (covers two n8 tiles): row = ntp*16 + (lane>>4)*8 + (lane&7), col = k0 + ((lane>>3)&1)*8
    const uint32_t b_off = (uint32_t)(((lane >> 4) * 8 + (lane & 7)) * TPITCH +
                                      ((lane >> 3) & 1) * 16);

    const int nk = D_MOD / 32;   // 64
    g2s_stage(sb, pAh, pAl, pBh, pBl, 0, tid);
    CP_COMMIT();

    for (int c = 0; c < nk; c++) {
        const uint32_t stg = sb + (c & 1) * STAGE_SZ;
        if (c + 1 < nk) {
            g2s_stage(sb + ((c + 1) & 1) * STAGE_SZ, pAh, pAl, pBh, pBl, (c + 1) * 32, tid);
            CP_COMMIT();
            CP_WAIT1();
        } else {
            CP_WAIT0();
        }
        __syncthreads();

#pragma unroll
        for (int s = 0; s < 2; s++) {
            const uint32_t k0b = s * 32;   // 16 halves = 32 bytes
            // load A fragments (hi & lo), 4 m-tiles each
            uint32_t ah[4][4], al[4][4];
#pragma unroll
            for (int mt = 0; mt < 4; mt++) {
                uint32_t base = stg + (wm * 64 + mt * 16) * TPITCH + k0b + a_off;
                ldm_x4(base,          ah[mt][0], ah[mt][1], ah[mt][2], ah[mt][3]);
                ldm_x4(base + TSZ,    al[mt][0], al[mt][1], al[mt][2], al[mt][3]);
            }
            // load B fragments (hi & lo), 4 n-tiles via 2 x4 loads each
            uint32_t bh[4][2], bl[4][2];
#pragma unroll
            for (int ntp = 0; ntp < 2; ntp++) {
                uint32_t base = stg + 2 * TSZ + (wn * 32 + ntp * 16) * TPITCH + k0b + b_off;
                ldm_x4(base,       bh[2*ntp][0], bh[2*ntp][1], bh[2*ntp+1][0], bh[2*ntp+1][1]);
                ldm_x4(base + TSZ, bl[2*ntp][0], bl[2*ntp][1], bl[2*ntp+1][0], bl[2*ntp+1][1]);
            }
            // 3-product accumulate
#pragma unroll
            for (int mt = 0; mt < 4; mt++)
#pragma unroll
                for (int nt = 0; nt < 4; nt++) {
                    mma_bf16(acc[mt][nt], ah[mt], bh[nt]);
                    mma_bf16(acc[mt][nt], ah[mt], bl[nt]);
                    mma_bf16(acc[mt][nt], al[mt], bh[nt]);
                }
        }
        __syncthreads();
    }

    // epilogue
    const int mrow = bm + wm * 64 + (lane >> 2);
    const int ncol = bn + wn * 32 + (lane & 3) * 2;
#pragma unroll
    for (int mt = 0; mt < 4; mt++)
#pragma unroll
        for (int nt = 0; nt < 4; nt++) {
            float* c0 = C + (size_t)(mrow + mt * 16)     * D_MOD + ncol + nt * 8;
            float* c1 = C + (size_t)(mrow + mt * 16 + 8) * D_MOD + ncol + nt * 8;
            *reinterpret_cast<float2*>(c0) = make_float2(acc[mt][nt][0], acc[mt][nt][1]);
            *reinterpret_cast<float2*>(c1) = make_float2(acc[mt][nt][2], acc[mt][nt][3]);
        }
}

// ---------------------------------------------------------------------------
// RoPE: in-place on q and k laid out [B, S, H, HD]
// ---------------------------------------------------------------------------
__global__ __launch_bounds__(256) void rope_kernel(
    float* __restrict__ q, float* __restrict__ k,
    const float* __restrict__ cosb, const float* __restrict__ sinb)
{
    int idx = blockIdx.x * blockDim.x + threadIdx.x;
    int d = idx & 63;
    int h = (idx >> 6) & 15;
    int s = (idx >> 10) & 2047;
    int b = idx >> 21;

    size_t base = ((size_t)(b * S_LEN + s)) * D_MOD + h * HD;
    float c1 = cosb[s * HD + d];
    float s1 = sinb[s * HD + d];
    float c2 = cosb[s * HD + 64 + d];
    float s2 = sinb[s * HD + 64 + d];

    float q1 = q[base + d], q2 = q[base + 64 + d];
    q[base + d]      = q1 * c1 - q2 * s1;
    q[base + 64 + d] = q2 * c2 + q1 * s2;

    float k1 = k[base + d], k2 = k[base + 64 + d];
    k[base + d]      = k1 * c1 - k2 * s1;
    k[base + 64 + d] = k2 * c2 + k1 * s2;
}

// ---------------------------------------------------------------------------
// Flash attention (causal), fp32. Br=128, Bc=64, hd=128, 256 threads.
// ---------------------------------------------------------------------------
#define LDQ 132
#define LDK 132
#define LDV 132
#define LDP 68

__global__ __launch_bounds__(256, 1) void attn_kernel(
    const float* __restrict__ Qg, const float* __restrict__ Kg,
    const float* __restrict__ Vg, float* __restrict__ Og)
{
    extern __shared__ float sm[];
    float* Qs = sm;
    float* Ks = Qs + 128 * LDQ;
    float* Vs = Ks + 64 * LDK;
    float* Ps = Vs + 64 * LDV;

    const int tid = threadIdx.x;
    const int tx = tid & 15;
    const int ty = tid >> 4;
    const int bid = blockIdx.x;
    const int qb = 15 - (bid >> 5);
    const int bh = bid & 31;
    const int b  = bh >> 4;
    const int h  = bh & 15;

    const size_t row0 = (size_t)b * S_LEN;
    const int    hoff = h * HD;
    const int    q0   = qb * 128;

#pragma unroll
    for (int it = 0; it < 16; it++) {
        int idx = tid + it * 256;
        int r = idx >> 5;
        int c = (idx & 31) << 2;
        float4 v = *reinterpret_cast<const float4*>(
            &Qg[(row0 + q0 + r) * D_MOD + hoff + c]);
        *reinterpret_cast<float4*>(&Qs[r * LDQ + c]) = v;
    }

    int rrow[8];
#pragma unroll
    for (int i = 0; i < 8; i++)
        rrow[i] = (i < 4) ? (ty * 4 + i) : (64 + ty * 4 + (i - 4));

    float m[8], l[8];
    u64 o2[8][4];
#pragma unroll
    for (int i = 0; i < 8; i++) {
        m[i] = -1e30f; l[i] = 0.f;
#pragma unroll
        for (int j = 0; j < 4; j++) o2[i][j] = 0ull;
    }

    const float scale = 0.08838834764831845f;
    const int kb_max = qb * 2 + 1;

    for (int kb = 0; kb <= kb_max; kb++) {
        __syncthreads();
#pragma unroll
        for (int it = 0; it < 8; it++) {
            int idx = tid + it * 256;
            int r = idx >> 5;
            int c = (idx & 31) << 2;
            size_t g = (row0 + kb * 64 + r) * D_MOD + hoff + c;
            *reinterpret_cast<float4*>(&Ks[r * LDK + c]) =
                *reinterpret_cast<const float4*>(&Kg[g]);
            *reinterpret_cast<float4*>(&Vs[r * LDV + c]) =
                *reinterpret_cast<const float4*>(&Vg[g]);
        }
        __syncthreads();

        u64 sacc2[4][4];
#pragma unroll
        for (int ip = 0; ip < 4; ip++)
#pragma unroll
            for (int j = 0; j < 4; j++) sacc2[ip][j] = 0ull;

#pragma unroll 2
        for (int kk = 0; kk < 128; kk += 4) {
            float4 bf[4];
#pragma unroll
            for (int j = 0; j < 4; j++)
                bf[j] = *reinterpret_cast<const float4*>(&Ks[(tx + 16 * j) * LDK + kk]);
            u64 bb[4][4];
#pragma unroll
            for (int j = 0; j < 4; j++) {
                bb[0][j] = pack2(bf[j].x, bf[j].x);
                bb[1][j] = pack2(bf[j].y, bf[j].y);
                bb[2][j] = pack2(bf[j].z, bf[j].z);
                bb[3][j] = pack2(bf[j].w, bf[j].w);
            }
#pragma unroll
            for (int ip = 0; ip < 4; ip++) {
                float4 af0 = *reinterpret_cast<const float4*>(&Qs[rrow[2 * ip]     * LDQ + kk]);
                float4 af1 = *reinterpret_cast<const float4*>(&Qs[rrow[2 * ip + 1] * LDQ + kk]);
                u64 aa[4];
                aa[0] = pack2(af0.x, af1.x);
                aa[1] = pack2(af0.y, af1.y);
                aa[2] = pack2(af0.z, af1.z);
                aa[3] = pack2(af0.w, af1.w);
#pragma unroll
                for (int j = 0; j < 4; j++) {
                    ffma2(sacc2[ip][j], aa[0], bb[0][j]);
                    ffma2(sacc2[ip][j], aa[1], bb[1][j]);
                    ffma2(sacc2[ip][j], aa[2], bb[2][j]);
                    ffma2(sacc2[ip][j], aa[3], bb[3][j]);
                }
            }
        }

        float sacc[8][4];
#pragma unroll
        for (int ip = 0; ip < 4; ip++)
#pragma unroll
            for (int j = 0; j < 4; j++) {
                float2 s2v = unpack2(sacc2[ip][j]);
                sacc[2 * ip][j]     = s2v.x;
                sacc[2 * ip + 1][j] = s2v.y;
            }

#pragma unroll
        for (int i = 0; i < 8; i++) {
            int grow = q0 + rrow[i];
            float mx = m[i];
            float sv[4];
#pragma unroll
            for (int j = 0; j < 4; j++) {
                float v = sacc[i][j] * scale;
                int col = kb * 64 + tx + 16 * j;
                if (col > grow) v = -1e30f;
                sv[j] = v;
                mx = fmaxf(mx, v);
            }
#pragma unroll
            for (int off = 8; off >= 1; off >>= 1)
                mx = fmaxf(mx, __shfl_xor_sync(0xffffffffu, mx, off));

            float corr = __expf(m[i] - mx);
            m[i] = mx;
            float psum = 0.f;
#pragma unroll
            for (int j = 0; j < 4; j++) {
                float p = __expf(sv[j] - mx);
                psum += p;
                Ps[rrow[i] * LDP + tx + 16 * j] = p;
            }
            l[i] = l[i] * corr + psum;
            u64 cp = pack2(corr, corr);
#pragma unroll
            for (int j = 0; j < 4; j++) fmul2(o2[i][j], cp);
        }
        __syncthreads();

#pragma unroll 2
        for (int jj = 0; jj < 64; jj += 4) {
            u64 vv[4][4];
#pragma unroll
            for (int t = 0; t < 4; t++) {
                float4 a = *reinterpret_cast<const float4*>(&Vs[(jj + t) * LDV + tx * 4]);
                float4 c = *reinterpret_cast<const float4*>(&Vs[(jj + t) * LDV + 64 + tx * 4]);
                vv[t][0] = pack2(a.x, a.y); vv[t][1] = pack2(a.z, a.w);
                vv[t][2] = pack2(c.x, c.y); vv[t][3] = pack2(c.z, c.w);
            }
#pragma unroll
            for (int i = 0; i < 8; i++) {
                float4 pf = *reinterpret_cast<const float4*>(&Ps[rrow[i] * LDP + jj]);
                u64 pp[4];
                pp[0] = pack2(pf.x, pf.x); pp[1] = pack2(pf.y, pf.y);
                pp[2] = pack2(pf.z, pf.z); pp[3] = pack2(pf.w, pf.w);
#pragma unroll
                for (int t = 0; t < 4; t++)
#pragma unroll
                    for (int jp = 0; jp < 4; jp++)
                        ffma2(o2[i][jp], pp[t], vv[t][jp]);
            }
        }
    }

#pragma unroll
    for (int i = 0; i < 8; i++) {
        float lt = l[i];
#pragma unroll
        for (int off = 8; off >= 1; off >>= 1)
            lt += __shfl_xor_sync(0xffffffffu, lt, off);
        float inv = 1.f / lt;
        size_t obase = (row0 + q0 + rrow[i]) * D_MOD + hoff;
        float2 c0 = unpack2(o2[i][0]);
        float2 c1 = unpack2(o2[i][1]);
        float2 c2 = unpack2(o2[i][2]);
        float2 c3 = unpack2(o2[i][3]);
        float4 oa = make_float4(c0.x * inv, c0.y * inv, c1.x * inv, c1.y * inv);
        float4 ob = make_float4(c2.x * inv, c2.y * inv, c3.x * inv, c3.y * inv);
        *reinterpret_cast<float4*>(&Og[obase + tx * 4])      = oa;
        *reinterpret_cast<float4*>(&Og[obase + 64 + tx * 4]) = ob;
    }
}

// ---------------------------------------------------------------------------
extern "C" void kernel_launch(void* const* d_in, const int* in_sizes, int n_in,
                              void* d_out, int out_size)
{
    const float* x    = (const float*)d_in[0];
    const float* cosb = (const float*)d_in[1];
    const float* sinb = (const float*)d_in[2];
    const float* Wq   = (const float*)d_in[3];
    const float* Wk   = (const float*)d_in[4];
    const float* Wv   = (const float*)d_in[5];
    const float* Wo   = (const float*)d_in[6];
    float* out = (float*)d_out;

    float *q, *k, *v, *ao;
    cudaGetSymbolAddress((void**)&q,  g_q);
    cudaGetSymbolAddress((void**)&k,  g_k);
    cudaGetSymbolAddress((void**)&v,  g_v);
    cudaGetSymbolAddress((void**)&ao, g_ao);
    __nv_bfloat16 *xhi, *xlo, *whi, *wlo, *aohi, *aolo;
    cudaGetSymbolAddress((void**)&xhi,  g_xhi);
    cudaGetSymbolAddress((void**)&xlo,  g_xlo);
    cudaGetSymbolAddress((void**)&whi,  g_whi);
    cudaGetSymbolAddress((void**)&wlo,  g_wlo);
    cudaGetSymbolAddress((void**)&aohi, g_aohi);
    cudaGetSymbolAddress((void**)&aolo, g_aolo);

    const int attn_smem = (128 * LDQ + 64 * LDK + 64 * LDV + 128 * LDP) * 4;
    cudaFuncSetAttribute(attn_kernel,
                         cudaFuncAttributeMaxDynamicSharedMemorySize, attn_smem);
    cudaFuncSetAttribute(gemm_hmma,
                         cudaFuncAttributeMaxDynamicSharedMemorySize, GEMM_SMEM);

    const int nx4 = (M_TOT * D_MOD) / 4;
    const int nw4 = (D_MOD * D_MOD) / 4;
    const float* Ws[4] = {Wq, Wk, Wv, Wo};

    split_bf16_kernel<<<nx4 / 256, 256>>>((const float4*)x, (uint2*)xhi, (uint2*)xlo, nx4);
    for (int i = 0; i < 4; i++)
        split_bf16_kernel<<<nw4 / 256, 256>>>((const float4*)Ws[i],
            (uint2*)(whi + (size_t)i * D_MOD * D_MOD),
            (uint2*)(wlo + (size_t)i * D_MOD * D_MOD), nw4);

    dim3 ggrid(D_MOD / 128, M_TOT / 128);   // (16, 32)
    gemm_hmma<<<ggrid, 256, GEMM_SMEM>>>(xhi, xlo,
        whi + 0 * (size_t)D_MOD * D_MOD, wlo + 0 * (size_t)D_MOD * D_MOD, q);
    gemm_hmma<<<ggrid, 256, GEMM_SMEM>>>(xhi, xlo,
        whi + 1 * (size_t)D_MOD * D_MOD, wlo + 1 * (size_t)D_MOD * D_MOD, k);
    gemm_hmma<<<ggrid, 256, GEMM_SMEM>>>(xhi, xlo,
        whi + 2 * (size_t)D_MOD * D_MOD, wlo + 2 * (size_t)D_MOD * D_MOD, v);

    rope_kernel<<<(M_TOT * NHEAD * 64) / 256, 256>>>(q, k, cosb, sinb);

    attn_kernel<<<BATCH * NHEAD * (S_LEN / 128), 256, attn_smem>>>(q, k, v, ao);

    split_bf16_kernel<<<nx4 / 256, 256>>>((const float4*)ao, (uint2*)aohi, (uint2*)aolo, nx4);
    gemm_hmma<<<ggrid, 256, GEMM_SMEM>>>(aohi, aolo,
        whi + 3 * (size_t)D_MOD * D_MOD, wlo + 3 * (size_t)D_MOD * D_MOD, out);
}

// round 5
// speedup vs baseline: 2.3753x; 1.3972x over previous
#include <cuda_runtime.h>
#include <cuda_bf16.h>
#include <math.h>
#include <cstdint>

#define S_LEN   2048
#define D_MOD   2048
#define NHEAD   16
#define HD      128
#define BATCH   2
#define M_TOT   (BATCH * S_LEN)   // 4096

typedef unsigned long long u64;

// ---------------------------------------------------------------------------
// helpers
// ---------------------------------------------------------------------------
__device__ __forceinline__ uint32_t smem_u32(const void* p) {
    uint32_t a;
    asm("{ .reg .u64 t; cvta.to.shared.u64 t, %1; cvt.u32.u64 %0, t; }"
        : "=r"(a) : "l"(p));
    return a;
}

#define CP_ASYNC16(dst, src) \
    asm volatile("cp.async.cg.shared.global [%0], [%1], 16;" \
                 :: "r"(dst), "l"(src) : "memory")
#define CP_COMMIT() asm volatile("cp.async.commit_group;" ::: "memory")
#define CP_WAIT1()  asm volatile("cp.async.wait_group 1;" ::: "memory")
#define CP_WAIT0()  asm volatile("cp.async.wait_group 0;" ::: "memory")

__device__ __forceinline__ void ldm_x4(uint32_t addr, uint32_t& r0, uint32_t& r1,
                                       uint32_t& r2, uint32_t& r3) {
    asm volatile("ldmatrix.sync.aligned.m8n8.x4.shared.b16 {%0,%1,%2,%3}, [%4];"
                 : "=r"(r0), "=r"(r1), "=r"(r2), "=r"(r3) : "r"(addr));
}
__device__ __forceinline__ void ldm_x4t(uint32_t addr, uint32_t& r0, uint32_t& r1,
                                        uint32_t& r2, uint32_t& r3) {
    asm volatile("ldmatrix.sync.aligned.m8n8.x4.trans.shared.b16 {%0,%1,%2,%3}, [%4];"
                 : "=r"(r0), "=r"(r1), "=r"(r2), "=r"(r3) : "r"(addr));
}
__device__ __forceinline__ void mma_bf16(float* d, const uint32_t* a, const uint32_t* b) {
    asm volatile(
        "mma.sync.aligned.m16n8k16.row.col.f32.bf16.bf16.f32 "
        "{%0,%1,%2,%3}, {%4,%5,%6,%7}, {%8,%9}, {%0,%1,%2,%3};"
        : "+f"(d[0]), "+f"(d[1]), "+f"(d[2]), "+f"(d[3])
        : "r"(a[0]), "r"(a[1]), "r"(a[2]), "r"(a[3]), "r"(b[0]), "r"(b[1]));
}
__device__ __forceinline__ uint32_t bf16x2_pack(float lo, float hi) {
    uint32_t r;
    asm("cvt.rn.bf16x2.f32 %0, %1, %2;" : "=r"(r) : "f"(hi), "f"(lo));
    return r;
}
// split two floats into bf16 hi pack + residual lo pack
__device__ __forceinline__ uint32_t split2(float a, float b, uint32_t& lo) {
    uint32_t h = bf16x2_pack(a, b);
    float ha = __uint_as_float(h << 16);
    float hb = __uint_as_float(h & 0xffff0000u);
    lo = bf16x2_pack(a - ha, b - hb);
    return h;
}
__device__ __forceinline__ float ex2f(float x) {
    float y; asm("ex2.approx.ftz.f32 %0, %1;" : "=f"(y) : "f"(x)); return y;
}

// ---------------------------------------------------------------------------
// Scratch (device globals: allocation-free rule)
// ---------------------------------------------------------------------------
__device__ float g_q [M_TOT * D_MOD];
__device__ float g_k [M_TOT * D_MOD];
__device__ float g_v [M_TOT * D_MOD];

__device__ __nv_bfloat16 g_xhi [M_TOT * D_MOD];
__device__ __nv_bfloat16 g_xlo [M_TOT * D_MOD];
__device__ __nv_bfloat16 g_whi [4][D_MOD * D_MOD];
__device__ __nv_bfloat16 g_wlo [4][D_MOD * D_MOD];
__device__ __nv_bfloat16 g_aohi[M_TOT * D_MOD];
__device__ __nv_bfloat16 g_aolo[M_TOT * D_MOD];
__device__ __nv_bfloat16 g_qhi [M_TOT * D_MOD];
__device__ __nv_bfloat16 g_qlo [M_TOT * D_MOD];
__device__ __nv_bfloat16 g_khi [M_TOT * D_MOD];
__device__ __nv_bfloat16 g_klo [M_TOT * D_MOD];
__device__ __nv_bfloat16 g_vhi [M_TOT * D_MOD];
__device__ __nv_bfloat16 g_vlo [M_TOT * D_MOD];

// ---------------------------------------------------------------------------
// Split fp32 -> (hi, lo) bf16 pair.
// ---------------------------------------------------------------------------
__global__ __launch_bounds__(256) void split_bf16_kernel(
    const float4* __restrict__ src, uint2* __restrict__ hi, uint2* __restrict__ lo, int n4)
{
    int i = blockIdx.x * blockDim.x + threadIdx.x;
    if (i >= n4) return;
    float4 x = src[i];
    uint2 hv, lv;
    hv.x = split2(x.x, x.y, lv.x);
    hv.y = split2(x.z, x.w, lv.y);
    hi[i] = hv; lo[i] = lv;
}

// ---------------------------------------------------------------------------
// HMMA bf16-split GEMM NT: C[M,N] = A[M,K] * B[N,K]^T  (fp32 via 3 products)
// ---------------------------------------------------------------------------
#define TPITCH   80
#define TSZ      (128 * TPITCH)
#define STAGE_SZ (4 * TSZ)
#define GEMM_SMEM (2 * STAGE_SZ)

__device__ __forceinline__ void g2s_stage(
    uint32_t sbase, const __nv_bfloat16* s0, const __nv_bfloat16* s1,
    const __nv_bfloat16* s2, const __nv_bfloat16* s3, int kc, int tid)
{
#pragma unroll
    for (int t = 0; t < 2; t++) {
        int idx = tid + t * 256;
        int row = idx >> 2;
        int c16 = idx & 3;
        uint32_t d = sbase + row * TPITCH + c16 * 16;
        size_t g = (size_t)row * D_MOD + kc + c16 * 8;
        CP_ASYNC16(d + 0 * TSZ, s0 + g);
        CP_ASYNC16(d + 1 * TSZ, s1 + g);
        CP_ASYNC16(d + 2 * TSZ, s2 + g);
        CP_ASYNC16(d + 3 * TSZ, s3 + g);
    }
}

__global__ __launch_bounds__(256, 1) void gemm_hmma(
    const __nv_bfloat16* __restrict__ Ahi, const __nv_bfloat16* __restrict__ Alo,
    const __nv_bfloat16* __restrict__ Bhi, const __nv_bfloat16* __restrict__ Blo,
    float* __restrict__ C)
{
    extern __shared__ char smem[];
    uint32_t sb = smem_u32(smem);
    const int tid  = threadIdx.x;
    const int wid  = tid >> 5;
    const int lane = tid & 31;
    const int wm   = wid & 1;
    const int wn   = wid >> 1;
    const int bm = blockIdx.y * 128;
    const int bn = blockIdx.x * 128;

    const __nv_bfloat16* pAh = Ahi + (size_t)bm * D_MOD;
    const __nv_bfloat16* pAl = Alo + (size_t)bm * D_MOD;
    const __nv_bfloat16* pBh = Bhi + (size_t)bn * D_MOD;
    const __nv_bfloat16* pBl = Blo + (size_t)bn * D_MOD;

    float acc[4][4][4];
#pragma unroll
    for (int i = 0; i < 4; i++)
#pragma unroll
        for (int j = 0; j < 4; j++)
#pragma unroll
            for (int e = 0; e < 4; e++) acc[i][j][e] = 0.f;

    const uint32_t a_off = (uint32_t)((lane & 15) * TPITCH + (lane >> 4) * 16);
    const uint32_t b_off = (uint32_t)(((lane >> 4) * 8 + (lane & 7)) * TPITCH +
                                      ((lane >> 3) & 1) * 16);

    const int nk = D_MOD / 32;
    g2s_stage(sb, pAh, pAl, pBh, pBl, 0, tid);
    CP_COMMIT();

    for (int c = 0; c < nk; c++) {
        const uint32_t stg = sb + (c & 1) * STAGE_SZ;
        if (c + 1 < nk) {
            g2s_stage(sb + ((c + 1) & 1) * STAGE_SZ, pAh, pAl, pBh, pBl, (c + 1) * 32, tid);
            CP_COMMIT();
            CP_WAIT1();
        } else {
            CP_WAIT0();
        }
        __syncthreads();

#pragma unroll
        for (int s = 0; s < 2; s++) {
            const uint32_t k0b = s * 32;
            uint32_t ah[4][4], al[4][4];
#pragma unroll
            for (int mt = 0; mt < 4; mt++) {
                uint32_t base = stg + (wm * 64 + mt * 16) * TPITCH + k0b + a_off;
                ldm_x4(base,       ah[mt][0], ah[mt][1], ah[mt][2], ah[mt][3]);
                ldm_x4(base + TSZ, al[mt][0], al[mt][1], al[mt][2], al[mt][3]);
            }
            uint32_t bh[4][2], bl[4][2];
#pragma unroll
            for (int ntp = 0; ntp < 2; ntp++) {
                uint32_t base = stg + 2 * TSZ + (wn * 32 + ntp * 16) * TPITCH + k0b + b_off;
                ldm_x4(base,       bh[2*ntp][0], bh[2*ntp][1], bh[2*ntp+1][0], bh[2*ntp+1][1]);
                ldm_x4(base + TSZ, bl[2*ntp][0], bl[2*ntp][1], bl[2*ntp+1][0], bl[2*ntp+1][1]);
            }
#pragma unroll
            for (int mt = 0; mt < 4; mt++)
#pragma unroll
                for (int nt = 0; nt < 4; nt++) {
                    mma_bf16(acc[mt][nt], ah[mt], bh[nt]);
                    mma_bf16(acc[mt][nt], ah[mt], bl[nt]);
                    mma_bf16(acc[mt][nt], al[mt], bh[nt]);
                }
        }
        __syncthreads();
    }

    const int mrow = bm + wm * 64 + (lane >> 2);
    const int ncol = bn + wn * 32 + (lane & 3) * 2;
#pragma unroll
    for (int mt = 0; mt < 4; mt++)
#pragma unroll
        for (int nt = 0; nt < 4; nt++) {
            float* c0 = C + (size_t)(mrow + mt * 16)     * D_MOD + ncol + nt * 8;
            float* c1 = C + (size_t)(mrow + mt * 16 + 8) * D_MOD + ncol + nt * 8;
            *reinterpret_cast<float2*>(c0) = make_float2(acc[mt][nt][0], acc[mt][nt][1]);
            *reinterpret_cast<float2*>(c1) = make_float2(acc[mt][nt][2], acc[mt][nt][3]);
        }
}

// ---------------------------------------------------------------------------
// RoPE + split to bf16 hi/lo.  q,k fp32 [B,S,H,HD] -> qhi/qlo/khi/klo bf16.
// one thread per (b,s,h,d2) with d2 = 2 adjacent dims in first half (d<64)
// ---------------------------------------------------------------------------
__global__ __launch_bounds__(256) void rope_split_kernel(
    const float* __restrict__ q, const float* __restrict__ k,
    const float* __restrict__ cosb, const float* __restrict__ sinb,
    uint32_t* __restrict__ qhi, uint32_t* __restrict__ qlo,
    uint32_t* __restrict__ khi, uint32_t* __restrict__ klo)
{
    int idx = blockIdx.x * blockDim.x + threadIdx.x;   // B*S*H*32
    int d = (idx & 31) * 2;
    int h = (idx >> 5) & 15;
    int s = (idx >> 9) & 2047;
    int b = idx >> 20;

    size_t base = ((size_t)(b * S_LEN + s)) * D_MOD + h * HD;
    float c1a = cosb[s * HD + d],      c1b = cosb[s * HD + d + 1];
    float s1a = sinb[s * HD + d],      s1b = sinb[s * HD + d + 1];
    float c2a = cosb[s * HD + 64 + d], c2b = cosb[s * HD + 64 + d + 1];
    float s2a = sinb[s * HD + 64 + d], s2b = sinb[s * HD + 64 + d + 1];

    float qa1 = q[base + d],     qb1 = q[base + d + 1];
    float qa2 = q[base + 64 + d], qb2 = q[base + 64 + d + 1];
    float oa1 = qa1 * c1a - qa2 * s1a, ob1 = qb1 * c1b - qb2 * s1b;
    float oa2 = qa2 * c2a + qa1 * s2a, ob2 = qb2 * c2b + qb1 * s2b;
    uint32_t lo;
    uint32_t i1 = (uint32_t)((base + d) >> 1);
    uint32_t i2 = (uint32_t)((base + 64 + d) >> 1);
    qhi[i1] = split2(oa1, ob1, lo); qlo[i1] = lo;
    qhi[i2] = split2(oa2, ob2, lo); qlo[i2] = lo;

    float ka1 = k[base + d],      kb1 = k[base + d + 1];
    float ka2 = k[base + 64 + d], kb2 = k[base + 64 + d + 1];
    float pa1 = ka1 * c1a - ka2 * s1a, pb1 = kb1 * c1b - kb2 * s1b;
    float pa2 = ka2 * c2a + ka1 * s2a, pb2 = kb2 * c2b + kb1 * s2b;
    khi[i1] = split2(pa1, pb1, lo); klo[i1] = lo;
    khi[i2] = split2(pa2, pb2, lo); klo[i2] = lo;
}

// ---------------------------------------------------------------------------
// Flash attention (causal) with HMMA bf16 3-product split.
// Br=128, Bc=64, hd=128. 256 threads = 8 warps, warp owns 16 q-rows.
// Output written directly as bf16 hi/lo split (for the Wo GEMM).
// ---------------------------------------------------------------------------
#define AP    136               // smem pitch in halves
#define APB   (AP * 2)          // 272 bytes
#define QTILE (128 * APB)       // 34816
#define KVT   (64 * APB)        // 17408
#define KVSTG (4 * KVT)         // 69632
#define SKV0  (2 * QTILE)
#define ATTN_SMEM (2 * QTILE + 2 * KVSTG)   // 208896

__device__ __forceinline__ void attn_g2s_kv(
    uint32_t dst, const __nv_bfloat16* kh, const __nv_bfloat16* kl,
    const __nv_bfloat16* vh, const __nv_bfloat16* vl,
    size_t gbase, int tid)
{
    const __nv_bfloat16* ptrs[4] = {kh, kl, vh, vl};
#pragma unroll
    for (int t = 0; t < 4; t++) {
#pragma unroll
        for (int i = 0; i < 4; i++) {
            int idx = tid + i * 256;          // 0..1023
            int r = idx >> 4;                  // 0..63
            int c = idx & 15;
            CP_ASYNC16(dst + t * KVT + r * APB + c * 16,
                       ptrs[t] + gbase + (size_t)r * D_MOD + c * 8);
        }
    }
}

__global__ __launch_bounds__(256, 1) void attn_mma(
    const __nv_bfloat16* __restrict__ qh_, const __nv_bfloat16* __restrict__ ql_,
    const __nv_bfloat16* __restrict__ kh_, const __nv_bfloat16* __restrict__ kl_,
    const __nv_bfloat16* __restrict__ vh_, const __nv_bfloat16* __restrict__ vl_,
    uint32_t* __restrict__ aohi, uint32_t* __restrict__ aolo)
{
    extern __shared__ char smem[];
    uint32_t sb = smem_u32(smem);
    const int tid  = threadIdx.x;
    const int wid  = tid >> 5;
    const int lane = tid & 31;
    const int bid = blockIdx.x;
    const int qb = 15 - (bid >> 5);
    const int bh = bid & 31;
    const int b  = bh >> 4;
    const int h  = bh & 15;

    const size_t row0 = (size_t)b * S_LEN;
    const int    hoff = h * HD;
    const int    q0   = qb * 128;

    // prologue: Q hi/lo + KV stage 0 (one cp.async group)
    {
        const size_t qg = (row0 + q0) * D_MOD + hoff;
#pragma unroll
        for (int i = 0; i < 8; i++) {
            int idx = tid + i * 256;          // 0..2047
            int r = idx >> 4;                  // 0..127
            int c = idx & 15;
            uint32_t d = sb + r * APB + c * 16;
            size_t g = qg + (size_t)r * D_MOD + c * 8;
            CP_ASYNC16(d,         qh_ + g);
            CP_ASYNC16(d + QTILE, ql_ + g);
        }
        attn_g2s_kv(sb + SKV0, kh_, kl_, vh_, vl_, row0 * D_MOD + hoff, tid);
        CP_COMMIT();
    }

    float oacc[16][4];
#pragma unroll
    for (int j = 0; j < 16; j++)
#pragma unroll
        for (int e = 0; e < 4; e++) oacc[j][e] = 0.f;
    float m0 = -1e30f, m1 = -1e30f, l0 = 0.f, l1 = 0.f;

    const float sl2 = 0.08838834764831845f * 1.4426950408889634f;  // scale*log2e
    const int kb_max = qb * 2 + 1;
    const int rg0 = q0 + wid * 16 + (lane >> 2);
    const int rg1 = rg0 + 8;

    const uint32_t a_off = (uint32_t)((lane & 15) * APB + (lane >> 4) * 16);
    const uint32_t b_off = (uint32_t)(((lane >> 4) * 8 + (lane & 7)) * APB +
                                      ((lane >> 3) & 1) * 16);
    const uint32_t v_off = (uint32_t)(((lane & 7) + ((lane >> 3) & 1) * 8) * APB +
                                      (lane >> 4) * 16);

    for (int kb = 0; kb <= kb_max; kb++) {
        if (kb + 1 <= kb_max) {
            attn_g2s_kv(sb + SKV0 + ((kb + 1) & 1) * KVSTG, kh_, kl_, vh_, vl_,
                        (row0 + (kb + 1) * 64) * D_MOD + hoff, tid);
            CP_COMMIT();
            CP_WAIT1();
        } else {
            CP_WAIT0();
        }
        __syncthreads();

        const uint32_t stg = sb + SKV0 + (kb & 1) * KVSTG;

        // ---- S = Q K^T (3 products) ----
        float sacc[8][4];
#pragma unroll
        for (int j = 0; j < 8; j++)
#pragma unroll
            for (int e = 0; e < 4; e++) sacc[j][e] = 0.f;

#pragma unroll
        for (int t = 0; t < 8; t++) {
            uint32_t qa = sb + (wid * 16) * APB + t * 32 + a_off;
            uint32_t qhF[4], qlF[4];
            ldm_x4(qa,         qhF[0], qhF[1], qhF[2], qhF[3]);
            ldm_x4(qa + QTILE, qlF[0], qlF[1], qlF[2], qlF[3]);
#pragma unroll
            for (int ng = 0; ng < 4; ng++) {
                uint32_t ka = stg + (ng * 16) * APB + t * 32 + b_off;
                uint32_t khF[4], klF[4];
                ldm_x4(ka,       khF[0], khF[1], khF[2], khF[3]);
                ldm_x4(ka + KVT, klF[0], klF[1], klF[2], klF[3]);
                mma_bf16(sacc[2*ng],   qhF, khF + 0);
                mma_bf16(sacc[2*ng],   qhF, klF + 0);
                mma_bf16(sacc[2*ng],   qlF, khF + 0);
                mma_bf16(sacc[2*ng+1], qhF, khF + 2);
                mma_bf16(sacc[2*ng+1], qhF, klF + 2);
                mma_bf16(sacc[2*ng+1], qlF, khF + 2);
            }
        }

        // ---- softmax (log2 domain) ----
        const bool diag = (kb >= 2 * qb);
        float mx0 = -1e30f, mx1 = -1e30f;
#pragma unroll
        for (int j = 0; j < 8; j++) {
            int colb = kb * 64 + 8 * j + 2 * (lane & 3);
#pragma unroll
            for (int e = 0; e < 4; e++) {
                float v = sacc[j][e] * sl2;
                if (diag) {
                    int col = colb + (e & 1);
                    int row = (e < 2) ? rg0 : rg1;
                    if (col > row) v = -1e30f;
                }
                sacc[j][e] = v;
            }
            mx0 = fmaxf(mx0, fmaxf(sacc[j][0], sacc[j][1]));
            mx1 = fmaxf(mx1, fmaxf(sacc[j][2], sacc[j][3]));
        }
        mx0 = fmaxf(mx0, __shfl_xor_sync(0xffffffffu, mx0, 1));
        mx0 = fmaxf(mx0, __shfl_xor_sync(0xffffffffu, mx0, 2));
        mx1 = fmaxf(mx1, __shfl_xor_sync(0xffffffffu, mx1, 1));
        mx1 = fmaxf(mx1, __shfl_xor_sync(0xffffffffu, mx1, 2));

        float mn0 = fmaxf(m0, mx0), mn1 = fmaxf(m1, mx1);
        float corr0 = ex2f(m0 - mn0), corr1 = ex2f(m1 - mn1);
        m0 = mn0; m1 = mn1;

        float ps0 = 0.f, ps1 = 0.f;
#pragma unroll
        for (int j = 0; j < 8; j++) {
            sacc[j][0] = ex2f(sacc[j][0] - mn0);
            sacc[j][1] = ex2f(sacc[j][1] - mn0);
            sacc[j][2] = ex2f(sacc[j][2] - mn1);
            sacc[j][3] = ex2f(sacc[j][3] - mn1);
            ps0 += sacc[j][0] + sacc[j][1];
            ps1 += sacc[j][2] + sacc[j][3];
        }
        l0 = l0 * corr0 + ps0;
        l1 = l1 * corr1 + ps1;
#pragma unroll
        for (int j = 0; j < 16; j++) {
            oacc[j][0] *= corr0; oacc[j][1] *= corr0;
            oacc[j][2] *= corr1; oacc[j][3] *= corr1;
        }

        // ---- O += P V (3 products), P packed in registers ----
#pragma unroll
        for (int t = 0; t < 4; t++) {
            uint32_t pah[4], pal[4];
            pah[0] = split2(sacc[2*t][0],   sacc[2*t][1],   pal[0]);
            pah[1] = split2(sacc[2*t][2],   sacc[2*t][3],   pal[1]);
            pah[2] = split2(sacc[2*t+1][0], sacc[2*t+1][1], pal[2]);
            pah[3] = split2(sacc[2*t+1][2], sacc[2*t+1][3], pal[3]);
#pragma unroll
            for (int ng = 0; ng < 8; ng++) {
                uint32_t va = stg + 2 * KVT + (t * 16) * APB + ng * 32 + v_off;
                uint32_t vhF[4], vlF[4];
                ldm_x4t(va,       vhF[0], vhF[1], vhF[2], vhF[3]);
                ldm_x4t(va + KVT, vlF[0], vlF[1], vlF[2], vlF[3]);
                mma_bf16(oacc[2*ng],   pah, vhF + 0);
                mma_bf16(oacc[2*ng],   pah, vlF + 0);
                mma_bf16(oacc[2*ng],   pal, vhF + 0);
                mma_bf16(oacc[2*ng+1], pah, vhF + 2);
                mma_bf16(oacc[2*ng+1], pah, vlF + 2);
                mma_bf16(oacc[2*ng+1], pal, vhF + 2);
            }
        }
        __syncthreads();
    }

    // ---- epilogue ----
    l0 += __shfl_xor_sync(0xffffffffu, l0, 1);
    l0 += __shfl_xor_sync(0xffffffffu, l0, 2);
    l1 += __shfl_xor_sync(0xffffffffu, l1, 1);
    l1 += __shfl_xor_sync(0xffffffffu, l1, 2);
    float inv0 = 1.f / l0, inv1 = 1.f / l1;

    const uint32_t i0 = (uint32_t)(((row0 + rg0) * D_MOD + hoff + 2 * (lane & 3)) >> 1);
    const uint32_t i1 = (uint32_t)(((row0 + rg1) * D_MOD + hoff + 2 * (lane & 3)) >> 1);
#pragma unroll
    for (int j = 0; j < 16; j++) {
        uint32_t lo;
        uint32_t hi = split2(oacc[j][0] * inv0, oacc[j][1] * inv0, lo);
        aohi[i0 + 4 * j] = hi; aolo[i0 + 4 * j] = lo;
        hi = split2(oacc[j][2] * inv1, oacc[j][3] * inv1, lo);
        aohi[i1 + 4 * j] = hi; aolo[i1 + 4 * j] = lo;
    }
}

// ---------------------------------------------------------------------------
extern "C" void kernel_launch(void* const* d_in, const int* in_sizes, int n_in,
                              void* d_out, int out_size)
{
    const float* x    = (const float*)d_in[0];
    const float* cosb = (const float*)d_in[1];
    const float* sinb = (const float*)d_in[2];
    const float* Wq   = (const float*)d_in[3];
    const float* Wk   = (const float*)d_in[4];
    const float* Wv   = (const float*)d_in[5];
    const float* Wo   = (const float*)d_in[6];
    float* out = (float*)d_out;

    float *q, *k, *v;
    cudaGetSymbolAddress((void**)&q, g_q);
    cudaGetSymbolAddress((void**)&k, g_k);
    cudaGetSymbolAddress((void**)&v, g_v);
    __nv_bfloat16 *xhi, *xlo, *whi, *wlo, *aohi, *aolo;
    __nv_bfloat16 *qhi, *qlo, *khi, *klo, *vhi, *vlo;
    cudaGetSymbolAddress((void**)&xhi,  g_xhi);
    cudaGetSymbolAddress((void**)&xlo,  g_xlo);
    cudaGetSymbolAddress((void**)&whi,  g_whi);
    cudaGetSymbolAddress((void**)&wlo,  g_wlo);
    cudaGetSymbolAddress((void**)&aohi, g_aohi);
    cudaGetSymbolAddress((void**)&aolo, g_aolo);
    cudaGetSymbolAddress((void**)&qhi,  g_qhi);
    cudaGetSymbolAddress((void**)&qlo,  g_qlo);
    cudaGetSymbolAddress((void**)&khi,  g_khi);
    cudaGetSymbolAddress((void**)&klo,  g_klo);
    cudaGetSymbolAddress((void**)&vhi,  g_vhi);
    cudaGetSymbolAddress((void**)&vlo,  g_vlo);

    cudaFuncSetAttribute(gemm_hmma,
                         cudaFuncAttributeMaxDynamicSharedMemorySize, GEMM_SMEM);
    cudaFuncSetAttribute(attn_mma,
                         cudaFuncAttributeMaxDynamicSharedMemorySize, ATTN_SMEM);

    const int nx4 = (M_TOT * D_MOD) / 4;
    const int nw4 = (D_MOD * D_MOD) / 4;
    const float* Ws[4] = {Wq, Wk, Wv, Wo};

    split_bf16_kernel<<<nx4 / 256, 256>>>((const float4*)x, (uint2*)xhi, (uint2*)xlo, nx4);
    for (int i = 0; i < 4; i++)
        split_bf16_kernel<<<nw4 / 256, 256>>>((const float4*)Ws[i],
            (uint2*)(whi + (size_t)i * D_MOD * D_MOD),
            (uint2*)(wlo + (size_t)i * D_MOD * D_MOD), nw4);

    dim3 ggrid(D_MOD / 128, M_TOT / 128);   // (16, 32)
    gemm_hmma<<<ggrid, 256, GEMM_SMEM>>>(xhi, xlo,
        whi + 0 * (size_t)D_MOD * D_MOD, wlo + 0 * (size_t)D_MOD * D_MOD, q);
    gemm_hmma<<<ggrid, 256, GEMM_SMEM>>>(xhi, xlo,
        whi + 1 * (size_t)D_MOD * D_MOD, wlo + 1 * (size_t)D_MOD * D_MOD, k);
    gemm_hmma<<<ggrid, 256, GEMM_SMEM>>>(xhi, xlo,
        whi + 2 * (size_t)D_MOD * D_MOD, wlo + 2 * (size_t)D_MOD * D_MOD, v);

    rope_split_kernel<<<(M_TOT * NHEAD * 32) / 256, 256>>>(
        q, k, cosb, sinb, (uint32_t*)qhi, (uint32_t*)qlo, (uint32_t*)khi, (uint32_t*)klo);
    split_bf16_kernel<<<nx4 / 256, 256>>>((const float4*)v, (uint2*)vhi, (uint2*)vlo, nx4);

    attn_mma<<<BATCH * NHEAD * (S_LEN / 128), 256, ATTN_SMEM>>>(
        qhi, qlo, khi, klo, vhi, vlo, (uint32_t*)aohi, (uint32_t*)aolo);

    gemm_hmma<<<ggrid, 256, GEMM_SMEM>>>(aohi, aolo,
        whi + 3 * (size_t)D_MOD * D_MOD, wlo + 3 * (size_t)D_MOD * D_MOD, out);
}

// round 6
// speedup vs baseline: 2.5384x; 1.0687x over previous
#include <cuda_runtime.h>
#include <cuda_bf16.h>
#include <math.h>
#include <cstdint>

#define S_LEN   2048
#define D_MOD   2048
#define NHEAD   16
#define HD      128
#define BATCH   2
#define M_TOT   (BATCH * S_LEN)   // 4096

// ---------------------------------------------------------------------------
// helpers
// ---------------------------------------------------------------------------
__device__ __forceinline__ uint32_t smem_u32(const void* p) {
    uint32_t a;
    asm("{ .reg .u64 t; cvta.to.shared.u64 t, %1; cvt.u32.u64 %0, t; }"
        : "=r"(a) : "l"(p));
    return a;
}

#define CP_ASYNC16(dst, src) \
    asm volatile("cp.async.cg.shared.global [%0], [%1], 16;" \
                 :: "r"(dst), "l"(src) : "memory")
#define CP_COMMIT() asm volatile("cp.async.commit_group;" ::: "memory")
#define CP_WAIT1()  asm volatile("cp.async.wait_group 1;" ::: "memory")
#define CP_WAIT0()  asm volatile("cp.async.wait_group 0;" ::: "memory")

__device__ __forceinline__ void ldm_x4(uint32_t addr, uint32_t& r0, uint32_t& r1,
                                       uint32_t& r2, uint32_t& r3) {
    asm volatile("ldmatrix.sync.aligned.m8n8.x4.shared.b16 {%0,%1,%2,%3}, [%4];"
                 : "=r"(r0), "=r"(r1), "=r"(r2), "=r"(r3) : "r"(addr));
}
__device__ __forceinline__ void ldm_x4t(uint32_t addr, uint32_t& r0, uint32_t& r1,
                                        uint32_t& r2, uint32_t& r3) {
    asm volatile("ldmatrix.sync.aligned.m8n8.x4.trans.shared.b16 {%0,%1,%2,%3}, [%4];"
                 : "=r"(r0), "=r"(r1), "=r"(r2), "=r"(r3) : "r"(addr));
}
__device__ __forceinline__ void mma_bf16(float* d, const uint32_t* a, const uint32_t* b) {
    asm volatile(
        "mma.sync.aligned.m16n8k16.row.col.f32.bf16.bf16.f32 "
        "{%0,%1,%2,%3}, {%4,%5,%6,%7}, {%8,%9}, {%0,%1,%2,%3};"
        : "+f"(d[0]), "+f"(d[1]), "+f"(d[2]), "+f"(d[3])
        : "r"(a[0]), "r"(a[1]), "r"(a[2]), "r"(a[3]), "r"(b[0]), "r"(b[1]));
}
__device__ __forceinline__ uint32_t bf16x2_pack(float lo, float hi) {
    uint32_t r;
    asm("cvt.rn.bf16x2.f32 %0, %1, %2;" : "=r"(r) : "f"(hi), "f"(lo));
    return r;
}
__device__ __forceinline__ uint32_t split2(float a, float b, uint32_t& lo) {
    uint32_t h = bf16x2_pack(a, b);
    float ha = __uint_as_float(h << 16);
    float hb = __uint_as_float(h & 0xffff0000u);
    lo = bf16x2_pack(a - ha, b - hb);
    return h;
}
__device__ __forceinline__ float ex2f(float x) {
    float y; asm("ex2.approx.ftz.f32 %0, %1;" : "=f"(y) : "f"(x)); return y;
}

// ---------------------------------------------------------------------------
// Scratch (device globals: allocation-free rule)
// ---------------------------------------------------------------------------
__device__ __nv_bfloat16 g_xhi [M_TOT * D_MOD];
__device__ __nv_bfloat16 g_xlo [M_TOT * D_MOD];
__device__ __nv_bfloat16 g_whi [4][D_MOD * D_MOD];
__device__ __nv_bfloat16 g_wlo [4][D_MOD * D_MOD];
__device__ __nv_bfloat16 g_aohi[M_TOT * D_MOD];
__device__ __nv_bfloat16 g_aolo[M_TOT * D_MOD];
__device__ __nv_bfloat16 g_qhi [M_TOT * D_MOD];
__device__ __nv_bfloat16 g_qlo [M_TOT * D_MOD];
__device__ __nv_bfloat16 g_khi [M_TOT * D_MOD];
__device__ __nv_bfloat16 g_klo [M_TOT * D_MOD];
__device__ __nv_bfloat16 g_vhi [M_TOT * D_MOD];
__device__ __nv_bfloat16 g_vlo [M_TOT * D_MOD];

// ---------------------------------------------------------------------------
// Split fp32 -> (hi, lo) bf16 pair.  4 float4 per thread, grid-strided.
// ---------------------------------------------------------------------------
__global__ __launch_bounds__(256) void split_bf16_kernel(
    const float4* __restrict__ src, uint2* __restrict__ hi, uint2* __restrict__ lo, int n4)
{
    int stride = n4 >> 2;   // n4 divisible by 4*256 in all our uses
    int base = blockIdx.x * blockDim.x + threadIdx.x;
#pragma unroll
    for (int t = 0; t < 4; t++) {
        int i = base + t * stride;
        float4 x = src[i];
        uint2 hv, lv;
        hv.x = split2(x.x, x.y, lv.x);
        hv.y = split2(x.z, x.w, lv.y);
        hi[i] = hv; lo[i] = lv;
    }
}

// ---------------------------------------------------------------------------
// HMMA bf16-split GEMM NT core: C[M,N] = A[M,K] * B[N,K]^T (fp32, 3 products)
// CTA 128x128, BK=32, 256 threads (8 warps, warp tile 64x32), cp.async pipe.
// ---------------------------------------------------------------------------
#define TPITCH   80
#define TSZ      (128 * TPITCH)
#define STAGE_SZ (4 * TSZ)
#define GEMM_SMEM (2 * STAGE_SZ)      // 81920 (also covers 128x136 fp32 epi buf)

__device__ __forceinline__ void g2s_stage(
    uint32_t sbase, const __nv_bfloat16* s0, const __nv_bfloat16* s1,
    const __nv_bfloat16* s2, const __nv_bfloat16* s3, int kc, int tid)
{
#pragma unroll
    for (int t = 0; t < 2; t++) {
        int idx = tid + t * 256;
        int row = idx >> 2;
        int c16 = idx & 3;
        uint32_t d = sbase + row * TPITCH + c16 * 16;
        size_t g = (size_t)row * D_MOD + kc + c16 * 8;
        CP_ASYNC16(d + 0 * TSZ, s0 + g);
        CP_ASYNC16(d + 1 * TSZ, s1 + g);
        CP_ASYNC16(d + 2 * TSZ, s2 + g);
        CP_ASYNC16(d + 3 * TSZ, s3 + g);
    }
}

// mainloop shared by both GEMM kernels; acc[4][4][4] filled
__device__ __forceinline__ void gemm_mainloop(
    uint32_t sb, const __nv_bfloat16* pAh, const __nv_bfloat16* pAl,
    const __nv_bfloat16* pBh, const __nv_bfloat16* pBl,
    int tid, int wm, int wn, int lane, float acc[4][4][4])
{
#pragma unroll
    for (int i = 0; i < 4; i++)
#pragma unroll
        for (int j = 0; j < 4; j++)
#pragma unroll
            for (int e = 0; e < 4; e++) acc[i][j][e] = 0.f;

    const uint32_t a_off = (uint32_t)((lane & 15) * TPITCH + (lane >> 4) * 16);
    const uint32_t b_off = (uint32_t)(((lane >> 4) * 8 + (lane & 7)) * TPITCH +
                                      ((lane >> 3) & 1) * 16);

    const int nk = D_MOD / 32;
    g2s_stage(sb, pAh, pAl, pBh, pBl, 0, tid);
    CP_COMMIT();

    for (int c = 0; c < nk; c++) {
        const uint32_t stg = sb + (c & 1) * STAGE_SZ;
        if (c + 1 < nk) {
            g2s_stage(sb + ((c + 1) & 1) * STAGE_SZ, pAh, pAl, pBh, pBl, (c + 1) * 32, tid);
            CP_COMMIT();
            CP_WAIT1();
        } else {
            CP_WAIT0();
        }
        __syncthreads();

#pragma unroll
        for (int s = 0; s < 2; s++) {
            const uint32_t k0b = s * 32;
            uint32_t ah[4][4], al[4][4];
#pragma unroll
            for (int mt = 0; mt < 4; mt++) {
                uint32_t base = stg + (wm * 64 + mt * 16) * TPITCH + k0b + a_off;
                ldm_x4(base,       ah[mt][0], ah[mt][1], ah[mt][2], ah[mt][3]);
                ldm_x4(base + TSZ, al[mt][0], al[mt][1], al[mt][2], al[mt][3]);
            }
            uint32_t bh[4][2], bl[4][2];
#pragma unroll
            for (int ntp = 0; ntp < 2; ntp++) {
                uint32_t base = stg + 2 * TSZ + (wn * 32 + ntp * 16) * TPITCH + k0b + b_off;
                ldm_x4(base,       bh[2*ntp][0], bh[2*ntp][1], bh[2*ntp+1][0], bh[2*ntp+1][1]);
                ldm_x4(base + TSZ, bl[2*ntp][0], bl[2*ntp][1], bl[2*ntp+1][0], bl[2*ntp+1][1]);
            }
#pragma unroll
            for (int mt = 0; mt < 4; mt++)
#pragma unroll
                for (int nt = 0; nt < 4; nt++) {
                    mma_bf16(acc[mt][nt], ah[mt], bh[nt]);
                    mma_bf16(acc[mt][nt], ah[mt], bl[nt]);
                    mma_bf16(acc[mt][nt], al[mt], bh[nt]);
                }
        }
        __syncthreads();
    }
}

// Wo GEMM: fp32 output
__global__ __launch_bounds__(256, 1) void gemm_hmma(
    const __nv_bfloat16* __restrict__ Ahi, const __nv_bfloat16* __restrict__ Alo,
    const __nv_bfloat16* __restrict__ Bhi, const __nv_bfloat16* __restrict__ Blo,
    float* __restrict__ C)
{
    extern __shared__ char smem[];
    uint32_t sb = smem_u32(smem);
    const int tid  = threadIdx.x;
    const int wid  = tid >> 5;
    const int lane = tid & 31;
    const int wm   = wid & 1;
    const int wn   = wid >> 1;
    const int bm = blockIdx.y * 128;
    const int bn = blockIdx.x * 128;

    float acc[4][4][4];
    gemm_mainloop(sb, Ahi + (size_t)bm * D_MOD, Alo + (size_t)bm * D_MOD,
                  Bhi + (size_t)bn * D_MOD, Blo + (size_t)bn * D_MOD,
                  tid, wm, wn, lane, acc);

    const int mrow = bm + wm * 64 + (lane >> 2);
    const int ncol = bn + wn * 32 + (lane & 3) * 2;
#pragma unroll
    for (int mt = 0; mt < 4; mt++)
#pragma unroll
        for (int nt = 0; nt < 4; nt++) {
            float* c0 = C + (size_t)(mrow + mt * 16)     * D_MOD + ncol + nt * 8;
            float* c1 = C + (size_t)(mrow + mt * 16 + 8) * D_MOD + ncol + nt * 8;
            *reinterpret_cast<float2*>(c0) = make_float2(acc[mt][nt][0], acc[mt][nt][1]);
            *reinterpret_cast<float2*>(c1) = make_float2(acc[mt][nt][2], acc[mt][nt][3]);
        }
}

// Fused QKV GEMM: z = blockIdx.z selects weight/output.
// z=0 -> Q (rope + split), z=1 -> K (rope + split), z=2 -> V (split only)
#define EPIP 136   // fp32 epilogue smem pitch
__global__ __launch_bounds__(256, 1) void gemm_qkv(
    const __nv_bfloat16* __restrict__ Ahi, const __nv_bfloat16* __restrict__ Alo,
    const __nv_bfloat16* __restrict__ Whi, const __nv_bfloat16* __restrict__ Wlo,
    const float* __restrict__ cosb, const float* __restrict__ sinb,
    uint32_t* __restrict__ qhi, uint32_t* __restrict__ qlo,
    uint32_t* __restrict__ khi, uint32_t* __restrict__ klo,
    uint32_t* __restrict__ vhi, uint32_t* __restrict__ vlo)
{
    extern __shared__ char smem[];
    uint32_t sb = smem_u32(smem);
    const int tid  = threadIdx.x;
    const int wid  = tid >> 5;
    const int lane = tid & 31;
    const int wm   = wid & 1;
    const int wn   = wid >> 1;
    const int bm = blockIdx.y * 128;
    const int bn = blockIdx.x * 128;
    const int z  = blockIdx.z;

    const size_t woff = (size_t)z * D_MOD * D_MOD;
    float acc[4][4][4];
    gemm_mainloop(sb, Ahi + (size_t)bm * D_MOD, Alo + (size_t)bm * D_MOD,
                  Whi + woff + (size_t)bn * D_MOD, Wlo + woff + (size_t)bn * D_MOD,
                  tid, wm, wn, lane, acc);

    if (z == 2) {
        // V: direct bf16 hi/lo split
        const int mrow = bm + wm * 64 + (lane >> 2);
        const int ncol = bn + wn * 32 + (lane & 3) * 2;
#pragma unroll
        for (int mt = 0; mt < 4; mt++)
#pragma unroll
            for (int nt = 0; nt < 4; nt++) {
                uint32_t lo;
                size_t i0 = ((size_t)(mrow + mt * 16)     * D_MOD + ncol + nt * 8) >> 1;
                size_t i1 = ((size_t)(mrow + mt * 16 + 8) * D_MOD + ncol + nt * 8) >> 1;
                vhi[i0] = split2(acc[mt][nt][0], acc[mt][nt][1], lo); vlo[i0] = lo;
                vhi[i1] = split2(acc[mt][nt][2], acc[mt][nt][3], lo); vlo[i1] = lo;
            }
        return;
    }

    // Q/K: stage acc tile in smem, then RoPE + split.
    float* sf = reinterpret_cast<float*>(smem);
    const int r0 = wm * 64 + (lane >> 2);
    const int c0 = wn * 32 + (lane & 3) * 2;
#pragma unroll
    for (int mt = 0; mt < 4; mt++)
#pragma unroll
        for (int nt = 0; nt < 4; nt++) {
            sf[(r0 + mt * 16)     * EPIP + c0 + nt * 8]     = acc[mt][nt][0];
            sf[(r0 + mt * 16)     * EPIP + c0 + nt * 8 + 1] = acc[mt][nt][1];
            sf[(r0 + mt * 16 + 8) * EPIP + c0 + nt * 8]     = acc[mt][nt][2];
            sf[(r0 + mt * 16 + 8) * EPIP + c0 + nt * 8 + 1] = acc[mt][nt][3];
        }
    __syncthreads();

    uint32_t* OH = z ? khi : qhi;
    uint32_t* OL = z ? klo : qlo;
#pragma unroll
    for (int it = 0; it < 16; it++) {
        int idx = tid + it * 256;          // 0..4095
        int r = idx >> 5;                  // 0..127
        int d = (idx & 31) * 2;            // 0..62
        float2 v1 = *reinterpret_cast<const float2*>(sf + r * EPIP + d);
        float2 v2 = *reinterpret_cast<const float2*>(sf + r * EPIP + 64 + d);
        int gm = bm + r;
        int srow = gm & (S_LEN - 1);
        float2 c1 = *reinterpret_cast<const float2*>(cosb + srow * HD + d);
        float2 s1 = *reinterpret_cast<const float2*>(sinb + srow * HD + d);
        float2 c2 = *reinterpret_cast<const float2*>(cosb + srow * HD + 64 + d);
        float2 s2 = *reinterpret_cast<const float2*>(sinb + srow * HD + 64 + d);
        float o1x = v1.x * c1.x - v2.x * s1.x;
        float o1y = v1.y * c1.y - v2.y * s1.y;
        float o2x = v2.x * c2.x + v1.x * s2.x;
        float o2y = v2.y * c2.y + v1.y * s2.y;
        size_t base = (size_t)gm * D_MOD + bn;
        uint32_t lo;
        OH[(base + d) >> 1]      = split2(o1x, o1y, lo); OL[(base + d) >> 1]      = lo;
        OH[(base + 64 + d) >> 1] = split2(o2x, o2y, lo); OL[(base + 64 + d) >> 1] = lo;
    }
}

// ---------------------------------------------------------------------------
// Flash attention (causal) with HMMA bf16 3-product split.
// Br=128, Bc=64, hd=128. 256 threads = 8 warps, warp owns 16 q-rows.
// ---------------------------------------------------------------------------
#define AP    136
#define APB   (AP * 2)
#define QTILE (128 * APB)
#define KVT   (64 * APB)
#define KVSTG (4 * KVT)
#define SKV0  (2 * QTILE)
#define ATTN_SMEM (2 * QTILE + 2 * KVSTG)   // 208896

__device__ __forceinline__ void attn_g2s_kv(
    uint32_t dst, const __nv_bfloat16* kh, const __nv_bfloat16* kl,
    const __nv_bfloat16* vh, const __nv_bfloat16* vl,
    size_t gbase, int tid)
{
    const __nv_bfloat16* ptrs[4] = {kh, kl, vh, vl};
#pragma unroll
    for (int t = 0; t < 4; t++) {
#pragma unroll
        for (int i = 0; i < 4; i++) {
            int idx = tid + i * 256;
            int r = idx >> 4;
            int c = idx & 15;
            CP_ASYNC16(dst + t * KVT + r * APB + c * 16,
                       ptrs[t] + gbase + (size_t)r * D_MOD + c * 8);
        }
    }
}

__global__ __launch_bounds__(256, 1) void attn_mma(
    const __nv_bfloat16* __restrict__ qh_, const __nv_bfloat16* __restrict__ ql_,
    const __nv_bfloat16* __restrict__ kh_, const __nv_bfloat16* __restrict__ kl_,
    const __nv_bfloat16* __restrict__ vh_, const __nv_bfloat16* __restrict__ vl_,
    uint32_t* __restrict__ aohi, uint32_t* __restrict__ aolo)
{
    extern __shared__ char smem[];
    uint32_t sb = smem_u32(smem);
    const int tid  = threadIdx.x;
    const int wid  = tid >> 5;
    const int lane = tid & 31;
    const int bid = blockIdx.x;
    const int qb = 15 - (bid >> 5);
    const int bh = bid & 31;
    const int b  = bh >> 4;
    const int h  = bh & 15;

    const size_t row0 = (size_t)b * S_LEN;
    const int    hoff = h * HD;
    const int    q0   = qb * 128;

    {
        const size_t qg = (row0 + q0) * D_MOD + hoff;
#pragma unroll
        for (int i = 0; i < 8; i++) {
            int idx = tid + i * 256;
            int r = idx >> 4;
            int c = idx & 15;
            uint32_t d = sb + r * APB + c * 16;
            size_t g = qg + (size_t)r * D_MOD + c * 8;
            CP_ASYNC16(d,         qh_ + g);
            CP_ASYNC16(d + QTILE, ql_ + g);
        }
        attn_g2s_kv(sb + SKV0, kh_, kl_, vh_, vl_, row0 * D_MOD + hoff, tid);
        CP_COMMIT();
    }

    float oacc[16][4];
#pragma unroll
    for (int j = 0; j < 16; j++)
#pragma unroll
        for (int e = 0; e < 4; e++) oacc[j][e] = 0.f;
    float m0 = -1e30f, m1 = -1e30f, l0 = 0.f, l1 = 0.f;

    const float sl2 = 0.08838834764831845f * 1.4426950408889634f;
    const int kb_max = qb * 2 + 1;
    const int rg0 = q0 + wid * 16 + (lane >> 2);
    const int rg1 = rg0 + 8;

    const uint32_t a_off = (uint32_t)((lane & 15) * APB + (lane >> 4) * 16);
    const uint32_t b_off = (uint32_t)(((lane >> 4) * 8 + (lane & 7)) * APB +
                                      ((lane >> 3) & 1) * 16);
    const uint32_t v_off = (uint32_t)(((lane & 7) + ((lane >> 3) & 1) * 8) * APB +
                                      (lane >> 4) * 16);

    for (int kb = 0; kb <= kb_max; kb++) {
        if (kb + 1 <= kb_max) {
            attn_g2s_kv(sb + SKV0 + ((kb + 1) & 1) * KVSTG, kh_, kl_, vh_, vl_,
                        (row0 + (kb + 1) * 64) * D_MOD + hoff, tid);
            CP_COMMIT();
            CP_WAIT1();
        } else {
            CP_WAIT0();
        }
        __syncthreads();

        const uint32_t stg = sb + SKV0 + (kb & 1) * KVSTG;

        float sacc[8][4];
#pragma unroll
        for (int j = 0; j < 8; j++)
#pragma unroll
            for (int e = 0; e < 4; e++) sacc[j][e] = 0.f;

#pragma unroll
        for (int t = 0; t < 8; t++) {
            uint32_t qa = sb + (wid * 16) * APB + t * 32 + a_off;
            uint32_t qhF[4], qlF[4];
            ldm_x4(qa,         qhF[0], qhF[1], qhF[2], qhF[3]);
            ldm_x4(qa + QTILE, qlF[0], qlF[1], qlF[2], qlF[3]);
#pragma unroll
            for (int ng = 0; ng < 4; ng++) {
                uint32_t ka = stg + (ng * 16) * APB + t * 32 + b_off;
                uint32_t khF[4], klF[4];
                ldm_x4(ka,       khF[0], khF[1], khF[2], khF[3]);
                ldm_x4(ka + KVT, klF[0], klF[1], klF[2], klF[3]);
                mma_bf16(sacc[2*ng],   qhF, khF + 0);
                mma_bf16(sacc[2*ng],   qhF, klF + 0);
                mma_bf16(sacc[2*ng],   qlF, khF + 0);
                mma_bf16(sacc[2*ng+1], qhF, khF + 2);
                mma_bf16(sacc[2*ng+1], qhF, klF + 2);
                mma_bf16(sacc[2*ng+1], qlF, khF + 2);
            }
        }

        const bool diag = (kb >= 2 * qb);
        float mx0 = -1e30f, mx1 = -1e30f;
#pragma unroll
        for (int j = 0; j < 8; j++) {
            int colb = kb * 64 + 8 * j + 2 * (lane & 3);
#pragma unroll
            for (int e = 0; e < 4; e++) {
                float v = sacc[j][e] * sl2;
                if (diag) {
                    int col = colb + (e & 1);
                    int row = (e < 2) ? rg0 : rg1;
                    if (col > row) v = -1e30f;
                }
                sacc[j][e] = v;
            }
            mx0 = fmaxf(mx0, fmaxf(sacc[j][0], sacc[j][1]));
            mx1 = fmaxf(mx1, fmaxf(sacc[j][2], sacc[j][3]));
        }
        mx0 = fmaxf(mx0, __shfl_xor_sync(0xffffffffu, mx0, 1));
        mx0 = fmaxf(mx0, __shfl_xor_sync(0xffffffffu, mx0, 2));
        mx1 = fmaxf(mx1, __shfl_xor_sync(0xffffffffu, mx1, 1));
        mx1 = fmaxf(mx1, __shfl_xor_sync(0xffffffffu, mx1, 2));

        float mn0 = fmaxf(m0, mx0), mn1 = fmaxf(m1, mx1);
        float corr0 = ex2f(m0 - mn0), corr1 = ex2f(m1 - mn1);
        m0 = mn0; m1 = mn1;

        float ps0 = 0.f, ps1 = 0.f;
#pragma unroll
        for (int j = 0; j < 8; j++) {
            sacc[j][0] = ex2f(sacc[j][0] - mn0);
            sacc[j][1] = ex2f(sacc[j][1] - mn0);
            sacc[j][2] = ex2f(sacc[j][2] - mn1);
            sacc[j][3] = ex2f(sacc[j][3] - mn1);
            ps0 += sacc[j][0] + sacc[j][1];
            ps1 += sacc[j][2] + sacc[j][3];
        }
        l0 = l0 * corr0 + ps0;
        l1 = l1 * corr1 + ps1;
#pragma unroll
        for (int j = 0; j < 16; j++) {
            oacc[j][0] *= corr0; oacc[j][1] *= corr0;
            oacc[j][2] *= corr1; oacc[j][3] *= corr1;
        }

#pragma unroll
        for (int t = 0; t < 4; t++) {
            uint32_t pah[4], pal[4];
            pah[0] = split2(sacc[2*t][0],   sacc[2*t][1],   pal[0]);
            pah[1] = split2(sacc[2*t][2],   sacc[2*t][3],   pal[1]);
            pah[2] = split2(sacc[2*t+1][0], sacc[2*t+1][1], pal[2]);
            pah[3] = split2(sacc[2*t+1][2], sacc[2*t+1][3], pal[3]);
#pragma unroll
            for (int ng = 0; ng < 8; ng++) {
                uint32_t va = stg + 2 * KVT + (t * 16) * APB + ng * 32 + v_off;
                uint32_t vhF[4], vlF[4];
                ldm_x4t(va,       vhF[0], vhF[1], vhF[2], vhF[3]);
                ldm_x4t(va + KVT, vlF[0], vlF[1], vlF[2], vlF[3]);
                mma_bf16(oacc[2*ng],   pah, vhF + 0);
                mma_bf16(oacc[2*ng],   pah, vlF + 0);
                mma_bf16(oacc[2*ng],   pal, vhF + 0);
                mma_bf16(oacc[2*ng+1], pah, vhF + 2);
                mma_bf16(oacc[2*ng+1], pah, vlF + 2);
                mma_bf16(oacc[2*ng+1], pal, vhF + 2);
            }
        }
        __syncthreads();
    }

    l0 += __shfl_xor_sync(0xffffffffu, l0, 1);
    l0 += __shfl_xor_sync(0xffffffffu, l0, 2);
    l1 += __shfl_xor_sync(0xffffffffu, l1, 1);
    l1 += __shfl_xor_sync(0xffffffffu, l1, 2);
    float inv0 = 1.f / l0, inv1 = 1.f / l1;

    const uint32_t i0 = (uint32_t)(((row0 + rg0) * D_MOD + hoff + 2 * (lane & 3)) >> 1);
    const uint32_t i1 = (uint32_t)(((row0 + rg1) * D_MOD + hoff + 2 * (lane & 3)) >> 1);
#pragma unroll
    for (int j = 0; j < 16; j++) {
        uint32_t lo;
        uint32_t hi = split2(oacc[j][0] * inv0, oacc[j][1] * inv0, lo);
        aohi[i0 + 4 * j] = hi; aolo[i0 + 4 * j] = lo;
        hi = split2(oacc[j][2] * inv1, oacc[j][3] * inv1, lo);
        aohi[i1 + 4 * j] = hi; aolo[i1 + 4 * j] = lo;
    }
}

// ---------------------------------------------------------------------------
extern "C" void kernel_launch(void* const* d_in, const int* in_sizes, int n_in,
                              void* d_out, int out_size)
{
    const float* x    = (const float*)d_in[0];
    const float* cosb = (const float*)d_in[1];
    const float* sinb = (const float*)d_in[2];
    const float* Wq   = (const float*)d_in[3];
    const float* Wk   = (const float*)d_in[4];
    const float* Wv   = (const float*)d_in[5];
    const float* Wo   = (const float*)d_in[6];
    float* out = (float*)d_out;

    __nv_bfloat16 *xhi, *xlo, *whi, *wlo, *aohi, *aolo;
    __nv_bfloat16 *qhi, *qlo, *khi, *klo, *vhi, *vlo;
    cudaGetSymbolAddress((void**)&xhi,  g_xhi);
    cudaGetSymbolAddress((void**)&xlo,  g_xlo);
    cudaGetSymbolAddress((void**)&whi,  g_whi);
    cudaGetSymbolAddress((void**)&wlo,  g_wlo);
    cudaGetSymbolAddress((void**)&aohi, g_aohi);
    cudaGetSymbolAddress((void**)&aolo, g_aolo);
    cudaGetSymbolAddress((void**)&qhi,  g_qhi);
    cudaGetSymbolAddress((void**)&qlo,  g_qlo);
    cudaGetSymbolAddress((void**)&khi,  g_khi);
    cudaGetSymbolAddress((void**)&klo,  g_klo);
    cudaGetSymbolAddress((void**)&vhi,  g_vhi);
    cudaGetSymbolAddress((void**)&vlo,  g_vlo);

    cudaFuncSetAttribute(gemm_hmma,
                         cudaFuncAttributeMaxDynamicSharedMemorySize, GEMM_SMEM);
    cudaFuncSetAttribute(gemm_qkv,
                         cudaFuncAttributeMaxDynamicSharedMemorySize, GEMM_SMEM);
    cudaFuncSetAttribute(attn_mma,
                         cudaFuncAttributeMaxDynamicSharedMemorySize, ATTN_SMEM);

    const int nx4 = (M_TOT * D_MOD) / 4;
    const int nw4 = (D_MOD * D_MOD) / 4;
    const float* Ws[4] = {Wq, Wk, Wv, Wo};

    split_bf16_kernel<<<nx4 / 1024, 256>>>((const float4*)x, (uint2*)xhi, (uint2*)xlo, nx4);
    for (int i = 0; i < 4; i++)
        split_bf16_kernel<<<nw4 / 1024, 256>>>((const float4*)Ws[i],
            (uint2*)(whi + (size_t)i * D_MOD * D_MOD),
            (uint2*)(wlo + (size_t)i * D_MOD * D_MOD), nw4);

    dim3 qkvgrid(D_MOD / 128, M_TOT / 128, 3);   // (16, 32, 3)
    gemm_qkv<<<qkvgrid, 256, GEMM_SMEM>>>(xhi, xlo, whi, wlo, cosb, sinb,
        (uint32_t*)qhi, (uint32_t*)qlo, (uint32_t*)khi, (uint32_t*)klo,
        (uint32_t*)vhi, (uint32_t*)vlo);

    attn_mma<<<BATCH * NHEAD * (S_LEN / 128), 256, ATTN_SMEM>>>(
        qhi, qlo, khi, klo, vhi, vlo, (uint32_t*)aohi, (uint32_t*)aolo);

    dim3 ggrid(D_MOD / 128, M_TOT / 128);   // (16, 32)
    gemm_hmma<<<ggrid, 256, GEMM_SMEM>>>(aohi, aolo,
        whi + 3 * (size_t)D_MOD * D_MOD, wlo + 3 * (size_t)D_MOD * D_MOD, out);
}

// round 7
// speedup vs baseline: 2.5543x; 1.0063x over previous
#include <cuda_runtime.h>
#include <cuda_bf16.h>
#include <math.h>
#include <cstdint>

#define S_LEN   2048
#define D_MOD   2048
#define NHEAD   16
#define HD      128
#define BATCH   2
#define M_TOT   (BATCH * S_LEN)   // 4096

// ---------------------------------------------------------------------------
// helpers
// ---------------------------------------------------------------------------
__device__ __forceinline__ uint32_t smem_u32(const void* p) {
    uint32_t a;
    asm("{ .reg .u64 t; cvta.to.shared.u64 t, %1; cvt.u32.u64 %0, t; }"
        : "=r"(a) : "l"(p));
    return a;
}

#define CP_ASYNC16(dst, src) \
    asm volatile("cp.async.cg.shared.global [%0], [%1], 16;" \
                 :: "r"(dst), "l"(src) : "memory")
#define CP_COMMIT() asm volatile("cp.async.commit_group;" ::: "memory")
#define CP_WAIT1()  asm volatile("cp.async.wait_group 1;" ::: "memory")
#define CP_WAIT0()  asm volatile("cp.async.wait_group 0;" ::: "memory")

__device__ __forceinline__ void ldm_x4(uint32_t addr, uint32_t& r0, uint32_t& r1,
                                       uint32_t& r2, uint32_t& r3) {
    asm volatile("ldmatrix.sync.aligned.m8n8.x4.shared.b16 {%0,%1,%2,%3}, [%4];"
                 : "=r"(r0), "=r"(r1), "=r"(r2), "=r"(r3) : "r"(addr));
}
__device__ __forceinline__ void ldm_x4t(uint32_t addr, uint32_t& r0, uint32_t& r1,
                                        uint32_t& r2, uint32_t& r3) {
    asm volatile("ldmatrix.sync.aligned.m8n8.x4.trans.shared.b16 {%0,%1,%2,%3}, [%4];"
                 : "=r"(r0), "=r"(r1), "=r"(r2), "=r"(r3) : "r"(addr));
}
__device__ __forceinline__ void mma_bf16(float* d, const uint32_t* a, const uint32_t* b) {
    asm volatile(
        "mma.sync.aligned.m16n8k16.row.col.f32.bf16.bf16.f32 "
        "{%0,%1,%2,%3}, {%4,%5,%6,%7}, {%8,%9}, {%0,%1,%2,%3};"
        : "+f"(d[0]), "+f"(d[1]), "+f"(d[2]), "+f"(d[3])
        : "r"(a[0]), "r"(a[1]), "r"(a[2]), "r"(a[3]), "r"(b[0]), "r"(b[1]));
}
__device__ __forceinline__ uint32_t bf16x2_pack(float lo, float hi) {
    uint32_t r;
    asm("cvt.rn.bf16x2.f32 %0, %1, %2;" : "=r"(r) : "f"(hi), "f"(lo));
    return r;
}
__device__ __forceinline__ uint32_t split2(float a, float b, uint32_t& lo) {
    uint32_t h = bf16x2_pack(a, b);
    float ha = __uint_as_float(h << 16);
    float hb = __uint_as_float(h & 0xffff0000u);
    lo = bf16x2_pack(a - ha, b - hb);
    return h;
}
__device__ __forceinline__ float ex2f(float x) {
    float y; asm("ex2.approx.ftz.f32 %0, %1;" : "=f"(y) : "f"(x)); return y;
}

// ---------------------------------------------------------------------------
// Scratch (device globals: allocation-free rule)
// ---------------------------------------------------------------------------
__device__ __nv_bfloat16 g_xhi [M_TOT * D_MOD];
__device__ __nv_bfloat16 g_xlo [M_TOT * D_MOD];
__device__ __nv_bfloat16 g_whi [4][D_MOD * D_MOD];
__device__ __nv_bfloat16 g_wlo [4][D_MOD * D_MOD];
__device__ __nv_bfloat16 g_aohi[M_TOT * D_MOD];
__device__ __nv_bfloat16 g_aolo[M_TOT * D_MOD];
__device__ __nv_bfloat16 g_qhi [M_TOT * D_MOD];
__device__ __nv_bfloat16 g_qlo [M_TOT * D_MOD];
__device__ __nv_bfloat16 g_khi [M_TOT * D_MOD];
__device__ __nv_bfloat16 g_klo [M_TOT * D_MOD];
__device__ __nv_bfloat16 g_vhi [M_TOT * D_MOD];
__device__ __nv_bfloat16 g_vlo [M_TOT * D_MOD];

// ---------------------------------------------------------------------------
// Split fp32 -> (hi, lo) bf16 pair.  4 float4 per thread, grid-strided.
// ---------------------------------------------------------------------------
__global__ __launch_bounds__(256) void split_bf16_kernel(
    const float4* __restrict__ src, uint2* __restrict__ hi, uint2* __restrict__ lo, int n4)
{
    int stride = n4 >> 2;
    int base = blockIdx.x * blockDim.x + threadIdx.x;
#pragma unroll
    for (int t = 0; t < 4; t++) {
        int i = base + t * stride;
        float4 x = src[i];
        uint2 hv, lv;
        hv.x = split2(x.x, x.y, lv.x);
        hv.y = split2(x.z, x.w, lv.y);
        hi[i] = hv; lo[i] = lv;
    }
}

// ---------------------------------------------------------------------------
// HMMA bf16-split GEMM NT core: C[M,N] = A[M,K] * B[N,K]^T (fp32, 3 products)
// CTA 128x128, BK=32, 256 threads, 3-stage cp.async pipe, 1 sync per chunk.
// ---------------------------------------------------------------------------
#define TPITCH   80
#define TSZ      (128 * TPITCH)
#define STAGE_SZ (4 * TSZ)
#define GEMM_SMEM (3 * STAGE_SZ)      // 122880

__device__ __forceinline__ void g2s_stage(
    uint32_t sbase, const __nv_bfloat16* s0, const __nv_bfloat16* s1,
    const __nv_bfloat16* s2, const __nv_bfloat16* s3, int kc, int tid)
{
#pragma unroll
    for (int t = 0; t < 2; t++) {
        int idx = tid + t * 256;
        int row = idx >> 2;
        int c16 = idx & 3;
        uint32_t d = sbase + row * TPITCH + c16 * 16;
        size_t g = (size_t)row * D_MOD + kc + c16 * 8;
        CP_ASYNC16(d + 0 * TSZ, s0 + g);
        CP_ASYNC16(d + 1 * TSZ, s1 + g);
        CP_ASYNC16(d + 2 * TSZ, s2 + g);
        CP_ASYNC16(d + 3 * TSZ, s3 + g);
    }
}

// mainloop shared by both GEMM kernels; acc[4][4][4] filled.
// NOTE: no trailing __syncthreads — callers must sync before reusing smem.
__device__ __forceinline__ void gemm_mainloop(
    uint32_t sb, const __nv_bfloat16* pAh, const __nv_bfloat16* pAl,
    const __nv_bfloat16* pBh, const __nv_bfloat16* pBl,
    int tid, int wm, int wn, int lane, float acc[4][4][4])
{
#pragma unroll
    for (int i = 0; i < 4; i++)
#pragma unroll
        for (int j = 0; j < 4; j++)
#pragma unroll
            for (int e = 0; e < 4; e++) acc[i][j][e] = 0.f;

    const uint32_t a_off = (uint32_t)((lane & 15) * TPITCH + (lane >> 4) * 16);
    const uint32_t b_off = (uint32_t)(((lane >> 4) * 8 + (lane & 7)) * TPITCH +
                                      ((lane >> 3) & 1) * 16);

    const int nk = D_MOD / 32;   // 64
    g2s_stage(sb + 0 * STAGE_SZ, pAh, pAl, pBh, pBl, 0, tid);
    CP_COMMIT();
    g2s_stage(sb + 1 * STAGE_SZ, pAh, pAl, pBh, pBl, 32, tid);
    CP_COMMIT();

    int stg_idx = 0;
    for (int c = 0; c < nk; c++) {
        const uint32_t stg = sb + stg_idx * STAGE_SZ;
        if (c + 1 < nk) { CP_WAIT1(); } else { CP_WAIT0(); }
        __syncthreads();

        // prefetch chunk c+2 into the buffer freed by compute(c-1)
        if (c + 2 < nk) {
            int nidx = stg_idx + 2; if (nidx >= 3) nidx -= 3;
            g2s_stage(sb + nidx * STAGE_SZ, pAh, pAl, pBh, pBl, (c + 2) * 32, tid);
            CP_COMMIT();
        }

#pragma unroll
        for (int s = 0; s < 2; s++) {
            const uint32_t k0b = s * 32;
            uint32_t ah[4][4], al[4][4];
#pragma unroll
            for (int mt = 0; mt < 4; mt++) {
                uint32_t base = stg + (wm * 64 + mt * 16) * TPITCH + k0b + a_off;
                ldm_x4(base,       ah[mt][0], ah[mt][1], ah[mt][2], ah[mt][3]);
                ldm_x4(base + TSZ, al[mt][0], al[mt][1], al[mt][2], al[mt][3]);
            }
            uint32_t bh[4][2], bl[4][2];
#pragma unroll
            for (int ntp = 0; ntp < 2; ntp++) {
                uint32_t base = stg + 2 * TSZ + (wn * 32 + ntp * 16) * TPITCH + k0b + b_off;
                ldm_x4(base,       bh[2*ntp][0], bh[2*ntp][1], bh[2*ntp+1][0], bh[2*ntp+1][1]);
                ldm_x4(base + TSZ, bl[2*ntp][0], bl[2*ntp][1], bl[2*ntp+1][0], bl[2*ntp+1][1]);
            }
#pragma unroll
            for (int mt = 0; mt < 4; mt++)
#pragma unroll
                for (int nt = 0; nt < 4; nt++) {
                    mma_bf16(acc[mt][nt], ah[mt], bh[nt]);
                    mma_bf16(acc[mt][nt], ah[mt], bl[nt]);
                    mma_bf16(acc[mt][nt], al[mt], bh[nt]);
                }
        }
        if (++stg_idx == 3) stg_idx = 0;
    }
}

// Wo GEMM: fp32 output (no smem reuse after mainloop -> no sync needed)
__global__ __launch_bounds__(256, 1) void gemm_hmma(
    const __nv_bfloat16* __restrict__ Ahi, const __nv_bfloat16* __restrict__ Alo,
    const __nv_bfloat16* __restrict__ Bhi, const __nv_bfloat16* __restrict__ Blo,
    float* __restrict__ C)
{
    extern __shared__ char smem[];
    uint32_t sb = smem_u32(smem);
    const int tid  = threadIdx.x;
    const int wid  = tid >> 5;
    const int lane = tid & 31;
    const int wm   = wid & 1;
    const int wn   = wid >> 1;
    const int bm = blockIdx.y * 128;
    const int bn = blockIdx.x * 128;

    float acc[4][4][4];
    gemm_mainloop(sb, Ahi + (size_t)bm * D_MOD, Alo + (size_t)bm * D_MOD,
                  Bhi + (size_t)bn * D_MOD, Blo + (size_t)bn * D_MOD,
                  tid, wm, wn, lane, acc);

    const int mrow = bm + wm * 64 + (lane >> 2);
    const int ncol = bn + wn * 32 + (lane & 3) * 2;
#pragma unroll
    for (int mt = 0; mt < 4; mt++)
#pragma unroll
        for (int nt = 0; nt < 4; nt++) {
            float* c0 = C + (size_t)(mrow + mt * 16)     * D_MOD + ncol + nt * 8;
            float* c1 = C + (size_t)(mrow + mt * 16 + 8) * D_MOD + ncol + nt * 8;
            *reinterpret_cast<float2*>(c0) = make_float2(acc[mt][nt][0], acc[mt][nt][1]);
            *reinterpret_cast<float2*>(c1) = make_float2(acc[mt][nt][2], acc[mt][nt][3]);
        }
}

// Fused QKV GEMM: z selects weight/output. z<2: RoPE+split epilogue, z=2: split.
#define EPIP 136
__global__ __launch_bounds__(256, 1) void gemm_qkv(
    const __nv_bfloat16* __restrict__ Ahi, const __nv_bfloat16* __restrict__ Alo,
    const __nv_bfloat16* __restrict__ Whi, const __nv_bfloat16* __restrict__ Wlo,
    const float* __restrict__ cosb, const float* __restrict__ sinb,
    uint32_t* __restrict__ qhi, uint32_t* __restrict__ qlo,
    uint32_t* __restrict__ khi, uint32_t* __restrict__ klo,
    uint32_t* __restrict__ vhi, uint32_t* __restrict__ vlo)
{
    extern __shared__ char smem[];
    uint32_t sb = smem_u32(smem);
    const int tid  = threadIdx.x;
    const int wid  = tid >> 5;
    const int lane = tid & 31;
    const int wm   = wid & 1;
    const int wn   = wid >> 1;
    const int bm = blockIdx.y * 128;
    const int bn = blockIdx.x * 128;
    const int z  = blockIdx.z;

    const size_t woff = (size_t)z * D_MOD * D_MOD;
    float acc[4][4][4];
    gemm_mainloop(sb, Ahi + (size_t)bm * D_MOD, Alo + (size_t)bm * D_MOD,
                  Whi + woff + (size_t)bn * D_MOD, Wlo + woff + (size_t)bn * D_MOD,
                  tid, wm, wn, lane, acc);

    if (z == 2) {
        const int mrow = bm + wm * 64 + (lane >> 2);
        const int ncol = bn + wn * 32 + (lane & 3) * 2;
#pragma unroll
        for (int mt = 0; mt < 4; mt++)
#pragma unroll
            for (int nt = 0; nt < 4; nt++) {
                uint32_t lo;
                size_t i0 = ((size_t)(mrow + mt * 16)     * D_MOD + ncol + nt * 8) >> 1;
                size_t i1 = ((size_t)(mrow + mt * 16 + 8) * D_MOD + ncol + nt * 8) >> 1;
                vhi[i0] = split2(acc[mt][nt][0], acc[mt][nt][1], lo); vlo[i0] = lo;
                vhi[i1] = split2(acc[mt][nt][2], acc[mt][nt][3], lo); vlo[i1] = lo;
            }
        return;
    }

    // Q/K: stage acc tile in smem (reuses pipeline buffers), then RoPE + split.
    __syncthreads();   // all warps done reading stage smem
    float* sf = reinterpret_cast<float*>(smem);
    const int r0 = wm * 64 + (lane >> 2);
    const int c0 = wn * 32 + (lane & 3) * 2;
#pragma unroll
    for (int mt = 0; mt < 4; mt++)
#pragma unroll
        for (int nt = 0; nt < 4; nt++) {
            sf[(r0 + mt * 16)     * EPIP + c0 + nt * 8]     = acc[mt][nt][0];
            sf[(r0 + mt * 16)     * EPIP + c0 + nt * 8 + 1] = acc[mt][nt][1];
            sf[(r0 + mt * 16 + 8) * EPIP + c0 + nt * 8]     = acc[mt][nt][2];
            sf[(r0 + mt * 16 + 8) * EPIP + c0 + nt * 8 + 1] = acc[mt][nt][3];
        }
    __syncthreads();

    uint32_t* OH = z ? khi : qhi;
    uint32_t* OL = z ? klo : qlo;
#pragma unroll
    for (int it = 0; it < 16; it++) {
        int idx = tid + it * 256;
        int r = idx >> 5;
        int d = (idx & 31) * 2;
        float2 v1 = *reinterpret_cast<const float2*>(sf + r * EPIP + d);
        float2 v2 = *reinterpret_cast<const float2*>(sf + r * EPIP + 64 + d);
        int gm = bm + r;
        int srow = gm & (S_LEN - 1);
        float2 c1 = *reinterpret_cast<const float2*>(cosb + srow * HD + d);
        float2 s1 = *reinterpret_cast<const float2*>(sinb + srow * HD + d);
        float2 c2 = *reinterpret_cast<const float2*>(cosb + srow * HD + 64 + d);
        float2 s2 = *reinterpret_cast<const float2*>(sinb + srow * HD + 64 + d);
        float o1x = v1.x * c1.x - v2.x * s1.x;
        float o1y = v1.y * c1.y - v2.y * s1.y;
        float o2x = v2.x * c2.x + v1.x * s2.x;
        float o2y = v2.y * c2.y + v1.y * s2.y;
        size_t base = (size_t)gm * D_MOD + bn;
        uint32_t lo;
        OH[(base + d) >> 1]      = split2(o1x, o1y, lo); OL[(base + d) >> 1]      = lo;
        OH[(base + 64 + d) >> 1] = split2(o2x, o2y, lo); OL[(base + 64 + d) >> 1] = lo;
    }
}

// ---------------------------------------------------------------------------
// Flash attention (causal) with HMMA bf16 3-product split.
// ---------------------------------------------------------------------------
#define AP    136
#define APB   (AP * 2)
#define QTILE (128 * APB)
#define KVT   (64 * APB)
#define KVSTG (4 * KVT)
#define SKV0  (2 * QTILE)
#define ATTN_SMEM (2 * QTILE + 2 * KVSTG)   // 208896

__device__ __forceinline__ void attn_g2s_kv(
    uint32_t dst, const __nv_bfloat16* kh, const __nv_bfloat16* kl,
    const __nv_bfloat16* vh, const __nv_bfloat16* vl,
    size_t gbase, int tid)
{
    const __nv_bfloat16* ptrs[4] = {kh, kl, vh, vl};
#pragma unroll
    for (int t = 0; t < 4; t++) {
#pragma unroll
        for (int i = 0; i < 4; i++) {
            int idx = tid + i * 256;
            int r = idx >> 4;
            int c = idx & 15;
            CP_ASYNC16(dst + t * KVT + r * APB + c * 16,
                       ptrs[t] + gbase + (size_t)r * D_MOD + c * 8);
        }
    }
}

__global__ __launch_bounds__(256, 1) void attn_mma(
    const __nv_bfloat16* __restrict__ qh_, const __nv_bfloat16* __restrict__ ql_,
    const __nv_bfloat16* __restrict__ kh_, const __nv_bfloat16* __restrict__ kl_,
    const __nv_bfloat16* __restrict__ vh_, const __nv_bfloat16* __restrict__ vl_,
    uint32_t* __restrict__ aohi, uint32_t* __restrict__ aolo)
{
    extern __shared__ char smem[];
    uint32_t sb = smem_u32(smem);
    const int tid  = threadIdx.x;
    const int wid  = tid >> 5;
    const int lane = tid & 31;
    const int bid = blockIdx.x;
    const int qb = 15 - (bid >> 5);
    const int bh = bid & 31;
    const int b  = bh >> 4;
    const int h  = bh & 15;

    const size_t row0 = (size_t)b * S_LEN;
    const int    hoff = h * HD;
    const int    q0   = qb * 128;

    {
        const size_t qg = (row0 + q0) * D_MOD + hoff;
#pragma unroll
        for (int i = 0; i < 8; i++) {
            int idx = tid + i * 256;
            int r = idx >> 4;
            int c = idx & 15;
            uint32_t d = sb + r * APB + c * 16;
            size_t g = qg + (size_t)r * D_MOD + c * 8;
            CP_ASYNC16(d,         qh_ + g);
            CP_ASYNC16(d + QTILE, ql_ + g);
        }
        attn_g2s_kv(sb + SKV0, kh_, kl_, vh_, vl_, row0 * D_MOD + hoff, tid);
        CP_COMMIT();
    }

    float oacc[16][4];
#pragma unroll
    for (int j = 0; j < 16; j++)
#pragma unroll
        for (int e = 0; e < 4; e++) oacc[j][e] = 0.f;
    float m0 = -1e30f, m1 = -1e30f, l0 = 0.f, l1 = 0.f;

    const float sl2 = 0.08838834764831845f * 1.4426950408889634f;
    const int kb_max = qb * 2 + 1;
    const int rg0 = q0 + wid * 16 + (lane >> 2);
    const int rg1 = rg0 + 8;

    const uint32_t a_off = (uint32_t)((lane & 15) * APB + (lane >> 4) * 16);
    const uint32_t b_off = (uint32_t)(((lane >> 4) * 8 + (lane & 7)) * APB +
                                      ((lane >> 3) & 1) * 16);
    const uint32_t v_off = (uint32_t)(((lane & 7) + ((lane >> 3) & 1) * 8) * APB +
                                      (lane >> 4) * 16);

    for (int kb = 0; kb <= kb_max; kb++) {
        if (kb + 1 <= kb_max) {
            attn_g2s_kv(sb + SKV0 + ((kb + 1) & 1) * KVSTG, kh_, kl_, vh_, vl_,
                        (row0 + (kb + 1) * 64) * D_MOD + hoff, tid);
            CP_COMMIT();
            CP_WAIT1();
        } else {
            CP_WAIT0();
        }
        __syncthreads();

        const uint32_t stg = sb + SKV0 + (kb & 1) * KVSTG;

        float sacc[8][4];
#pragma unroll
        for (int j = 0; j < 8; j++)
#pragma unroll
            for (int e = 0; e < 4; e++) sacc[j][e] = 0.f;

#pragma unroll
        for (int t = 0; t < 8; t++) {
            uint32_t qa = sb + (wid * 16) * APB + t * 32 + a_off;
            uint32_t qhF[4], qlF[4];
            ldm_x4(qa,         qhF[0], qhF[1], qhF[2], qhF[3]);
            ldm_x4(qa + QTILE, qlF[0], qlF[1], qlF[2], qlF[3]);
#pragma unroll
            for (int ng = 0; ng < 4; ng++) {
                uint32_t ka = stg + (ng * 16) * APB + t * 32 + b_off;
                uint32_t khF[4], klF[4];
                ldm_x4(ka,       khF[0], khF[1], khF[2], khF[3]);
                ldm_x4(ka + KVT, klF[0], klF[1], klF[2], klF[3]);
                mma_bf16(sacc[2*ng],   qhF, khF + 0);
                mma_bf16(sacc[2*ng],   qhF, klF + 0);
                mma_bf16(sacc[2*ng],   qlF, khF + 0);
                mma_bf16(sacc[2*ng+1], qhF, khF + 2);
                mma_bf16(sacc[2*ng+1], qhF, klF + 2);
                mma_bf16(sacc[2*ng+1], qlF, khF + 2);
            }
        }

        const bool diag = (kb >= 2 * qb);
        float mx0 = -1e30f, mx1 = -1e30f;
#pragma unroll
        for (int j = 0; j < 8; j++) {
            int colb = kb * 64 + 8 * j + 2 * (lane & 3);
#pragma unroll
            for (int e = 0; e < 4; e++) {
                float v = sacc[j][e] * sl2;
                if (diag) {
                    int col = colb + (e & 1);
                    int row = (e < 2) ? rg0 : rg1;
                    if (col > row) v = -1e30f;
                }
                sacc[j][e] = v;
            }
            mx0 = fmaxf(mx0, fmaxf(sacc[j][0], sacc[j][1]));
            mx1 = fmaxf(mx1, fmaxf(sacc[j][2], sacc[j][3]));
        }
        mx0 = fmaxf(mx0, __shfl_xor_sync(0xffffffffu, mx0, 1));
        mx0 = fmaxf(mx0, __shfl_xor_sync(0xffffffffu, mx0, 2));
        mx1 = fmaxf(mx1, __shfl_xor_sync(0xffffffffu, mx1, 1));
        mx1 = fmaxf(mx1, __shfl_xor_sync(0xffffffffu, mx1, 2));

        float mn0 = fmaxf(m0, mx0), mn1 = fmaxf(m1, mx1);
        float corr0 = ex2f(m0 - mn0), corr1 = ex2f(m1 - mn1);
        m0 = mn0; m1 = mn1;

        float ps0 = 0.f, ps1 = 0.f;
#pragma unroll
        for (int j = 0; j < 8; j++) {
            sacc[j][0] = ex2f(sacc[j][0] - mn0);
            sacc[j][1] = ex2f(sacc[j][1] - mn0);
            sacc[j][2] = ex2f(sacc[j][2] - mn1);
            sacc[j][3] = ex2f(sacc[j][3] - mn1);
            ps0 += sacc[j][0] + sacc[j][1];
            ps1 += sacc[j][2] + sacc[j][3];
        }
        l0 = l0 * corr0 + ps0;
        l1 = l1 * corr1 + ps1;
#pragma unroll
        for (int j = 0; j < 16; j++) {
            oacc[j][0] *= corr0; oacc[j][1] *= corr0;
            oacc[j][2] *= corr1; oacc[j][3] *= corr1;
        }

#pragma unroll
        for (int t = 0; t < 4; t++) {
            uint32_t pah[4], pal[4];
            pah[0] = split2(sacc[2*t][0],   sacc[2*t][1],   pal[0]);
            pah[1] = split2(sacc[2*t][2],   sacc[2*t][3],   pal[1]);
            pah[2] = split2(sacc[2*t+1][0], sacc[2*t+1][1], pal[2]);
            pah[3] = split2(sacc[2*t+1][2], sacc[2*t+1][3], pal[3]);
#pragma unroll
            for (int ng = 0; ng < 8; ng++) {
                uint32_t va = stg + 2 * KVT + (t * 16) * APB + ng * 32 + v_off;
                uint32_t vhF[4], vlF[4];
                ldm_x4t(va,       vhF[0], vhF[1], vhF[2], vhF[3]);
                ldm_x4t(va + KVT, vlF[0], vlF[1], vlF[2], vlF[3]);
                mma_bf16(oacc[2*ng],   pah, vhF + 0);
                mma_bf16(oacc[2*ng],   pah, vlF + 0);
                mma_bf16(oacc[2*ng],   pal, vhF + 0);
                mma_bf16(oacc[2*ng+1], pah, vhF + 2);
                mma_bf16(oacc[2*ng+1], pah, vlF + 2);
                mma_bf16(oacc[2*ng+1], pal, vhF + 2);
            }
        }
        __syncthreads();
    }

    l0 += __shfl_xor_sync(0xffffffffu, l0, 1);
    l0 += __shfl_xor_sync(0xffffffffu, l0, 2);
    l1 += __shfl_xor_sync(0xffffffffu, l1, 1);
    l1 += __shfl_xor_sync(0xffffffffu, l1, 2);
    float inv0 = 1.f / l0, inv1 = 1.f / l1;

    const uint32_t i0 = (uint32_t)(((row0 + rg0) * D_MOD + hoff + 2 * (lane & 3)) >> 1);
    const uint32_t i1 = (uint32_t)(((row0 + rg1) * D_MOD + hoff + 2 * (lane & 3)) >> 1);
#pragma unroll
    for (int j = 0; j < 16; j++) {
        uint32_t lo;
        uint32_t hi = split2(oacc[j][0] * inv0, oacc[j][1] * inv0, lo);
        aohi[i0 + 4 * j] = hi; aolo[i0 + 4 * j] = lo;
        hi = split2(oacc[j][2] * inv1, oacc[j][3] * inv1, lo);
        aohi[i1 + 4 * j] = hi; aolo[i1 + 4 * j] = lo;
    }
}

// ---------------------------------------------------------------------------
extern "C" void kernel_launch(void* const* d_in, const int* in_sizes, int n_in,
                              void* d_out, int out_size)
{
    const float* x    = (const float*)d_in[0];
    const float* cosb = (const float*)d_in[1];
    const float* sinb = (const float*)d_in[2];
    const float* Wq   = (const float*)d_in[3];
    const float* Wk   = (const float*)d_in[4];
    const float* Wv   = (const float*)d_in[5];
    const float* Wo   = (const float*)d_in[6];
    float* out = (float*)d_out;

    __nv_bfloat16 *xhi, *xlo, *whi, *wlo, *aohi, *aolo;
    __nv_bfloat16 *qhi, *qlo, *khi, *klo, *vhi, *vlo;
    cudaGetSymbolAddress((void**)&xhi,  g_xhi);
    cudaGetSymbolAddress((void**)&xlo,  g_xlo);
    cudaGetSymbolAddress((void**)&whi,  g_whi);
    cudaGetSymbolAddress((void**)&wlo,  g_wlo);
    cudaGetSymbolAddress((void**)&aohi, g_aohi);
    cudaGetSymbolAddress((void**)&aolo, g_aolo);
    cudaGetSymbolAddress((void**)&qhi,  g_qhi);
    cudaGetSymbolAddress((void**)&qlo,  g_qlo);
    cudaGetSymbolAddress((void**)&khi,  g_khi);
    cudaGetSymbolAddress((void**)&klo,  g_klo);
    cudaGetSymbolAddress((void**)&vhi,  g_vhi);
    cudaGetSymbolAddress((void**)&vlo,  g_vlo);

    cudaFuncSetAttribute(gemm_hmma,
                         cudaFuncAttributeMaxDynamicSharedMemorySize, GEMM_SMEM);
    cudaFuncSetAttribute(gemm_qkv,
                         cudaFuncAttributeMaxDynamicSharedMemorySize, GEMM_SMEM);
    cudaFuncSetAttribute(attn_mma,
                         cudaFuncAttributeMaxDynamicSharedMemorySize, ATTN_SMEM);

    const int nx4 = (M_TOT * D_MOD) / 4;
    const int nw4 = (D_MOD * D_MOD) / 4;
    const float* Ws[4] = {Wq, Wk, Wv, Wo};

    split_bf16_kernel<<<nx4 / 1024, 256>>>((const float4*)x, (uint2*)xhi, (uint2*)xlo, nx4);
    for (int i = 0; i < 4; i++)
        split_bf16_kernel<<<nw4 / 1024, 256>>>((const float4*)Ws[i],
            (uint2*)(whi + (size_t)i * D_MOD * D_MOD),
            (uint2*)(wlo + (size_t)i * D_MOD * D_MOD), nw4);

    dim3 qkvgrid(D_MOD / 128, M_TOT / 128, 3);
    gemm_qkv<<<qkvgrid, 256, GEMM_SMEM>>>(xhi, xlo, whi, wlo, cosb, sinb,
        (uint32_t*)qhi, (uint32_t*)qlo, (uint32_t*)khi, (uint32_t*)klo,
        (uint32_t*)vhi, (uint32_t*)vlo);

    attn_mma<<<BATCH * NHEAD * (S_LEN / 128), 256, ATTN_SMEM>>>(
        qhi, qlo, khi, klo, vhi, vlo, (uint32_t*)aohi, (uint32_t*)aolo);

    dim3 ggrid(D_MOD / 128, M_TOT / 128);
    gemm_hmma<<<ggrid, 256, GEMM_SMEM>>>(aohi, aolo,
        whi + 3 * (size_t)D_MOD * D_MOD, wlo + 3 * (size_t)D_MOD * D_MOD, out);
}

// round 8
// speedup vs baseline: 2.6572x; 1.0403x over previous
#include <cuda_runtime.h>
#include <cuda_bf16.h>
#include <math.h>
#include <cstdint>

#define S_LEN   2048
#define D_MOD   2048
#define NHEAD   16
#define HD      128
#define BATCH   2
#define M_TOT   (BATCH * S_LEN)   // 4096

// ---------------------------------------------------------------------------
// helpers
// ---------------------------------------------------------------------------
__device__ __forceinline__ uint32_t smem_u32(const void* p) {
    uint32_t a;
    asm("{ .reg .u64 t; cvta.to.shared.u64 t, %1; cvt.u32.u64 %0, t; }"
        : "=r"(a) : "l"(p));
    return a;
}

#define CP_ASYNC16(dst, src) \
    asm volatile("cp.async.cg.shared.global [%0], [%1], 16;" \
                 :: "r"(dst), "l"(src) : "memory")
#define CP_COMMIT() asm volatile("cp.async.commit_group;" ::: "memory")
#define CP_WAIT1()  asm volatile("cp.async.wait_group 1;" ::: "memory")
#define CP_WAIT0()  asm volatile("cp.async.wait_group 0;" ::: "memory")

__device__ __forceinline__ void ldm_x4(uint32_t addr, uint32_t& r0, uint32_t& r1,
                                       uint32_t& r2, uint32_t& r3) {
    asm volatile("ldmatrix.sync.aligned.m8n8.x4.shared.b16 {%0,%1,%2,%3}, [%4];"
                 : "=r"(r0), "=r"(r1), "=r"(r2), "=r"(r3) : "r"(addr));
}
__device__ __forceinline__ void ldm_x4t(uint32_t addr, uint32_t& r0, uint32_t& r1,
                                        uint32_t& r2, uint32_t& r3) {
    asm volatile("ldmatrix.sync.aligned.m8n8.x4.trans.shared.b16 {%0,%1,%2,%3}, [%4];"
                 : "=r"(r0), "=r"(r1), "=r"(r2), "=r"(r3) : "r"(addr));
}
__device__ __forceinline__ void mma_bf16(float* d, const uint32_t* a, const uint32_t* b) {
    asm volatile(
        "mma.sync.aligned.m16n8k16.row.col.f32.bf16.bf16.f32 "
        "{%0,%1,%2,%3}, {%4,%5,%6,%7}, {%8,%9}, {%0,%1,%2,%3};"
        : "+f"(d[0]), "+f"(d[1]), "+f"(d[2]), "+f"(d[3])
        : "r"(a[0]), "r"(a[1]), "r"(a[2]), "r"(a[3]), "r"(b[0]), "r"(b[1]));
}
__device__ __forceinline__ uint32_t bf16x2_pack(float lo, float hi) {
    uint32_t r;
    asm("cvt.rn.bf16x2.f32 %0, %1, %2;" : "=r"(r) : "f"(hi), "f"(lo));
    return r;
}
__device__ __forceinline__ uint32_t split2(float a, float b, uint32_t& lo) {
    uint32_t h = bf16x2_pack(a, b);
    float ha = __uint_as_float(h << 16);
    float hb = __uint_as_float(h & 0xffff0000u);
    lo = bf16x2_pack(a - ha, b - hb);
    return h;
}
__device__ __forceinline__ float ex2f(float x) {
    float y; asm("ex2.approx.ftz.f32 %0, %1;" : "=f"(y) : "f"(x)); return y;
}

// ---------------------------------------------------------------------------
// Scratch (device globals: allocation-free rule)
// ---------------------------------------------------------------------------
__device__ __nv_bfloat16 g_xhi [M_TOT * D_MOD];
__device__ __nv_bfloat16 g_xlo [M_TOT * D_MOD];
__device__ __nv_bfloat16 g_whi [4][D_MOD * D_MOD];
__device__ __nv_bfloat16 g_wlo [4][D_MOD * D_MOD];
__device__ __nv_bfloat16 g_aohi[M_TOT * D_MOD];
__device__ __nv_bfloat16 g_aolo[M_TOT * D_MOD];
__device__ __nv_bfloat16 g_qhi [M_TOT * D_MOD];
__device__ __nv_bfloat16 g_qlo [M_TOT * D_MOD];
__device__ __nv_bfloat16 g_khi [M_TOT * D_MOD];
__device__ __nv_bfloat16 g_klo [M_TOT * D_MOD];
__device__ __nv_bfloat16 g_vhi [M_TOT * D_MOD];
__device__ __nv_bfloat16 g_vlo [M_TOT * D_MOD];

// ---------------------------------------------------------------------------
// Fused split: x (2 regions) + 4 weights (1 region each) -> hi/lo bf16.
// 6 regions x 1M float4, 4 float4 per thread, 1024 blocks per region.
// ---------------------------------------------------------------------------
#define REG4 (1024 * 1024)     // float4 per region
__global__ __launch_bounds__(256) void split_all_kernel(
    const float4* __restrict__ x,
    const float4* __restrict__ w0, const float4* __restrict__ w1,
    const float4* __restrict__ w2, const float4* __restrict__ w3,
    uint2* __restrict__ xhi, uint2* __restrict__ xlo,
    uint2* __restrict__ whi, uint2* __restrict__ wlo)
{
    const int region = blockIdx.x >> 10;
    const int bl     = blockIdx.x & 1023;
    const float4* src; uint2 *ph, *pl;
    switch (region) {
        case 0:  src = x;           ph = xhi;            pl = xlo;            break;
        case 1:  src = x + REG4;    ph = xhi + REG4;     pl = xlo + REG4;     break;
        case 2:  src = w0;          ph = whi;            pl = wlo;            break;
        case 3:  src = w1;          ph = whi + REG4;     pl = wlo + REG4;     break;
        case 4:  src = w2;          ph = whi + 2*REG4;   pl = wlo + 2*REG4;   break;
        default: src = w3;          ph = whi + 3*REG4;   pl = wlo + 3*REG4;   break;
    }
    int base = bl * 256 + threadIdx.x;
#pragma unroll
    for (int t = 0; t < 4; t++) {
        int i = base + t * (REG4 / 4);
        float4 v = src[i];
        uint2 hv, lv;
        hv.x = split2(v.x, v.y, lv.x);
        hv.y = split2(v.z, v.w, lv.y);
        ph[i] = hv; pl[i] = lv;
    }
}

// ---------------------------------------------------------------------------
// HMMA bf16-split GEMM NT core: C[M,N] = A[M,K] * B[N,K]^T (fp32, 3 products)
// CTA 128x256, BK=32, 256 threads (8 warps, warp tile 64x64), 3-stage pipe.
// ---------------------------------------------------------------------------
#define APITCH   80
#define ASZ      (128 * APITCH)          // 10240
#define BSZ      (256 * APITCH)          // 20480
#define STAGE_SZ (2 * ASZ + 2 * BSZ)     // 61440
#define GEMM_SMEM (3 * STAGE_SZ)         // 184320

__device__ __forceinline__ void g2s_stage(
    uint32_t sbase, const __nv_bfloat16* pAh, const __nv_bfloat16* pAl,
    const __nv_bfloat16* pBh, const __nv_bfloat16* pBl, int kc, int tid)
{
#pragma unroll
    for (int t = 0; t < 2; t++) {
        int idx = tid + t * 256;            // 0..511
        int row = idx >> 2;                 // 0..127
        int c16 = idx & 3;
        uint32_t d = sbase + row * APITCH + c16 * 16;
        size_t g = (size_t)row * D_MOD + kc + c16 * 8;
        CP_ASYNC16(d,        pAh + g);
        CP_ASYNC16(d + ASZ,  pAl + g);
    }
#pragma unroll
    for (int t = 0; t < 4; t++) {
        int idx = tid + t * 256;            // 0..1023
        int row = idx >> 2;                 // 0..255
        int c16 = idx & 3;
        uint32_t d = sbase + 2 * ASZ + row * APITCH + c16 * 16;
        size_t g = (size_t)row * D_MOD + kc + c16 * 8;
        CP_ASYNC16(d,        pBh + g);
        CP_ASYNC16(d + BSZ,  pBl + g);
    }
}

// fills acc[4][8][4]; callers must sync before reusing smem
__device__ __forceinline__ void gemm_mainloop(
    uint32_t sb, const __nv_bfloat16* pAh, const __nv_bfloat16* pAl,
    const __nv_bfloat16* pBh, const __nv_bfloat16* pBl,
    int tid, int wm, int wn, int lane, float acc[4][8][4])
{
#pragma unroll
    for (int i = 0; i < 4; i++)
#pragma unroll
        for (int j = 0; j < 8; j++)
#pragma unroll
            for (int e = 0; e < 4; e++) acc[i][j][e] = 0.f;

    const uint32_t a_off = (uint32_t)((lane & 15) * APITCH + (lane >> 4) * 16);
    const uint32_t b_off = (uint32_t)(((lane >> 4) * 8 + (lane & 7)) * APITCH +
                                      ((lane >> 3) & 1) * 16);

    const int nk = D_MOD / 32;   // 64
    g2s_stage(sb + 0 * STAGE_SZ, pAh, pAl, pBh, pBl, 0, tid);
    CP_COMMIT();
    g2s_stage(sb + 1 * STAGE_SZ, pAh, pAl, pBh, pBl, 32, tid);
    CP_COMMIT();

    int stg_idx = 0;
    for (int c = 0; c < nk; c++) {
        const uint32_t stg = sb + stg_idx * STAGE_SZ;
        if (c + 1 < nk) { CP_WAIT1(); } else { CP_WAIT0(); }
        __syncthreads();

        if (c + 2 < nk) {
            int nidx = stg_idx + 2; if (nidx >= 3) nidx -= 3;
            g2s_stage(sb + nidx * STAGE_SZ, pAh, pAl, pBh, pBl, (c + 2) * 32, tid);
            CP_COMMIT();
        }

#pragma unroll
        for (int s = 0; s < 2; s++) {
            const uint32_t k0b = s * 32;
            uint32_t ah[4][4], al[4][4];
#pragma unroll
            for (int mt = 0; mt < 4; mt++) {
                uint32_t base = stg + (wm * 64 + mt * 16) * APITCH + k0b + a_off;
                ldm_x4(base,       ah[mt][0], ah[mt][1], ah[mt][2], ah[mt][3]);
                ldm_x4(base + ASZ, al[mt][0], al[mt][1], al[mt][2], al[mt][3]);
            }
            uint32_t bh[8][2], bl[8][2];
#pragma unroll
            for (int ntp = 0; ntp < 4; ntp++) {
                uint32_t base = stg + 2 * ASZ + (wn * 64 + ntp * 16) * APITCH + k0b + b_off;
                ldm_x4(base,       bh[2*ntp][0], bh[2*ntp][1], bh[2*ntp+1][0], bh[2*ntp+1][1]);
                ldm_x4(base + BSZ, bl[2*ntp][0], bl[2*ntp][1], bl[2*ntp+1][0], bl[2*ntp+1][1]);
            }
#pragma unroll
            for (int mt = 0; mt < 4; mt++)
#pragma unroll
                for (int nt = 0; nt < 8; nt++) {
                    mma_bf16(acc[mt][nt], ah[mt], bh[nt]);
                    mma_bf16(acc[mt][nt], ah[mt], bl[nt]);
                    mma_bf16(acc[mt][nt], al[mt], bh[nt]);
                }
        }
        if (++stg_idx == 3) stg_idx = 0;
    }
}

// Wo GEMM: fp32 output
__global__ __launch_bounds__(256, 1) void gemm_hmma(
    const __nv_bfloat16* __restrict__ Ahi, const __nv_bfloat16* __restrict__ Alo,
    const __nv_bfloat16* __restrict__ Bhi, const __nv_bfloat16* __restrict__ Blo,
    float* __restrict__ C)
{
    extern __shared__ char smem[];
    uint32_t sb = smem_u32(smem);
    const int tid  = threadIdx.x;
    const int wid  = tid >> 5;
    const int lane = tid & 31;
    const int wm   = wid & 1;
    const int wn   = wid >> 1;
    const int bm = blockIdx.y * 128;
    const int bn = blockIdx.x * 256;

    float acc[4][8][4];
    gemm_mainloop(sb, Ahi + (size_t)bm * D_MOD, Alo + (size_t)bm * D_MOD,
                  Bhi + (size_t)bn * D_MOD, Blo + (size_t)bn * D_MOD,
                  tid, wm, wn, lane, acc);

    const int mrow = bm + wm * 64 + (lane >> 2);
    const int ncol = bn + wn * 64 + (lane & 3) * 2;
#pragma unroll
    for (int mt = 0; mt < 4; mt++)
#pragma unroll
        for (int nt = 0; nt < 8; nt++) {
            float* c0 = C + (size_t)(mrow + mt * 16)     * D_MOD + ncol + nt * 8;
            float* c1 = C + (size_t)(mrow + mt * 16 + 8) * D_MOD + ncol + nt * 8;
            *reinterpret_cast<float2*>(c0) = make_float2(acc[mt][nt][0], acc[mt][nt][1]);
            *reinterpret_cast<float2*>(c1) = make_float2(acc[mt][nt][2], acc[mt][nt][3]);
        }
}

// Fused QKV GEMM: z selects weight/output. z<2: RoPE+split epilogue, z=2: split.
#define EPIP 264   // fp32 epilogue smem pitch (256 + 8 pad)
__global__ __launch_bounds__(256, 1) void gemm_qkv(
    const __nv_bfloat16* __restrict__ Ahi, const __nv_bfloat16* __restrict__ Alo,
    const __nv_bfloat16* __restrict__ Whi, const __nv_bfloat16* __restrict__ Wlo,
    const float* __restrict__ cosb, const float* __restrict__ sinb,
    uint32_t* __restrict__ qhi, uint32_t* __restrict__ qlo,
    uint32_t* __restrict__ khi, uint32_t* __restrict__ klo,
    uint32_t* __restrict__ vhi, uint32_t* __restrict__ vlo)
{
    extern __shared__ char smem[];
    uint32_t sb = smem_u32(smem);
    const int tid  = threadIdx.x;
    const int wid  = tid >> 5;
    const int lane = tid & 31;
    const int wm   = wid & 1;
    const int wn   = wid >> 1;
    const int bm = blockIdx.y * 128;
    const int bn = blockIdx.x * 256;
    const int z  = blockIdx.z;

    const size_t woff = (size_t)z * D_MOD * D_MOD;
    float acc[4][8][4];
    gemm_mainloop(sb, Ahi + (size_t)bm * D_MOD, Alo + (size_t)bm * D_MOD,
                  Whi + woff + (size_t)bn * D_MOD, Wlo + woff + (size_t)bn * D_MOD,
                  tid, wm, wn, lane, acc);

    if (z == 2) {
        const int mrow = bm + wm * 64 + (lane >> 2);
        const int ncol = bn + wn * 64 + (lane & 3) * 2;
#pragma unroll
        for (int mt = 0; mt < 4; mt++)
#pragma unroll
            for (int nt = 0; nt < 8; nt++) {
                uint32_t lo;
                size_t i0 = ((size_t)(mrow + mt * 16)     * D_MOD + ncol + nt * 8) >> 1;
                size_t i1 = ((size_t)(mrow + mt * 16 + 8) * D_MOD + ncol + nt * 8) >> 1;
                vhi[i0] = split2(acc[mt][nt][0], acc[mt][nt][1], lo); vlo[i0] = lo;
                vhi[i1] = split2(acc[mt][nt][2], acc[mt][nt][3], lo); vlo[i1] = lo;
            }
        return;
    }

    // Q/K: stage acc tile (128x256 fp32) in smem, then RoPE + split.
    __syncthreads();
    float* sf = reinterpret_cast<float*>(smem);
    const int r0 = wm * 64 + (lane >> 2);
    const int c0 = wn * 64 + (lane & 3) * 2;
#pragma unroll
    for (int mt = 0; mt < 4; mt++)
#pragma unroll
        for (int nt = 0; nt < 8; nt++) {
            sf[(r0 + mt * 16)     * EPIP + c0 + nt * 8]     = acc[mt][nt][0];
            sf[(r0 + mt * 16)     * EPIP + c0 + nt * 8 + 1] = acc[mt][nt][1];
            sf[(r0 + mt * 16 + 8) * EPIP + c0 + nt * 8]     = acc[mt][nt][2];
            sf[(r0 + mt * 16 + 8) * EPIP + c0 + nt * 8 + 1] = acc[mt][nt][3];
        }
    __syncthreads();

    uint32_t* OH = z ? khi : qhi;
    uint32_t* OL = z ? klo : qlo;
#pragma unroll
    for (int head = 0; head < 2; head++) {
        const int hc = head * 128;
#pragma unroll
        for (int it = 0; it < 16; it++) {
            int idx = tid + it * 256;          // 0..4095
            int r = idx >> 5;                  // 0..127
            int d = (idx & 31) * 2;            // 0..62
            float2 v1 = *reinterpret_cast<const float2*>(sf + r * EPIP + hc + d);
            float2 v2 = *reinterpret_cast<const float2*>(sf + r * EPIP + hc + 64 + d);
            int gm = bm + r;
            int srow = gm & (S_LEN - 1);
            float2 c1 = *reinterpret_cast<const float2*>(cosb + srow * HD + d);
            float2 s1 = *reinterpret_cast<const float2*>(sinb + srow * HD + d);
            float2 c2 = *reinterpret_cast<const float2*>(cosb + srow * HD + 64 + d);
            float2 s2 = *reinterpret_cast<const float2*>(sinb + srow * HD + 64 + d);
            float o1x = v1.x * c1.x - v2.x * s1.x;
            float o1y = v1.y * c1.y - v2.y * s1.y;
            float o2x = v2.x * c2.x + v1.x * s2.x;
            float o2y = v2.y * c2.y + v1.y * s2.y;
            size_t base = (size_t)gm * D_MOD + bn + hc;
            uint32_t lo;
            OH[(base + d) >> 1]      = split2(o1x, o1y, lo); OL[(base + d) >> 1]      = lo;
            OH[(base + 64 + d) >> 1] = split2(o2x, o2y, lo); OL[(base + 64 + d) >> 1] = lo;
        }
    }
}

// ---------------------------------------------------------------------------
// Flash attention (causal) with HMMA bf16 3-product split.  (unchanged)
// ---------------------------------------------------------------------------
#define AP    136
#define APB   (AP * 2)
#define QTILE (128 * APB)
#define KVT   (64 * APB)
#define KVSTG (4 * KVT)
#define SKV0  (2 * QTILE)
#define ATTN_SMEM (2 * QTILE + 2 * KVSTG)   // 208896

__device__ __forceinline__ void attn_g2s_kv(
    uint32_t dst, const __nv_bfloat16* kh, const __nv_bfloat16* kl,
    const __nv_bfloat16* vh, const __nv_bfloat16* vl,
    size_t gbase, int tid)
{
    const __nv_bfloat16* ptrs[4] = {kh, kl, vh, vl};
#pragma unroll
    for (int t = 0; t < 4; t++) {
#pragma unroll
        for (int i = 0; i < 4; i++) {
            int idx = tid + i * 256;
            int r = idx >> 4;
            int c = idx & 15;
            CP_ASYNC16(dst + t * KVT + r * APB + c * 16,
                       ptrs[t] + gbase + (size_t)r * D_MOD + c * 8);
        }
    }
}

__global__ __launch_bounds__(256, 1) void attn_mma(
    const __nv_bfloat16* __restrict__ qh_, const __nv_bfloat16* __restrict__ ql_,
    const __nv_bfloat16* __restrict__ kh_, const __nv_bfloat16* __restrict__ kl_,
    const __nv_bfloat16* __restrict__ vh_, const __nv_bfloat16* __restrict__ vl_,
    uint32_t* __restrict__ aohi, uint32_t* __restrict__ aolo)
{
    extern __shared__ char smem[];
    uint32_t sb = smem_u32(smem);
    const int tid  = threadIdx.x;
    const int wid  = tid >> 5;
    const int lane = tid & 31;
    const int bid = blockIdx.x;
    const int qb = 15 - (bid >> 5);
    const int bh = bid & 31;
    const int b  = bh >> 4;
    const int h  = bh & 15;

    const size_t row0 = (size_t)b * S_LEN;
    const int    hoff = h * HD;
    const int    q0   = qb * 128;

    {
        const size_t qg = (row0 + q0) * D_MOD + hoff;
#pragma unroll
        for (int i = 0; i < 8; i++) {
            int idx = tid + i * 256;
            int r = idx >> 4;
            int c = idx & 15;
            uint32_t d = sb + r * APB + c * 16;
            size_t g = qg + (size_t)r * D_MOD + c * 8;
            CP_ASYNC16(d,         qh_ + g);
            CP_ASYNC16(d + QTILE, ql_ + g);
        }
        attn_g2s_kv(sb + SKV0, kh_, kl_, vh_, vl_, row0 * D_MOD + hoff, tid);
        CP_COMMIT();
    }

    float oacc[16][4];
#pragma unroll
    for (int j = 0; j < 16; j++)
#pragma unroll
        for (int e = 0; e < 4; e++) oacc[j][e] = 0.f;
    float m0 = -1e30f, m1 = -1e30f, l0 = 0.f, l1 = 0.f;

    const float sl2 = 0.08838834764831845f * 1.4426950408889634f;
    const int kb_max = qb * 2 + 1;
    const int rg0 = q0 + wid * 16 + (lane >> 2);
    const int rg1 = rg0 + 8;

    const uint32_t a_off = (uint32_t)((lane & 15) * APB + (lane >> 4) * 16);
    const uint32_t b_off = (uint32_t)(((lane >> 4) * 8 + (lane & 7)) * APB +
                                      ((lane >> 3) & 1) * 16);
    const uint32_t v_off = (uint32_t)(((lane & 7) + ((lane >> 3) & 1) * 8) * APB +
                                      (lane >> 4) * 16);

    for (int kb = 0; kb <= kb_max; kb++) {
        if (kb + 1 <= kb_max) {
            attn_g2s_kv(sb + SKV0 + ((kb + 1) & 1) * KVSTG, kh_, kl_, vh_, vl_,
                        (row0 + (kb + 1) * 64) * D_MOD + hoff, tid);
            CP_COMMIT();
            CP_WAIT1();
        } else {
            CP_WAIT0();
        }
        __syncthreads();

        const uint32_t stg = sb + SKV0 + (kb & 1) * KVSTG;

        float sacc[8][4];
#pragma unroll
        for (int j = 0; j < 8; j++)
#pragma unroll
            for (int e = 0; e < 4; e++) sacc[j][e] = 0.f;

#pragma unroll
        for (int t = 0; t < 8; t++) {
            uint32_t qa = sb + (wid * 16) * APB + t * 32 + a_off;
            uint32_t qhF[4], qlF[4];
            ldm_x4(qa,         qhF[0], qhF[1], qhF[2], qhF[3]);
            ldm_x4(qa + QTILE, qlF[0], qlF[1], qlF[2], qlF[3]);
#pragma unroll
            for (int ng = 0; ng < 4; ng++) {
                uint32_t ka = stg + (ng * 16) * APB + t * 32 + b_off;
                uint32_t khF[4], klF[4];
                ldm_x4(ka,       khF[0], khF[1], khF[2], khF[3]);
                ldm_x4(ka + KVT, klF[0], klF[1], klF[2], klF[3]);
                mma_bf16(sacc[2*ng],   qhF, khF + 0);
                mma_bf16(sacc[2*ng],   qhF, klF + 0);
                mma_bf16(sacc[2*ng],   qlF, khF + 0);
                mma_bf16(sacc[2*ng+1], qhF, khF + 2);
                mma_bf16(sacc[2*ng+1], qhF, klF + 2);
                mma_bf16(sacc[2*ng+1], qlF, khF + 2);
            }
        }

        const bool diag = (kb >= 2 * qb);
        float mx0 = -1e30f, mx1 = -1e30f;
#pragma unroll
        for (int j = 0; j < 8; j++) {
            int colb = kb * 64 + 8 * j + 2 * (lane & 3);
#pragma unroll
            for (int e = 0; e < 4; e++) {
                float v = sacc[j][e] * sl2;
                if (diag) {
                    int col = colb + (e & 1);
                    int row = (e < 2) ? rg0 : rg1;
                    if (col > row) v = -1e30f;
                }
                sacc[j][e] = v;
            }
            mx0 = fmaxf(mx0, fmaxf(sacc[j][0], sacc[j][1]));
            mx1 = fmaxf(mx1, fmaxf(sacc[j][2], sacc[j][3]));
        }
        mx0 = fmaxf(mx0, __shfl_xor_sync(0xffffffffu, mx0, 1));
        mx0 = fmaxf(mx0, __shfl_xor_sync(0xffffffffu, mx0, 2));
        mx1 = fmaxf(mx1, __shfl_xor_sync(0xffffffffu, mx1, 1));
        mx1 = fmaxf(mx1, __shfl_xor_sync(0xffffffffu, mx1, 2));

        float mn0 = fmaxf(m0, mx0), mn1 = fmaxf(m1, mx1);
        float corr0 = ex2f(m0 - mn0), corr1 = ex2f(m1 - mn1);
        m0 = mn0; m1 = mn1;

        float ps0 = 0.f, ps1 = 0.f;
#pragma unroll
        for (int j = 0; j < 8; j++) {
            sacc[j][0] = ex2f(sacc[j][0] - mn0);
            sacc[j][1] = ex2f(sacc[j][1] - mn0);
            sacc[j][2] = ex2f(sacc[j][2] - mn1);
            sacc[j][3] = ex2f(sacc[j][3] - mn1);
            ps0 += sacc[j][0] + sacc[j][1];
            ps1 += sacc[j][2] + sacc[j][3];
        }
        l0 = l0 * corr0 + ps0;
        l1 = l1 * corr1 + ps1;
#pragma unroll
        for (int j = 0; j < 16; j++) {
            oacc[j][0] *= corr0; oacc[j][1] *= corr0;
            oacc[j][2] *= corr1; oacc[j][3] *= corr1;
        }

#pragma unroll
        for (int t = 0; t < 4; t++) {
            uint32_t pah[4], pal[4];
            pah[0] = split2(sacc[2*t][0],   sacc[2*t][1],   pal[0]);
            pah[1] = split2(sacc[2*t][2],   sacc[2*t][3],   pal[1]);
            pah[2] = split2(sacc[2*t+1][0], sacc[2*t+1][1], pal[2]);
            pah[3] = split2(sacc[2*t+1][2], sacc[2*t+1][3], pal[3]);
#pragma unroll
            for (int ng = 0; ng < 8; ng++) {
                uint32_t va = stg + 2 * KVT + (t * 16) * APB + ng * 32 + v_off;
                uint32_t vhF[4], vlF[4];
                ldm_x4t(va,       vhF[0], vhF[1], vhF[2], vhF[3]);
                ldm_x4t(va + KVT, vlF[0], vlF[1], vlF[2], vlF[3]);
                mma_bf16(oacc[2*ng],   pah, vhF + 0);
                mma_bf16(oacc[2*ng],   pah, vlF + 0);
                mma_bf16(oacc[2*ng],   pal, vhF + 0);
                mma_bf16(oacc[2*ng+1], pah, vhF + 2);
                mma_bf16(oacc[2*ng+1], pah, vlF + 2);
                mma_bf16(oacc[2*ng+1], pal, vhF + 2);
            }
        }
        __syncthreads();
    }

    l0 += __shfl_xor_sync(0xffffffffu, l0, 1);
    l0 += __shfl_xor_sync(0xffffffffu, l0, 2);
    l1 += __shfl_xor_sync(0xffffffffu, l1, 1);
    l1 += __shfl_xor_sync(0xffffffffu, l1, 2);
    float inv0 = 1.f / l0, inv1 = 1.f / l1;

    const uint32_t i0 = (uint32_t)(((row0 + rg0) * D_MOD + hoff + 2 * (lane & 3)) >> 1);
    const uint32_t i1 = (uint32_t)(((row0 + rg1) * D_MOD + hoff + 2 * (lane & 3)) >> 1);
#pragma unroll
    for (int j = 0; j < 16; j++) {
        uint32_t lo;
        uint32_t hi = split2(oacc[j][0] * inv0, oacc[j][1] * inv0, lo);
        aohi[i0 + 4 * j] = hi; aolo[i0 + 4 * j] = lo;
        hi = split2(oacc[j][2] * inv1, oacc[j][3] * inv1, lo);
        aohi[i1 + 4 * j] = hi; aolo[i1 + 4 * j] = lo;
    }
}

// ---------------------------------------------------------------------------
extern "C" void kernel_launch(void* const* d_in, const int* in_sizes, int n_in,
                              void* d_out, int out_size)
{
    const float* x    = (const float*)d_in[0];
    const float* cosb = (const float*)d_in[1];
    const float* sinb = (const float*)d_in[2];
    const float* Wq   = (const float*)d_in[3];
    const float* Wk   = (const float*)d_in[4];
    const float* Wv   = (const float*)d_in[5];
    const float* Wo   = (const float*)d_in[6];
    float* out = (float*)d_out;

    __nv_bfloat16 *xhi, *xlo, *whi, *wlo, *aohi, *aolo;
    __nv_bfloat16 *qhi, *qlo, *khi, *klo, *vhi, *vlo;
    cudaGetSymbolAddress((void**)&xhi,  g_xhi);
    cudaGetSymbolAddress((void**)&xlo,  g_xlo);
    cudaGetSymbolAddress((void**)&whi,  g_whi);
    cudaGetSymbolAddress((void**)&wlo,  g_wlo);
    cudaGetSymbolAddress((void**)&aohi, g_aohi);
    cudaGetSymbolAddress((void**)&aolo, g_aolo);
    cudaGetSymbolAddress((void**)&qhi,  g_qhi);
    cudaGetSymbolAddress((void**)&qlo,  g_qlo);
    cudaGetSymbolAddress((void**)&khi,  g_khi);
    cudaGetSymbolAddress((void**)&klo,  g_klo);
    cudaGetSymbolAddress((void**)&vhi,  g_vhi);
    cudaGetSymbolAddress((void**)&vlo,  g_vlo);

    cudaFuncSetAttribute(gemm_hmma,
                         cudaFuncAttributeMaxDynamicSharedMemorySize, GEMM_SMEM);
    cudaFuncSetAttribute(gemm_qkv,
                         cudaFuncAttributeMaxDynamicSharedMemorySize, GEMM_SMEM);
    cudaFuncSetAttribute(attn_mma,
                         cudaFuncAttributeMaxDynamicSharedMemorySize, ATTN_SMEM);

    // one fused split for x + all 4 weights (6 regions x 1024 blocks)
    split_all_kernel<<<6144, 256>>>(
        (const float4*)x, (const float4*)Wq, (const float4*)Wk,
        (const float4*)Wv, (const float4*)Wo,
        (uint2*)xhi, (uint2*)xlo, (uint2*)whi, (uint2*)wlo);

    dim3 qkvgrid(D_MOD / 256, M_TOT / 128, 3);   // (8, 32, 3)
    gemm_qkv<<<qkvgrid, 256, GEMM_SMEM>>>(xhi, xlo, whi, wlo, cosb, sinb,
        (uint32_t*)qhi, (uint32_t*)qlo, (uint32_t*)khi, (uint32_t*)klo,
        (uint32_t*)vhi, (uint32_t*)vlo);

    attn_mma<<<BATCH * NHEAD * (S_LEN / 128), 256, ATTN_SMEM>>>(
        qhi, qlo, khi, klo, vhi, vlo, (uint32_t*)aohi, (uint32_t*)aolo);

    dim3 ggrid(D_MOD / 256, M_TOT / 128);   // (8, 32)
    gemm_hmma<<<ggrid, 256, GEMM_SMEM>>>(aohi, aolo,
        whi + 3 * (size_t)D_MOD * D_MOD, wlo + 3 * (size_t)D_MOD * D_MOD, out);
}

// round 9
// speedup vs baseline: 2.8818x; 1.0845x over previous
#include <cuda_runtime.h>
#include <cuda_bf16.h>
#include <math.h>
#include <cstdint>

#define S_LEN   2048
#define D_MOD   2048
#define NHEAD   16
#define HD      128
#define BATCH   2
#define M_TOT   (BATCH * S_LEN)   // 4096

// ---------------------------------------------------------------------------
// helpers
// ---------------------------------------------------------------------------
__device__ __forceinline__ uint32_t smem_u32(const void* p) {
    uint32_t a;
    asm("{ .reg .u64 t; cvta.to.shared.u64 t, %1; cvt.u32.u64 %0, t; }"
        : "=r"(a) : "l"(p));
    return a;
}

#define CP_ASYNC16(dst, src) \
    asm volatile("cp.async.cg.shared.global [%0], [%1], 16;" \
                 :: "r"(dst), "l"(src) : "memory")
#define CP_COMMIT() asm volatile("cp.async.commit_group;" ::: "memory")
#define CP_WAIT1()  asm volatile("cp.async.wait_group 1;" ::: "memory")
#define CP_WAIT0()  asm volatile("cp.async.wait_group 0;" ::: "memory")

__device__ __forceinline__ void ldm_x4(uint32_t addr, uint32_t& r0, uint32_t& r1,
                                       uint32_t& r2, uint32_t& r3) {
    asm volatile("ldmatrix.sync.aligned.m8n8.x4.shared.b16 {%0,%1,%2,%3}, [%4];"
                 : "=r"(r0), "=r"(r1), "=r"(r2), "=r"(r3) : "r"(addr));
}
__device__ __forceinline__ void ldm_x4t(uint32_t addr, uint32_t& r0, uint32_t& r1,
                                        uint32_t& r2, uint32_t& r3) {
    asm volatile("ldmatrix.sync.aligned.m8n8.x4.trans.shared.b16 {%0,%1,%2,%3}, [%4];"
                 : "=r"(r0), "=r"(r1), "=r"(r2), "=r"(r3) : "r"(addr));
}
__device__ __forceinline__ void mma_bf16(float* d, const uint32_t* a, const uint32_t* b) {
    asm volatile(
        "mma.sync.aligned.m16n8k16.row.col.f32.bf16.bf16.f32 "
        "{%0,%1,%2,%3}, {%4,%5,%6,%7}, {%8,%9}, {%0,%1,%2,%3};"
        : "+f"(d[0]), "+f"(d[1]), "+f"(d[2]), "+f"(d[3])
        : "r"(a[0]), "r"(a[1]), "r"(a[2]), "r"(a[3]), "r"(b[0]), "r"(b[1]));
}
__device__ __forceinline__ uint32_t bf16x2_pack(float lo, float hi) {
    uint32_t r;
    asm("cvt.rn.bf16x2.f32 %0, %1, %2;" : "=r"(r) : "f"(hi), "f"(lo));
    return r;
}
__device__ __forceinline__ uint32_t split2(float a, float b, uint32_t& lo) {
    uint32_t h = bf16x2_pack(a, b);
    float ha = __uint_as_float(h << 16);
    float hb = __uint_as_float(h & 0xffff0000u);
    lo = bf16x2_pack(a - ha, b - hb);
    return h;
}
__device__ __forceinline__ float ex2f(float x) {
    float y; asm("ex2.approx.ftz.f32 %0, %1;" : "=f"(y) : "f"(x)); return y;
}

// ---------------------------------------------------------------------------
// Scratch (device globals: allocation-free rule)
// ---------------------------------------------------------------------------
__device__ __nv_bfloat16 g_xhi [M_TOT * D_MOD];
__device__ __nv_bfloat16 g_xlo [M_TOT * D_MOD];
__device__ __nv_bfloat16 g_whi [4][D_MOD * D_MOD];
__device__ __nv_bfloat16 g_wlo [4][D_MOD * D_MOD];
__device__ __nv_bfloat16 g_aohi[M_TOT * D_MOD];
__device__ __nv_bfloat16 g_aolo[M_TOT * D_MOD];
__device__ __nv_bfloat16 g_qhi [M_TOT * D_MOD];
__device__ __nv_bfloat16 g_qlo [M_TOT * D_MOD];
__device__ __nv_bfloat16 g_khi [M_TOT * D_MOD];
__device__ __nv_bfloat16 g_klo [M_TOT * D_MOD];
__device__ __nv_bfloat16 g_vhi [M_TOT * D_MOD];
__device__ __nv_bfloat16 g_vlo [M_TOT * D_MOD];

// ---------------------------------------------------------------------------
// Fused split: x (2 regions) + 4 weights (1 region each) -> hi/lo bf16.
// ---------------------------------------------------------------------------
#define REG4 (1024 * 1024)     // float4 per region
__global__ __launch_bounds__(256) void split_all_kernel(
    const float4* __restrict__ x,
    const float4* __restrict__ w0, const float4* __restrict__ w1,
    const float4* __restrict__ w2, const float4* __restrict__ w3,
    uint2* __restrict__ xhi, uint2* __restrict__ xlo,
    uint2* __restrict__ whi, uint2* __restrict__ wlo)
{
    const int region = blockIdx.x >> 10;
    const int bl     = blockIdx.x & 1023;
    const float4* src; uint2 *ph, *pl;
    switch (region) {
        case 0:  src = x;           ph = xhi;            pl = xlo;            break;
        case 1:  src = x + REG4;    ph = xhi + REG4;     pl = xlo + REG4;     break;
        case 2:  src = w0;          ph = whi;            pl = wlo;            break;
        case 3:  src = w1;          ph = whi + REG4;     pl = wlo + REG4;     break;
        case 4:  src = w2;          ph = whi + 2*REG4;   pl = wlo + 2*REG4;   break;
        default: src = w3;          ph = whi + 3*REG4;   pl = wlo + 3*REG4;   break;
    }
    int base = bl * 256 + threadIdx.x;
#pragma unroll
    for (int t = 0; t < 4; t++) {
        int i = base + t * (REG4 / 4);
        float4 v = src[i];
        uint2 hv, lv;
        hv.x = split2(v.x, v.y, lv.x);
        hv.y = split2(v.z, v.w, lv.y);
        ph[i] = hv; pl[i] = lv;
    }
}

// ---------------------------------------------------------------------------
// HMMA bf16-split GEMM NT core: C[M,N] = A[M,K] * B[N,K]^T (fp32, 3 products)
// CTA 128x256, BK=64, 256 threads (8 warps, warp tile 64x64), 2-stage pipe.
// ---------------------------------------------------------------------------
#define APITCH   144                      // 64 bf16 = 128B + 16B pad
#define ASZ      (128 * APITCH)           // 18432
#define BSZ      (256 * APITCH)           // 36864
#define STAGE_SZ (2 * ASZ + 2 * BSZ)      // 110592
#define GEMM_SMEM (2 * STAGE_SZ)          // 221184

__device__ __forceinline__ void g2s_stage(
    uint32_t sbase, const __nv_bfloat16* pAh, const __nv_bfloat16* pAl,
    const __nv_bfloat16* pBh, const __nv_bfloat16* pBl, int kc, int tid)
{
#pragma unroll
    for (int t = 0; t < 4; t++) {
        int idx = tid + t * 256;            // 0..1023
        int row = idx >> 3;                 // 0..127
        int c16 = idx & 7;
        uint32_t d = sbase + row * APITCH + c16 * 16;
        size_t g = (size_t)row * D_MOD + kc + c16 * 8;
        CP_ASYNC16(d,       pAh + g);
        CP_ASYNC16(d + ASZ, pAl + g);
    }
#pragma unroll
    for (int t = 0; t < 8; t++) {
        int idx = tid + t * 256;            // 0..2047
        int row = idx >> 3;                 // 0..255
        int c16 = idx & 7;
        uint32_t d = sbase + 2 * ASZ + row * APITCH + c16 * 16;
        size_t g = (size_t)row * D_MOD + kc + c16 * 8;
        CP_ASYNC16(d,       pBh + g);
        CP_ASYNC16(d + BSZ, pBl + g);
    }
}

// fills acc[4][8][4]; callers must sync before reusing smem
__device__ __forceinline__ void gemm_mainloop(
    uint32_t sb, const __nv_bfloat16* pAh, const __nv_bfloat16* pAl,
    const __nv_bfloat16* pBh, const __nv_bfloat16* pBl,
    int tid, int wm, int wn, int lane, float acc[4][8][4])
{
#pragma unroll
    for (int i = 0; i < 4; i++)
#pragma unroll
        for (int j = 0; j < 8; j++)
#pragma unroll
            for (int e = 0; e < 4; e++) acc[i][j][e] = 0.f;

    const uint32_t a_off = (uint32_t)((lane & 15) * APITCH + (lane >> 4) * 16);
    const uint32_t b_off = (uint32_t)(((lane >> 4) * 8 + (lane & 7)) * APITCH +
                                      ((lane >> 3) & 1) * 16);

    const int nk = D_MOD / 64;   // 32
    g2s_stage(sb, pAh, pAl, pBh, pBl, 0, tid);
    CP_COMMIT();

    for (int c = 0; c < nk; c++) {
        const uint32_t stg = sb + (c & 1) * STAGE_SZ;
        CP_WAIT0();              // only g2s(c) is pending at this point
        __syncthreads();         // all warps done with compute(c-1) (other buffer)

        if (c + 1 < nk) {        // prefetch next chunk; overlaps compute(c)
            g2s_stage(sb + ((c + 1) & 1) * STAGE_SZ, pAh, pAl, pBh, pBl,
                      (c + 1) * 64, tid);
            CP_COMMIT();
        }

#pragma unroll
        for (int s = 0; s < 4; s++) {
            const uint32_t k0b = s * 32;
            uint32_t ah[4][4], al[4][4];
#pragma unroll
            for (int mt = 0; mt < 4; mt++) {
                uint32_t base = stg + (wm * 64 + mt * 16) * APITCH + k0b + a_off;
                ldm_x4(base,       ah[mt][0], ah[mt][1], ah[mt][2], ah[mt][3]);
                ldm_x4(base + ASZ, al[mt][0], al[mt][1], al[mt][2], al[mt][3]);
            }
            uint32_t bh[8][2], bl[8][2];
#pragma unroll
            for (int ntp = 0; ntp < 4; ntp++) {
                uint32_t base = stg + 2 * ASZ + (wn * 64 + ntp * 16) * APITCH + k0b + b_off;
                ldm_x4(base,       bh[2*ntp][0], bh[2*ntp][1], bh[2*ntp+1][0], bh[2*ntp+1][1]);
                ldm_x4(base + BSZ, bl[2*ntp][0], bl[2*ntp][1], bl[2*ntp+1][0], bl[2*ntp+1][1]);
            }
#pragma unroll
            for (int mt = 0; mt < 4; mt++)
#pragma unroll
                for (int nt = 0; nt < 8; nt++) {
                    mma_bf16(acc[mt][nt], ah[mt], bh[nt]);
                    mma_bf16(acc[mt][nt], ah[mt], bl[nt]);
                    mma_bf16(acc[mt][nt], al[mt], bh[nt]);
                }
        }
    }
}

// Wo GEMM: fp32 output
__global__ __launch_bounds__(256, 1) void gemm_hmma(
    const __nv_bfloat16* __restrict__ Ahi, const __nv_bfloat16* __restrict__ Alo,
    const __nv_bfloat16* __restrict__ Bhi, const __nv_bfloat16* __restrict__ Blo,
    float* __restrict__ C)
{
    extern __shared__ char smem[];
    uint32_t sb = smem_u32(smem);
    const int tid  = threadIdx.x;
    const int wid  = tid >> 5;
    const int lane = tid & 31;
    const int wm   = wid & 1;
    const int wn   = wid >> 1;
    const int bm = blockIdx.y * 128;
    const int bn = blockIdx.x * 256;

    float acc[4][8][4];
    gemm_mainloop(sb, Ahi + (size_t)bm * D_MOD, Alo + (size_t)bm * D_MOD,
                  Bhi + (size_t)bn * D_MOD, Blo + (size_t)bn * D_MOD,
                  tid, wm, wn, lane, acc);

    const int mrow = bm + wm * 64 + (lane >> 2);
    const int ncol = bn + wn * 64 + (lane & 3) * 2;
#pragma unroll
    for (int mt = 0; mt < 4; mt++)
#pragma unroll
        for (int nt = 0; nt < 8; nt++) {
            float* c0 = C + (size_t)(mrow + mt * 16)     * D_MOD + ncol + nt * 8;
            float* c1 = C + (size_t)(mrow + mt * 16 + 8) * D_MOD + ncol + nt * 8;
            *reinterpret_cast<float2*>(c0) = make_float2(acc[mt][nt][0], acc[mt][nt][1]);
            *reinterpret_cast<float2*>(c1) = make_float2(acc[mt][nt][2], acc[mt][nt][3]);
        }
}

// Fused QKV GEMM: z selects weight/output. z<2: RoPE+split epilogue, z=2: split.
#define EPIP 264   // fp32 epilogue smem pitch (256 + 8 pad)
__global__ __launch_bounds__(256, 1) void gemm_qkv(
    const __nv_bfloat16* __restrict__ Ahi, const __nv_bfloat16* __restrict__ Alo,
    const __nv_bfloat16* __restrict__ Whi, const __nv_bfloat16* __restrict__ Wlo,
    const float* __restrict__ cosb, const float* __restrict__ sinb,
    uint32_t* __restrict__ qhi, uint32_t* __restrict__ qlo,
    uint32_t* __restrict__ khi, uint32_t* __restrict__ klo,
    uint32_t* __restrict__ vhi, uint32_t* __restrict__ vlo)
{
    extern __shared__ char smem[];
    uint32_t sb = smem_u32(smem);
    const int tid  = threadIdx.x;
    const int wid  = tid >> 5;
    const int lane = tid & 31;
    const int wm   = wid & 1;
    const int wn   = wid >> 1;
    const int bm = blockIdx.y * 128;
    const int bn = blockIdx.x * 256;
    const int z  = blockIdx.z;

    const size_t woff = (size_t)z * D_MOD * D_MOD;
    float acc[4][8][4];
    gemm_mainloop(sb, Ahi + (size_t)bm * D_MOD, Alo + (size_t)bm * D_MOD,
                  Whi + woff + (size_t)bn * D_MOD, Wlo + woff + (size_t)bn * D_MOD,
                  tid, wm, wn, lane, acc);

    if (z == 2) {
        const int mrow = bm + wm * 64 + (lane >> 2);
        const int ncol = bn + wn * 64 + (lane & 3) * 2;
#pragma unroll
        for (int mt = 0; mt < 4; mt++)
#pragma unroll
            for (int nt = 0; nt < 8; nt++) {
                uint32_t lo;
                size_t i0 = ((size_t)(mrow + mt * 16)     * D_MOD + ncol + nt * 8) >> 1;
                size_t i1 = ((size_t)(mrow + mt * 16 + 8) * D_MOD + ncol + nt * 8) >> 1;
                vhi[i0] = split2(acc[mt][nt][0], acc[mt][nt][1], lo); vlo[i0] = lo;
                vhi[i1] = split2(acc[mt][nt][2], acc[mt][nt][3], lo); vlo[i1] = lo;
            }
        return;
    }

    // Q/K: stage acc tile (128x256 fp32) in smem, then RoPE + split.
    __syncthreads();
    float* sf = reinterpret_cast<float*>(smem);
    const int r0 = wm * 64 + (lane >> 2);
    const int c0 = wn * 64 + (lane & 3) * 2;
#pragma unroll
    for (int mt = 0; mt < 4; mt++)
#pragma unroll
        for (int nt = 0; nt < 8; nt++) {
            sf[(r0 + mt * 16)     * EPIP + c0 + nt * 8]     = acc[mt][nt][0];
            sf[(r0 + mt * 16)     * EPIP + c0 + nt * 8 + 1] = acc[mt][nt][1];
            sf[(r0 + mt * 16 + 8) * EPIP + c0 + nt * 8]     = acc[mt][nt][2];
            sf[(r0 + mt * 16 + 8) * EPIP + c0 + nt * 8 + 1] = acc[mt][nt][3];
        }
    __syncthreads();

    uint32_t* OH = z ? khi : qhi;
    uint32_t* OL = z ? klo : qlo;
#pragma unroll
    for (int head = 0; head < 2; head++) {
        const int hc = head * 128;
#pragma unroll
        for (int it = 0; it < 16; it++) {
            int idx = tid + it * 256;
            int r = idx >> 5;
            int d = (idx & 31) * 2;
            float2 v1 = *reinterpret_cast<const float2*>(sf + r * EPIP + hc + d);
            float2 v2 = *reinterpret_cast<const float2*>(sf + r * EPIP + hc + 64 + d);
            int gm = bm + r;
            int srow = gm & (S_LEN - 1);
            float2 c1 = *reinterpret_cast<const float2*>(cosb + srow * HD + d);
            float2 s1 = *reinterpret_cast<const float2*>(sinb + srow * HD + d);
            float2 c2 = *reinterpret_cast<const float2*>(cosb + srow * HD + 64 + d);
            float2 s2 = *reinterpret_cast<const float2*>(sinb + srow * HD + 64 + d);
            float o1x = v1.x * c1.x - v2.x * s1.x;
            float o1y = v1.y * c1.y - v2.y * s1.y;
            float o2x = v2.x * c2.x + v1.x * s2.x;
            float o2y = v2.y * c2.y + v1.y * s2.y;
            size_t base = (size_t)gm * D_MOD + bn + hc;
            uint32_t lo;
            OH[(base + d) >> 1]      = split2(o1x, o1y, lo); OL[(base + d) >> 1]      = lo;
            OH[(base + 64 + d) >> 1] = split2(o2x, o2y, lo); OL[(base + 64 + d) >> 1] = lo;
        }
    }
}

// ---------------------------------------------------------------------------
// Flash attention (causal) with HMMA bf16 3-product split.  (unchanged)
// ---------------------------------------------------------------------------
#define AP    136
#define APB   (AP * 2)
#define QTILE (128 * APB)
#define KVT   (64 * APB)
#define KVSTG (4 * KVT)
#define SKV0  (2 * QTILE)
#define ATTN_SMEM (2 * QTILE + 2 * KVSTG)   // 208896

__device__ __forceinline__ void attn_g2s_kv(
    uint32_t dst, const __nv_bfloat16* kh, const __nv_bfloat16* kl,
    const __nv_bfloat16* vh, const __nv_bfloat16* vl,
    size_t gbase, int tid)
{
    const __nv_bfloat16* ptrs[4] = {kh, kl, vh, vl};
#pragma unroll
    for (int t = 0; t < 4; t++) {
#pragma unroll
        for (int i = 0; i < 4; i++) {
            int idx = tid + i * 256;
            int r = idx >> 4;
            int c = idx & 15;
            CP_ASYNC16(dst + t * KVT + r * APB + c * 16,
                       ptrs[t] + gbase + (size_t)r * D_MOD + c * 8);
        }
    }
}

__global__ __launch_bounds__(256, 1) void attn_mma(
    const __nv_bfloat16* __restrict__ qh_, const __nv_bfloat16* __restrict__ ql_,
    const __nv_bfloat16* __restrict__ kh_, const __nv_bfloat16* __restrict__ kl_,
    const __nv_bfloat16* __restrict__ vh_, const __nv_bfloat16* __restrict__ vl_,
    uint32_t* __restrict__ aohi, uint32_t* __restrict__ aolo)
{
    extern __shared__ char smem[];
    uint32_t sb = smem_u32(smem);
    const int tid  = threadIdx.x;
    const int wid  = tid >> 5;
    const int lane = tid & 31;
    const int bid = blockIdx.x;
    const int qb = 15 - (bid >> 5);
    const int bh = bid & 31;
    const int b  = bh >> 4;
    const int h  = bh & 15;

    const size_t row0 = (size_t)b * S_LEN;
    const int    hoff = h * HD;
    const int    q0   = qb * 128;

    {
        const size_t qg = (row0 + q0) * D_MOD + hoff;
#pragma unroll
        for (int i = 0; i < 8; i++) {
            int idx = tid + i * 256;
            int r = idx >> 4;
            int c = idx & 15;
            uint32_t d = sb + r * APB + c * 16;
            size_t g = qg + (size_t)r * D_MOD + c * 8;
            CP_ASYNC16(d,         qh_ + g);
            CP_ASYNC16(d + QTILE, ql_ + g);
        }
        attn_g2s_kv(sb + SKV0, kh_, kl_, vh_, vl_, row0 * D_MOD + hoff, tid);
        CP_COMMIT();
    }

    float oacc[16][4];
#pragma unroll
    for (int j = 0; j < 16; j++)
#pragma unroll
        for (int e = 0; e < 4; e++) oacc[j][e] = 0.f;
    float m0 = -1e30f, m1 = -1e30f, l0 = 0.f, l1 = 0.f;

    const float sl2 = 0.08838834764831845f * 1.4426950408889634f;
    const int kb_max = qb * 2 + 1;
    const int rg0 = q0 + wid * 16 + (lane >> 2);
    const int rg1 = rg0 + 8;

    const uint32_t a_off = (uint32_t)((lane & 15) * APB + (lane >> 4) * 16);
    const uint32_t b_off = (uint32_t)(((lane >> 4) * 8 + (lane & 7)) * APB +
                                      ((lane >> 3) & 1) * 16);
    const uint32_t v_off = (uint32_t)(((lane & 7) + ((lane >> 3) & 1) * 8) * APB +
                                      (lane >> 4) * 16);

    for (int kb = 0; kb <= kb_max; kb++) {
        if (kb + 1 <= kb_max) {
            attn_g2s_kv(sb + SKV0 + ((kb + 1) & 1) * KVSTG, kh_, kl_, vh_, vl_,
                        (row0 + (kb + 1) * 64) * D_MOD + hoff, tid);
            CP_COMMIT();
            CP_WAIT1();
        } else {
            CP_WAIT0();
        }
        __syncthreads();

        const uint32_t stg = sb + SKV0 + (kb & 1) * KVSTG;

        float sacc[8][4];
#pragma unroll
        for (int j = 0; j < 8; j++)
#pragma unroll
            for (int e = 0; e < 4; e++) sacc[j][e] = 0.f;

#pragma unroll
        for (int t = 0; t < 8; t++) {
            uint32_t qa = sb + (wid * 16) * APB + t * 32 + a_off;
            uint32_t qhF[4], qlF[4];
            ldm_x4(qa,         qhF[0], qhF[1], qhF[2], qhF[3]);
            ldm_x4(qa + QTILE, qlF[0], qlF[1], qlF[2], qlF[3]);
#pragma unroll
            for (int ng = 0; ng < 4; ng++) {
                uint32_t ka = stg + (ng * 16) * APB + t * 32 + b_off;
                uint32_t khF[4], klF[4];
                ldm_x4(ka,       khF[0], khF[1], khF[2], khF[3]);
                ldm_x4(ka + KVT, klF[0], klF[1], klF[2], klF[3]);
                mma_bf16(sacc[2*ng],   qhF, khF + 0);
                mma_bf16(sacc[2*ng],   qhF, klF + 0);
                mma_bf16(sacc[2*ng],   qlF, khF + 0);
                mma_bf16(sacc[2*ng+1], qhF, khF + 2);
                mma_bf16(sacc[2*ng+1], qhF, klF + 2);
                mma_bf16(sacc[2*ng+1], qlF, khF + 2);
            }
        }

        const bool diag = (kb >= 2 * qb);
        float mx0 = -1e30f, mx1 = -1e30f;
#pragma unroll
        for (int j = 0; j < 8; j++) {
            int colb = kb * 64 + 8 * j + 2 * (lane & 3);
#pragma unroll
            for (int e = 0; e < 4; e++) {
                float v = sacc[j][e] * sl2;
                if (diag) {
                    int col = colb + (e & 1);
                    int row = (e < 2) ? rg0 : rg1;
                    if (col > row) v = -1e30f;
                }
                sacc[j][e] = v;
            }
            mx0 = fmaxf(mx0, fmaxf(sacc[j][0], sacc[j][1]));
            mx1 = fmaxf(mx1, fmaxf(sacc[j][2], sacc[j][3]));
        }
        mx0 = fmaxf(mx0, __shfl_xor_sync(0xffffffffu, mx0, 1));
        mx0 = fmaxf(mx0, __shfl_xor_sync(0xffffffffu, mx0, 2));
        mx1 = fmaxf(mx1, __shfl_xor_sync(0xffffffffu, mx1, 1));
        mx1 = fmaxf(mx1, __shfl_xor_sync(0xffffffffu, mx1, 2));

        float mn0 = fmaxf(m0, mx0), mn1 = fmaxf(m1, mx1);
        float corr0 = ex2f(m0 - mn0), corr1 = ex2f(m1 - mn1);
        m0 = mn0; m1 = mn1;

        float ps0 = 0.f, ps1 = 0.f;
#pragma unroll
        for (int j = 0; j < 8; j++) {
            sacc[j][0] = ex2f(sacc[j][0] - mn0);
            sacc[j][1] = ex2f(sacc[j][1] - mn0);
            sacc[j][2] = ex2f(sacc[j][2] - mn1);
            sacc[j][3] = ex2f(sacc[j][3] - mn1);
            ps0 += sacc[j][0] + sacc[j][1];
            ps1 += sacc[j][2] + sacc[j][3];
        }
        l0 = l0 * corr0 + ps0;
        l1 = l1 * corr1 + ps1;
#pragma unroll
        for (int j = 0; j < 16; j++) {
            oacc[j][0] *= corr0; oacc[j][1] *= corr0;
            oacc[j][2] *= corr1; oacc[j][3] *= corr1;
        }

#pragma unroll
        for (int t = 0; t < 4; t++) {
            uint32_t pah[4], pal[4];
            pah[0] = split2(sacc[2*t][0],   sacc[2*t][1],   pal[0]);
            pah[1] = split2(sacc[2*t][2],   sacc[2*t][3],   pal[1]);
            pah[2] = split2(sacc[2*t+1][0], sacc[2*t+1][1], pal[2]);
            pah[3] = split2(sacc[2*t+1][2], sacc[2*t+1][3], pal[3]);
#pragma unroll
            for (int ng = 0; ng < 8; ng++) {
                uint32_t va = stg + 2 * KVT + (t * 16) * APB + ng * 32 + v_off;
                uint32_t vhF[4], vlF[4];
                ldm_x4t(va,       vhF[0], vhF[1], vhF[2], vhF[3]);
                ldm_x4t(va + KVT, vlF[0], vlF[1], vlF[2], vlF[3]);
                mma_bf16(oacc[2*ng],   pah, vhF + 0);
                mma_bf16(oacc[2*ng],   pah, vlF + 0);
                mma_bf16(oacc[2*ng],   pal, vhF + 0);
                mma_bf16(oacc[2*ng+1], pah, vhF + 2);
                mma_bf16(oacc[2*ng+1], pah, vlF + 2);
                mma_bf16(oacc[2*ng+1], pal, vhF + 2);
            }
        }
        __syncthreads();
    }

    l0 += __shfl_xor_sync(0xffffffffu, l0, 1);
    l0 += __shfl_xor_sync(0xffffffffu, l0, 2);
    l1 += __shfl_xor_sync(0xffffffffu, l1, 1);
    l1 += __shfl_xor_sync(0xffffffffu, l1, 2);
    float inv0 = 1.f / l0, inv1 = 1.f / l1;

    const uint32_t i0 = (uint32_t)(((row0 + rg0) * D_MOD + hoff + 2 * (lane & 3)) >> 1);
    const uint32_t i1 = (uint32_t)(((row0 + rg1) * D_MOD + hoff + 2 * (lane & 3)) >> 1);
#pragma unroll
    for (int j = 0; j < 16; j++) {
        uint32_t lo;
        uint32_t hi = split2(oacc[j][0] * inv0, oacc[j][1] * inv0, lo);
        aohi[i0 + 4 * j] = hi; aolo[i0 + 4 * j] = lo;
        hi = split2(oacc[j][2] * inv1, oacc[j][3] * inv1, lo);
        aohi[i1 + 4 * j] = hi; aolo[i1 + 4 * j] = lo;
    }
}

// ---------------------------------------------------------------------------
extern "C" void kernel_launch(void* const* d_in, const int* in_sizes, int n_in,
                              void* d_out, int out_size)
{
    const float* x    = (const float*)d_in[0];
    const float* cosb = (const float*)d_in[1];
    const float* sinb = (const float*)d_in[2];
    const float* Wq   = (const float*)d_in[3];
    const float* Wk   = (const float*)d_in[4];
    const float* Wv   = (const float*)d_in[5];
    const float* Wo   = (const float*)d_in[6];
    float* out = (float*)d_out;

    __nv_bfloat16 *xhi, *xlo, *whi, *wlo, *aohi, *aolo;
    __nv_bfloat16 *qhi, *qlo, *khi, *klo, *vhi, *vlo;
    cudaGetSymbolAddress((void**)&xhi,  g_xhi);
    cudaGetSymbolAddress((void**)&xlo,  g_xlo);
    cudaGetSymbolAddress((void**)&whi,  g_whi);
    cudaGetSymbolAddress((void**)&wlo,  g_wlo);
    cudaGetSymbolAddress((void**)&aohi, g_aohi);
    cudaGetSymbolAddress((void**)&aolo, g_aolo);
    cudaGetSymbolAddress((void**)&qhi,  g_qhi);
    cudaGetSymbolAddress((void**)&qlo,  g_qlo);
    cudaGetSymbolAddress((void**)&khi,  g_khi);
    cudaGetSymbolAddress((void**)&klo,  g_klo);
    cudaGetSymbolAddress((void**)&vhi,  g_vhi);
    cudaGetSymbolAddress((void**)&vlo,  g_vlo);

    cudaFuncSetAttribute(gemm_hmma,
                         cudaFuncAttributeMaxDynamicSharedMemorySize, GEMM_SMEM);
    cudaFuncSetAttribute(gemm_qkv,
                         cudaFuncAttributeMaxDynamicSharedMemorySize, GEMM_SMEM);
    cudaFuncSetAttribute(attn_mma,
                         cudaFuncAttributeMaxDynamicSharedMemorySize, ATTN_SMEM);

    split_all_kernel<<<6144, 256>>>(
        (const float4*)x, (const float4*)Wq, (const float4*)Wk,
        (const float4*)Wv, (const float4*)Wo,
        (uint2*)xhi, (uint2*)xlo, (uint2*)whi, (uint2*)wlo);

    dim3 qkvgrid(D_MOD / 256, M_TOT / 128, 3);   // (8, 32, 3)
    gemm_qkv<<<qkvgrid, 256, GEMM_SMEM>>>(xhi, xlo, whi, wlo, cosb, sinb,
        (uint32_t*)qhi, (uint32_t*)qlo, (uint32_t*)khi, (uint32_t*)klo,
        (uint32_t*)vhi, (uint32_t*)vlo);

    attn_mma<<<BATCH * NHEAD * (S_LEN / 128), 256, ATTN_SMEM>>>(
        qhi, qlo, khi, klo, vhi, vlo, (uint32_t*)aohi, (uint32_t*)aolo);

    dim3 ggrid(D_MOD / 256, M_TOT / 128);   // (8, 32)
    gemm_hmma<<<ggrid, 256, GEMM_SMEM>>>(aohi, aolo,
        whi + 3 * (size_t)D_MOD * D_MOD, wlo + 3 * (size_t)D_MOD * D_MOD, out);
}